// round 7
// baseline (speedup 1.0000x reference)
#include <cuda_runtime.h>

// Problem constants
static constexpr int HID  = 64;
static constexpr int OBS  = 20;
static constexpr int PRED = 12;
static constexpr int BMAX = 32768;

static constexpr int TPB = 256;

// Scratch (allocation-free rule: __device__ globals)
__device__ float g_hs1[(size_t)OBS * BMAX * HID];
__device__ float g_h1[(size_t)BMAX * HID];
__device__ float g_c1[(size_t)BMAX * HID];

using u64 = unsigned long long;

__device__ __forceinline__ void fma2(u64& d, u64 a, u64 b) {
    asm("fma.rn.f32x2 %0, %1, %2, %0;" : "+l"(d) : "l"(a), "l"(b));
}
__device__ __forceinline__ u64 pack0(float x) { return (u64)__float_as_uint(x); }
__device__ __forceinline__ float hsum2(u64 v) {
    return __uint_as_float((unsigned)v) + __uint_as_float((unsigned)(v >> 32));
}
__device__ __forceinline__ float sigf(float x) {
    return __fdividef(1.0f, 1.0f + __expf(-x));
}
__device__ __forceinline__ float tanhf_(float x) {
    return fmaf(2.0f, sigf(2.0f * x), -1.0f);
}

// ===========================================================================
// Kernel 1: encoder layer 0 (SIMT twin scheme, validated round 5).
// ===========================================================================
static constexpr int K1_EPB = 128;
static constexpr int K1_WIH = 0;
static constexpr int K1_WHH = 512;
static constexpr int K1_BS  = K1_WHH + 16384;
static constexpr int K1_H   = K1_BS + 256;
static constexpr int K1_C   = K1_H + K1_EPB * 68;
static constexpr int K1_OBS = K1_C + K1_EPB * 65;
static constexpr int K1_SMEM = (K1_OBS + K1_EPB * OBS * 2) * 4;

__global__ void __launch_bounds__(TPB, 1) k_layer0(
    const float* __restrict__ obs, const float* __restrict__ wih,
    const float* __restrict__ whh, const float* __restrict__ bih,
    const float* __restrict__ bhh, int B)
{
    extern __shared__ float sm[];
    float* wih_s = sm + K1_WIH;
    float* whh_s = sm + K1_WHH;
    float* bs    = sm + K1_BS;
    float* hsh   = sm + K1_H;
    float* csh   = sm + K1_C;
    float* obs_s = sm + K1_OBS;

    const int tid = threadIdx.x;
    const size_t blockBase = (size_t)blockIdx.x * K1_EPB;

    for (int i = tid; i < 512; i += TPB) wih_s[i] = wih[i];
    for (int i = tid; i < 16384; i += TPB) whh_s[i] = whh[i];
    for (int i = tid; i < 256; i += TPB) bs[i] = bih[i] + bhh[i];
    for (int i = tid; i < K1_EPB * 68; i += TPB) hsh[i] = 0.f;
    for (int i = tid; i < K1_EPB * 65; i += TPB) csh[i] = 0.f;
    for (int i = tid; i < K1_EPB * OBS * 2; i += TPB) {
        int ee = i / (OBS * 2), j = i % (OBS * 2);
        obs_s[ee * (OBS * 2) + j] = obs[(blockBase + ee) * (OBS * 2) + j];
    }

    const int lane = tid & 31, warp = tid >> 5;
    const int slot = ((warp & 1) << 5) | lane;
    const int e0 = slot, e1 = slot + 64;
    const int ug = warp >> 1;

    for (int t = 0; t < OBS; ++t) {
        __syncthreads();
        if (t > 0) {
            float4* dst = (float4*)(g_hs1 + ((size_t)(t - 1) * B + blockBase) * HID);
            for (int i = tid; i < K1_EPB * 16; i += TPB) {
                int ee = i >> 4, k4 = i & 15;
                dst[i] = *(const float4*)(hsh + ee * 68 + k4 * 4);
            }
        }
        u64 h0[32], h1[32];
        #pragma unroll
        for (int k4 = 0; k4 < 16; ++k4) {
            ulonglong2 p = *(const ulonglong2*)(hsh + e0 * 68 + k4 * 4);
            h0[2 * k4] = p.x; h0[2 * k4 + 1] = p.y;
            ulonglong2 q = *(const ulonglong2*)(hsh + e1 * 68 + k4 * 4);
            h1[2 * k4] = q.x; h1[2 * k4 + 1] = q.y;
        }
        const float x00 = obs_s[e0 * 40 + 2 * t], x01 = obs_s[e0 * 40 + 2 * t + 1];
        const float x10 = obs_s[e1 * 40 + 2 * t], x11 = obs_s[e1 * 40 + 2 * t + 1];
        __syncthreads();

        #pragma unroll 2
        for (int u = 0; u < 16; ++u) {
            const int unit = ug * 16 + u;
            const float bi = bs[unit], bf = bs[64 + unit], bg = bs[128 + unit], bo = bs[192 + unit];
            const float wi0 = wih_s[2*unit],       wi1 = wih_s[2*unit+1];
            const float wf0 = wih_s[2*(64+unit)],  wf1 = wih_s[2*(64+unit)+1];
            const float wg0 = wih_s[2*(128+unit)], wg1 = wih_s[2*(128+unit)+1];
            const float wo0 = wih_s[2*(192+unit)], wo1 = wih_s[2*(192+unit)+1];
            u64 zi0 = pack0(bi + wi0*x00 + wi1*x01), zi1 = pack0(bi + wi0*x10 + wi1*x11);
            u64 zf0 = pack0(bf + wf0*x00 + wf1*x01), zf1 = pack0(bf + wf0*x10 + wf1*x11);
            u64 zg0 = pack0(bg + wg0*x00 + wg1*x01), zg1 = pack0(bg + wg0*x10 + wg1*x11);
            u64 zo0 = pack0(bo + wo0*x00 + wo1*x01), zo1 = pack0(bo + wo0*x10 + wo1*x11);
            const ulonglong2* wi2 = (const ulonglong2*)(whh_s + unit * 64);
            const ulonglong2* wf2 = (const ulonglong2*)(whh_s + (64 + unit) * 64);
            const ulonglong2* wg2 = (const ulonglong2*)(whh_s + (128 + unit) * 64);
            const ulonglong2* wo2 = (const ulonglong2*)(whh_s + (192 + unit) * 64);
            #pragma unroll
            for (int k = 0; k < 16; ++k) {
                ulonglong2 a = wi2[k], b = wf2[k], c2 = wg2[k], d = wo2[k];
                fma2(zi0, a.x, h0[2*k]); fma2(zi0, a.y, h0[2*k+1]);
                fma2(zi1, a.x, h1[2*k]); fma2(zi1, a.y, h1[2*k+1]);
                fma2(zf0, b.x, h0[2*k]); fma2(zf0, b.y, h0[2*k+1]);
                fma2(zf1, b.x, h1[2*k]); fma2(zf1, b.y, h1[2*k+1]);
                fma2(zg0, c2.x, h0[2*k]); fma2(zg0, c2.y, h0[2*k+1]);
                fma2(zg1, c2.x, h1[2*k]); fma2(zg1, c2.y, h1[2*k+1]);
                fma2(zo0, d.x, h0[2*k]); fma2(zo0, d.y, h0[2*k+1]);
                fma2(zo1, d.x, h1[2*k]); fma2(zo1, d.y, h1[2*k+1]);
            }
            float co0 = csh[e0 * 65 + unit];
            float cn0 = sigf(hsum2(zf0)) * co0 + sigf(hsum2(zi0)) * tanhf_(hsum2(zg0));
            csh[e0 * 65 + unit] = cn0;
            hsh[e0 * 68 + unit] = sigf(hsum2(zo0)) * tanhf_(cn0);
            float co1 = csh[e1 * 65 + unit];
            float cn1 = sigf(hsum2(zf1)) * co1 + sigf(hsum2(zi1)) * tanhf_(hsum2(zg1));
            csh[e1 * 65 + unit] = cn1;
            hsh[e1 * 68 + unit] = sigf(hsum2(zo1)) * tanhf_(cn1);
        }
    }
    __syncthreads();
    {
        float4* dst = (float4*)(g_hs1 + ((size_t)(OBS - 1) * B + blockBase) * HID);
        for (int i = tid; i < K1_EPB * 16; i += TPB) {
            int ee = i >> 4, k4 = i & 15;
            dst[i] = *(const float4*)(hsh + ee * 68 + k4 * 4);
        }
    }
}

// ===========================================================================
// Kernel 2: encoder layer 1 — khalf k-split + 2 elems/thread, c stride 65.
// warp 0..7; ug = warp>>1; slot = (warp&1)*16 + (lane>>1); khalf = lane&1.
// elems (slot, slot+32). khalf0 -> x-half (xsh / wcat cols 0-63),
// khalf1 -> h-half (hsh / wcat cols 64-127). Combine via shfl_xor(.,1).
// ===========================================================================
static constexpr int K2_EPB = 64;
static constexpr int K2_W   = 0;                          // 32768
static constexpr int K2_BS  = 32768;                      // 256
static constexpr int K2_H   = K2_BS + 256;                // 64*68
static constexpr int K2_C   = K2_H + K2_EPB * 68;         // 64*65
static constexpr int K2_X   = K2_C + K2_EPB * 65;         // 64*68
static constexpr int K2_SMEM = (K2_X + K2_EPB * 68) * 4;

__global__ void __launch_bounds__(TPB, 1) k_layer1(
    const float* __restrict__ wih, const float* __restrict__ whh,
    const float* __restrict__ bih, const float* __restrict__ bhh, int B)
{
    extern __shared__ float sm[];
    float* wcat = sm + K2_W;
    float* bs   = sm + K2_BS;
    float* hsh  = sm + K2_H;
    float* csh  = sm + K2_C;
    float* xsh  = sm + K2_X;

    const int tid = threadIdx.x;
    const size_t blockBase = (size_t)blockIdx.x * K2_EPB;

    for (int i = tid; i < 256 * 128; i += TPB) {
        int row = i >> 7, col = i & 127;
        wcat[i] = (col < 64) ? wih[row * 64 + col] : whh[row * 64 + (col - 64)];
    }
    for (int i = tid; i < 256; i += TPB) bs[i] = bih[i] + bhh[i];
    for (int i = tid; i < K2_EPB * 68; i += TPB) hsh[i] = 0.f;
    for (int i = tid; i < K2_EPB * 65; i += TPB) csh[i] = 0.f;

    const int lane = tid & 31, warp = tid >> 5;
    const int khalf = lane & 1;
    const int slot = ((warp & 1) << 4) | (lane >> 1);   // 0..31
    const int e0 = slot, e1 = slot + 32;
    const int ug = warp >> 1;
    const float* vsrc = khalf ? hsh : xsh;

    for (int t = 0; t < OBS; ++t) {
        __syncthreads();  // prev writes complete; xsh free
        {
            const float4* src = (const float4*)(g_hs1 + ((size_t)t * B + blockBase) * HID);
            for (int i = tid; i < K2_EPB * 16; i += TPB) {
                int ee = i >> 4, k4 = i & 15;
                *(float4*)(xsh + ee * 68 + k4 * 4) = src[i];
            }
        }
        __syncthreads();  // x ready
        u64 v0[32], v1[32];
        #pragma unroll
        for (int k4 = 0; k4 < 16; ++k4) {
            ulonglong2 p = *(const ulonglong2*)(vsrc + e0 * 68 + k4 * 4);
            v0[2 * k4] = p.x; v0[2 * k4 + 1] = p.y;
            ulonglong2 q = *(const ulonglong2*)(vsrc + e1 * 68 + k4 * 4);
            v1[2 * k4] = q.x; v1[2 * k4 + 1] = q.y;
        }
        __syncthreads();  // all reads of hsh done before overwrite

        #pragma unroll 2
        for (int u = 0; u < 16; ++u) {
            const int unit = ug * 16 + u;
            u64 zi0 = 0, zi1 = 0, zf0 = 0, zf1 = 0, zg0 = 0, zg1 = 0, zo0 = 0, zo1 = 0;
            const ulonglong2* wi2 = (const ulonglong2*)(wcat + unit * 128 + khalf * 64);
            const ulonglong2* wf2 = (const ulonglong2*)(wcat + (64 + unit) * 128 + khalf * 64);
            const ulonglong2* wg2 = (const ulonglong2*)(wcat + (128 + unit) * 128 + khalf * 64);
            const ulonglong2* wo2 = (const ulonglong2*)(wcat + (192 + unit) * 128 + khalf * 64);
            #pragma unroll
            for (int k = 0; k < 16; ++k) {
                ulonglong2 a = wi2[k], b = wf2[k], c2 = wg2[k], d = wo2[k];
                fma2(zi0, a.x, v0[2*k]); fma2(zi0, a.y, v0[2*k+1]);
                fma2(zi1, a.x, v1[2*k]); fma2(zi1, a.y, v1[2*k+1]);
                fma2(zf0, b.x, v0[2*k]); fma2(zf0, b.y, v0[2*k+1]);
                fma2(zf1, b.x, v1[2*k]); fma2(zf1, b.y, v1[2*k+1]);
                fma2(zg0, c2.x, v0[2*k]); fma2(zg0, c2.y, v0[2*k+1]);
                fma2(zg1, c2.x, v1[2*k]); fma2(zg1, c2.y, v1[2*k+1]);
                fma2(zo0, d.x, v0[2*k]); fma2(zo0, d.y, v0[2*k+1]);
                fma2(zo1, d.x, v1[2*k]); fma2(zo1, d.y, v1[2*k+1]);
            }
            // combine k-halves with lane partner
            float i0 = hsum2(zi0); i0 += __shfl_xor_sync(0xffffffffu, i0, 1);
            float i1 = hsum2(zi1); i1 += __shfl_xor_sync(0xffffffffu, i1, 1);
            float f0 = hsum2(zf0); f0 += __shfl_xor_sync(0xffffffffu, f0, 1);
            float f1 = hsum2(zf1); f1 += __shfl_xor_sync(0xffffffffu, f1, 1);
            float g0 = hsum2(zg0); g0 += __shfl_xor_sync(0xffffffffu, g0, 1);
            float g1 = hsum2(zg1); g1 += __shfl_xor_sync(0xffffffffu, g1, 1);
            float o0 = hsum2(zo0); o0 += __shfl_xor_sync(0xffffffffu, o0, 1);
            float o1 = hsum2(zo1); o1 += __shfl_xor_sync(0xffffffffu, o1, 1);
            if (khalf == 0) {
                const float bi = bs[unit], bf = bs[64 + unit];
                const float bg = bs[128 + unit], bo = bs[192 + unit];
                float co0 = csh[e0 * 65 + unit];
                float cn0 = sigf(f0 + bf) * co0 + sigf(i0 + bi) * tanhf_(g0 + bg);
                csh[e0 * 65 + unit] = cn0;
                hsh[e0 * 68 + unit] = sigf(o0 + bo) * tanhf_(cn0);
                float co1 = csh[e1 * 65 + unit];
                float cn1 = sigf(f1 + bf) * co1 + sigf(i1 + bi) * tanhf_(g1 + bg);
                csh[e1 * 65 + unit] = cn1;
                hsh[e1 * 68 + unit] = sigf(o1 + bo) * tanhf_(cn1);
            }
        }
    }
    __syncthreads();
    for (int i = tid; i < K2_EPB * HID; i += TPB) {
        int ee = i >> 6, k = i & 63;
        g_h1[(blockBase + ee) * HID + k] = hsh[ee * 68 + k];
        g_c1[(blockBase + ee) * HID + k] = csh[ee * 65 + k];
    }
}

// ===========================================================================
// Kernel 3: decoder (SIMT twin scheme, validated round 5).
// ===========================================================================
static constexpr int K3_EPB = 128;
static constexpr int K3_WIH = 0;
static constexpr int K3_WHH = 512;
static constexpr int K3_BS  = K3_WHH + 16384;
static constexpr int K3_OW  = K3_BS + 256;
static constexpr int K3_OB  = K3_OW + 128;
static constexpr int K3_H   = K3_OB + 4;
static constexpr int K3_C   = K3_H + K3_EPB * 68;
static constexpr int K3_X   = K3_C + K3_EPB * 65;
static constexpr int K3_SMEM = (K3_X + K3_EPB * 2) * 4;

__global__ void __launch_bounds__(TPB, 1) k_decoder(
    const float* __restrict__ obs, const float* __restrict__ wih,
    const float* __restrict__ whh, const float* __restrict__ bih,
    const float* __restrict__ bhh, const float* __restrict__ outw,
    const float* __restrict__ outb, float* __restrict__ out, int B)
{
    extern __shared__ float sm[];
    float* wih_s = sm + K3_WIH;
    float* whh_s = sm + K3_WHH;
    float* bs    = sm + K3_BS;
    float* ow    = sm + K3_OW;
    float* ob    = sm + K3_OB;
    float* hsh   = sm + K3_H;
    float* csh   = sm + K3_C;
    float* xsh   = sm + K3_X;

    const int tid = threadIdx.x;
    const size_t blockBase = (size_t)blockIdx.x * K3_EPB;

    for (int i = tid; i < 512; i += TPB) wih_s[i] = wih[i];
    for (int i = tid; i < 16384; i += TPB) whh_s[i] = whh[i];
    for (int i = tid; i < 256; i += TPB) bs[i] = bih[i] + bhh[i];
    for (int i = tid; i < 128; i += TPB) ow[i] = outw[i];
    if (tid < 2) ob[tid] = outb[tid];
    for (int i = tid; i < K3_EPB * HID; i += TPB) {
        int ee = i >> 6, k = i & 63;
        hsh[ee * 68 + k] = g_h1[(blockBase + ee) * HID + k];
        csh[ee * 65 + k] = g_c1[(blockBase + ee) * HID + k];
    }
    for (int i = tid; i < K3_EPB * 2; i += TPB) {
        int ee = i >> 1, j = i & 1;
        xsh[i] = obs[(blockBase + ee) * (OBS * 2) + (OBS - 1) * 2 + j];
    }

    const int lane = tid & 31, warp = tid >> 5;
    const int slot = ((warp & 1) << 5) | lane;
    const int e0 = slot, e1 = slot + 64;
    const int ug = warp >> 1;

    for (int t = 0; t < PRED; ++t) {
        __syncthreads();
        u64 h0[32], h1[32];
        #pragma unroll
        for (int k4 = 0; k4 < 16; ++k4) {
            ulonglong2 p = *(const ulonglong2*)(hsh + e0 * 68 + k4 * 4);
            h0[2 * k4] = p.x; h0[2 * k4 + 1] = p.y;
            ulonglong2 q = *(const ulonglong2*)(hsh + e1 * 68 + k4 * 4);
            h1[2 * k4] = q.x; h1[2 * k4 + 1] = q.y;
        }
        const float x00 = xsh[e0 * 2], x01 = xsh[e0 * 2 + 1];
        const float x10 = xsh[e1 * 2], x11 = xsh[e1 * 2 + 1];
        __syncthreads();

        #pragma unroll 2
        for (int u = 0; u < 16; ++u) {
            const int unit = ug * 16 + u;
            const float bi = bs[unit], bf = bs[64 + unit], bg = bs[128 + unit], bo = bs[192 + unit];
            const float wi0 = wih_s[2*unit],       wi1 = wih_s[2*unit+1];
            const float wf0 = wih_s[2*(64+unit)],  wf1 = wih_s[2*(64+unit)+1];
            const float wg0 = wih_s[2*(128+unit)], wg1 = wih_s[2*(128+unit)+1];
            const float wo0 = wih_s[2*(192+unit)], wo1 = wih_s[2*(192+unit)+1];
            u64 zi0 = pack0(bi + wi0*x00 + wi1*x01), zi1 = pack0(bi + wi0*x10 + wi1*x11);
            u64 zf0 = pack0(bf + wf0*x00 + wf1*x01), zf1 = pack0(bf + wf0*x10 + wf1*x11);
            u64 zg0 = pack0(bg + wg0*x00 + wg1*x01), zg1 = pack0(bg + wg0*x10 + wg1*x11);
            u64 zo0 = pack0(bo + wo0*x00 + wo1*x01), zo1 = pack0(bo + wo0*x10 + wo1*x11);
            const ulonglong2* wi2 = (const ulonglong2*)(whh_s + unit * 64);
            const ulonglong2* wf2 = (const ulonglong2*)(whh_s + (64 + unit) * 64);
            const ulonglong2* wg2 = (const ulonglong2*)(whh_s + (128 + unit) * 64);
            const ulonglong2* wo2 = (const ulonglong2*)(whh_s + (192 + unit) * 64);
            #pragma unroll
            for (int k = 0; k < 16; ++k) {
                ulonglong2 a = wi2[k], b = wf2[k], c2 = wg2[k], d = wo2[k];
                fma2(zi0, a.x, h0[2*k]); fma2(zi0, a.y, h0[2*k+1]);
                fma2(zi1, a.x, h1[2*k]); fma2(zi1, a.y, h1[2*k+1]);
                fma2(zf0, b.x, h0[2*k]); fma2(zf0, b.y, h0[2*k+1]);
                fma2(zf1, b.x, h1[2*k]); fma2(zf1, b.y, h1[2*k+1]);
                fma2(zg0, c2.x, h0[2*k]); fma2(zg0, c2.y, h0[2*k+1]);
                fma2(zg1, c2.x, h1[2*k]); fma2(zg1, c2.y, h1[2*k+1]);
                fma2(zo0, d.x, h0[2*k]); fma2(zo0, d.y, h0[2*k+1]);
                fma2(zo1, d.x, h1[2*k]); fma2(zo1, d.y, h1[2*k+1]);
            }
            float co0 = csh[e0 * 65 + unit];
            float cn0 = sigf(hsum2(zf0)) * co0 + sigf(hsum2(zi0)) * tanhf_(hsum2(zg0));
            csh[e0 * 65 + unit] = cn0;
            hsh[e0 * 68 + unit] = sigf(hsum2(zo0)) * tanhf_(cn0);
            float co1 = csh[e1 * 65 + unit];
            float cn1 = sigf(hsum2(zf1)) * co1 + sigf(hsum2(zi1)) * tanhf_(hsum2(zg1));
            csh[e1 * 65 + unit] = cn1;
            hsh[e1 * 68 + unit] = sigf(hsum2(zo1)) * tanhf_(cn1);
        }
        __syncthreads();
        if (ug == 0) {
            #pragma unroll
            for (int ei = 0; ei < 2; ++ei) {
                const int e = ei ? e1 : e0;
                float o0 = ob[0], o1 = ob[1];
                #pragma unroll
                for (int k4 = 0; k4 < 16; ++k4) {
                    float4 hh = *(const float4*)(hsh + e * 68 + k4 * 4);
                    float4 w0 = *(const float4*)(ow + k4 * 4);
                    float4 w1 = *(const float4*)(ow + 64 + k4 * 4);
                    o0 += w0.x * hh.x + w0.y * hh.y + w0.z * hh.z + w0.w * hh.w;
                    o1 += w1.x * hh.x + w1.y * hh.y + w1.z * hh.z + w1.w * hh.w;
                }
                out[(blockBase + e) * (PRED * 2) + t * 2 + 0] = o0;
                out[(blockBase + e) * (PRED * 2) + t * 2 + 1] = o1;
                xsh[e * 2] = o0;
                xsh[e * 2 + 1] = o1;
            }
        }
    }
}

// ---------------------------------------------------------------------------
extern "C" void kernel_launch(void* const* d_in, const int* in_sizes, int n_in,
                              void* d_out, int out_size)
{
    const float* obs     = (const float*)d_in[0];
    const float* w_ih_l0 = (const float*)d_in[1];
    const float* w_hh_l0 = (const float*)d_in[2];
    const float* b_ih_l0 = (const float*)d_in[3];
    const float* b_hh_l0 = (const float*)d_in[4];
    const float* w_ih_l1 = (const float*)d_in[5];
    const float* w_hh_l1 = (const float*)d_in[6];
    const float* b_ih_l1 = (const float*)d_in[7];
    const float* b_hh_l1 = (const float*)d_in[8];
    const float* dec_w_ih = (const float*)d_in[9];
    const float* dec_w_hh = (const float*)d_in[10];
    const float* dec_b_ih = (const float*)d_in[11];
    const float* dec_b_hh = (const float*)d_in[12];
    const float* out_w   = (const float*)d_in[13];
    const float* out_b   = (const float*)d_in[14];
    float* out = (float*)d_out;

    const int B = in_sizes[0] / (OBS * 2);

    cudaFuncSetAttribute(k_layer0,  cudaFuncAttributeMaxDynamicSharedMemorySize, K1_SMEM);
    cudaFuncSetAttribute(k_layer1,  cudaFuncAttributeMaxDynamicSharedMemorySize, K2_SMEM);
    cudaFuncSetAttribute(k_decoder, cudaFuncAttributeMaxDynamicSharedMemorySize, K3_SMEM);

    k_layer0<<<B / K1_EPB, TPB, K1_SMEM>>>(obs, w_ih_l0, w_hh_l0, b_ih_l0, b_hh_l0, B);
    k_layer1<<<B / K2_EPB, TPB, K2_SMEM>>>(w_ih_l1, w_hh_l1, b_ih_l1, b_hh_l1, B);
    k_decoder<<<B / K3_EPB, TPB, K3_SMEM>>>(obs, dec_w_ih, dec_w_hh, dec_b_ih, dec_b_hh,
                                            out_w, out_b, out, B);
}

// round 8
// speedup vs baseline: 1.0781x; 1.0781x over previous
#include <cuda_runtime.h>

// Problem constants
static constexpr int HID  = 64;
static constexpr int OBS  = 20;
static constexpr int PRED = 12;
static constexpr int BMAX = 32768;

static constexpr int TPB = 256;

// Scratch (allocation-free rule: __device__ globals)
__device__ float g_hs1[(size_t)OBS * BMAX * HID];
__device__ float g_h1[(size_t)BMAX * HID];
__device__ float g_c1[(size_t)BMAX * HID];

using u64 = unsigned long long;

__device__ __forceinline__ void fma2(u64& d, u64 a, u64 b) {
    asm("fma.rn.f32x2 %0, %1, %2, %0;" : "+l"(d) : "l"(a), "l"(b));
}
__device__ __forceinline__ u64 pack0(float x) { return (u64)__float_as_uint(x); }
__device__ __forceinline__ u64 pack2(float lo, float hi) {
    return (u64)__float_as_uint(lo) | ((u64)__float_as_uint(hi) << 32);
}
__device__ __forceinline__ float hsum2(u64 v) {
    return __uint_as_float((unsigned)v) + __uint_as_float((unsigned)(v >> 32));
}
__device__ __forceinline__ float sigf(float x) {
    return __fdividef(1.0f, 1.0f + __expf(-x));
}
__device__ __forceinline__ float tanhf_(float x) {
    return fmaf(2.0f, sigf(2.0f * x), -1.0f);
}

// ===========================================================================
// Kernel 1: encoder layer 0 (SIMT twin scheme, validated round 5 — unchanged).
// ===========================================================================
static constexpr int K1_EPB = 128;
static constexpr int K1_WIH = 0;
static constexpr int K1_WHH = 512;
static constexpr int K1_BS  = K1_WHH + 16384;
static constexpr int K1_H   = K1_BS + 256;
static constexpr int K1_C   = K1_H + K1_EPB * 68;
static constexpr int K1_OBS = K1_C + K1_EPB * 65;
static constexpr int K1_SMEM = (K1_OBS + K1_EPB * OBS * 2) * 4;

__global__ void __launch_bounds__(TPB, 1) k_layer0(
    const float* __restrict__ obs, const float* __restrict__ wih,
    const float* __restrict__ whh, const float* __restrict__ bih,
    const float* __restrict__ bhh, int B)
{
    extern __shared__ float sm[];
    float* wih_s = sm + K1_WIH;
    float* whh_s = sm + K1_WHH;
    float* bs    = sm + K1_BS;
    float* hsh   = sm + K1_H;
    float* csh   = sm + K1_C;
    float* obs_s = sm + K1_OBS;

    const int tid = threadIdx.x;
    const size_t blockBase = (size_t)blockIdx.x * K1_EPB;

    for (int i = tid; i < 512; i += TPB) wih_s[i] = wih[i];
    for (int i = tid; i < 16384; i += TPB) whh_s[i] = whh[i];
    for (int i = tid; i < 256; i += TPB) bs[i] = bih[i] + bhh[i];
    for (int i = tid; i < K1_EPB * 68; i += TPB) hsh[i] = 0.f;
    for (int i = tid; i < K1_EPB * 65; i += TPB) csh[i] = 0.f;
    for (int i = tid; i < K1_EPB * OBS * 2; i += TPB) {
        int ee = i / (OBS * 2), j = i % (OBS * 2);
        obs_s[ee * (OBS * 2) + j] = obs[(blockBase + ee) * (OBS * 2) + j];
    }

    const int lane = tid & 31, warp = tid >> 5;
    const int slot = ((warp & 1) << 5) | lane;
    const int e0 = slot, e1 = slot + 64;
    const int ug = warp >> 1;

    for (int t = 0; t < OBS; ++t) {
        __syncthreads();
        if (t > 0) {
            float4* dst = (float4*)(g_hs1 + ((size_t)(t - 1) * B + blockBase) * HID);
            for (int i = tid; i < K1_EPB * 16; i += TPB) {
                int ee = i >> 4, k4 = i & 15;
                dst[i] = *(const float4*)(hsh + ee * 68 + k4 * 4);
            }
        }
        u64 h0[32], h1[32];
        #pragma unroll
        for (int k4 = 0; k4 < 16; ++k4) {
            ulonglong2 p = *(const ulonglong2*)(hsh + e0 * 68 + k4 * 4);
            h0[2 * k4] = p.x; h0[2 * k4 + 1] = p.y;
            ulonglong2 q = *(const ulonglong2*)(hsh + e1 * 68 + k4 * 4);
            h1[2 * k4] = q.x; h1[2 * k4 + 1] = q.y;
        }
        const float x00 = obs_s[e0 * 40 + 2 * t], x01 = obs_s[e0 * 40 + 2 * t + 1];
        const float x10 = obs_s[e1 * 40 + 2 * t], x11 = obs_s[e1 * 40 + 2 * t + 1];
        __syncthreads();

        #pragma unroll 2
        for (int u = 0; u < 16; ++u) {
            const int unit = ug * 16 + u;
            const float bi = bs[unit], bf = bs[64 + unit], bg = bs[128 + unit], bo = bs[192 + unit];
            const float wi0 = wih_s[2*unit],       wi1 = wih_s[2*unit+1];
            const float wf0 = wih_s[2*(64+unit)],  wf1 = wih_s[2*(64+unit)+1];
            const float wg0 = wih_s[2*(128+unit)], wg1 = wih_s[2*(128+unit)+1];
            const float wo0 = wih_s[2*(192+unit)], wo1 = wih_s[2*(192+unit)+1];
            u64 zi0 = pack0(bi + wi0*x00 + wi1*x01), zi1 = pack0(bi + wi0*x10 + wi1*x11);
            u64 zf0 = pack0(bf + wf0*x00 + wf1*x01), zf1 = pack0(bf + wf0*x10 + wf1*x11);
            u64 zg0 = pack0(bg + wg0*x00 + wg1*x01), zg1 = pack0(bg + wg0*x10 + wg1*x11);
            u64 zo0 = pack0(bo + wo0*x00 + wo1*x01), zo1 = pack0(bo + wo0*x10 + wo1*x11);
            const ulonglong2* wi2 = (const ulonglong2*)(whh_s + unit * 64);
            const ulonglong2* wf2 = (const ulonglong2*)(whh_s + (64 + unit) * 64);
            const ulonglong2* wg2 = (const ulonglong2*)(whh_s + (128 + unit) * 64);
            const ulonglong2* wo2 = (const ulonglong2*)(whh_s + (192 + unit) * 64);
            #pragma unroll
            for (int k = 0; k < 16; ++k) {
                ulonglong2 a = wi2[k], b = wf2[k], c2 = wg2[k], d = wo2[k];
                fma2(zi0, a.x, h0[2*k]); fma2(zi0, a.y, h0[2*k+1]);
                fma2(zi1, a.x, h1[2*k]); fma2(zi1, a.y, h1[2*k+1]);
                fma2(zf0, b.x, h0[2*k]); fma2(zf0, b.y, h0[2*k+1]);
                fma2(zf1, b.x, h1[2*k]); fma2(zf1, b.y, h1[2*k+1]);
                fma2(zg0, c2.x, h0[2*k]); fma2(zg0, c2.y, h0[2*k+1]);
                fma2(zg1, c2.x, h1[2*k]); fma2(zg1, c2.y, h1[2*k+1]);
                fma2(zo0, d.x, h0[2*k]); fma2(zo0, d.y, h0[2*k+1]);
                fma2(zo1, d.x, h1[2*k]); fma2(zo1, d.y, h1[2*k+1]);
            }
            float co0 = csh[e0 * 65 + unit];
            float cn0 = sigf(hsum2(zf0)) * co0 + sigf(hsum2(zi0)) * tanhf_(hsum2(zg0));
            csh[e0 * 65 + unit] = cn0;
            hsh[e0 * 68 + unit] = sigf(hsum2(zo0)) * tanhf_(cn0);
            float co1 = csh[e1 * 65 + unit];
            float cn1 = sigf(hsum2(zf1)) * co1 + sigf(hsum2(zi1)) * tanhf_(hsum2(zg1));
            csh[e1 * 65 + unit] = cn1;
            hsh[e1 * 68 + unit] = sigf(hsum2(zo1)) * tanhf_(cn1);
        }
    }
    __syncthreads();
    {
        float4* dst = (float4*)(g_hs1 + ((size_t)(OBS - 1) * B + blockBase) * HID);
        for (int i = tid; i < K1_EPB * 16; i += TPB) {
            int ee = i >> 4, k4 = i & 15;
            dst[i] = *(const float4*)(hsh + ee * 68 + k4 * 4);
        }
    }
}

// ===========================================================================
// Kernel 2 v2: layer 1 with REGISTER-RESIDENT WEIGHTS + broadcast streaming.
// Thread tid owns gate-row r=tid of Wcat (128 floats in 64 u64 regs).
// GEMM phase: all threads stream v[e] via warp-uniform (broadcast) LDS.128,
// each computes z[r][e], writes zbuf. Epilogue: thread owns unit u=tid&63,
// elems (tid>>6)*16..+15, c-state in registers.
// ===========================================================================
static constexpr int K2_EPB = 64;
static constexpr int K2_X = 0;                       // 64*68
static constexpr int K2_H = K2_EPB * 68;             // 64*68
static constexpr int K2_Z = K2_H + K2_EPB * 68;      // 64*256
static constexpr int K2_SMEM = (K2_Z + K2_EPB * 256) * 4;   // 100,352 B

__global__ void __launch_bounds__(TPB, 1) k_layer1(
    const float* __restrict__ wih, const float* __restrict__ whh,
    const float* __restrict__ bih, const float* __restrict__ bhh, int B)
{
    extern __shared__ float sm[];
    float* xsh  = sm + K2_X;
    float* hsh  = sm + K2_H;
    float* zbuf = sm + K2_Z;

    const int tid = threadIdx.x;
    const size_t blockBase = (size_t)blockIdx.x * K2_EPB;
    const int r = tid;                     // gate row 0..255

    // Row r of Wcat into registers (one-time; L2-hot after first wave).
    u64 w[64];
    #pragma unroll
    for (int m = 0; m < 16; ++m) {
        float4 a = ((const float4*)(wih + r * 64))[m];
        w[2 * m]     = pack2(a.x, a.y);
        w[2 * m + 1] = pack2(a.z, a.w);
        float4 b = ((const float4*)(whh + r * 64))[m];
        w[32 + 2 * m]     = pack2(b.x, b.y);
        w[32 + 2 * m + 1] = pack2(b.z, b.w);
    }
    const float bsr = bih[r] + bhh[r];

    for (int i = tid; i < K2_EPB * 68; i += TPB) hsh[i] = 0.f;

    // epilogue ownership: unit u, elems eg*16..eg*16+15; c in regs
    const int u  = tid & 63;
    const int eg = tid >> 6;
    float c[16];
    #pragma unroll
    for (int j = 0; j < 16; ++j) c[j] = 0.f;

    for (int t = 0; t < OBS; ++t) {
        __syncthreads();   // hsh from prev epilogue (or init) visible; xsh free
        {
            const float4* src = (const float4*)(g_hs1 + ((size_t)t * B + blockBase) * HID);
            for (int i = tid; i < K2_EPB * 16; i += TPB) {
                int ee = i >> 4, k4 = i & 15;
                *(float4*)(xsh + ee * 68 + k4 * 4) = src[i];
            }
        }
        __syncthreads();   // x ready

        // GEMM: z[r][e] = bsr + Wih[r]·x[e] + Whh[r]·h[e]
        #pragma unroll 1
        for (int e = 0; e < K2_EPB; ++e) {
            u64 a0 = pack0(bsr), a1 = 0, a2 = 0, a3 = 0;
            const ulonglong2* vx = (const ulonglong2*)(xsh + e * 68);
            const ulonglong2* vh = (const ulonglong2*)(hsh + e * 68);
            #pragma unroll
            for (int k = 0; k < 8; ++k) {
                ulonglong2 p = vx[2 * k], q = vx[2 * k + 1];
                fma2(a0, w[4 * k],     p.x); fma2(a1, w[4 * k + 1], p.y);
                fma2(a2, w[4 * k + 2], q.x); fma2(a3, w[4 * k + 3], q.y);
            }
            #pragma unroll
            for (int k = 0; k < 8; ++k) {
                ulonglong2 p = vh[2 * k], q = vh[2 * k + 1];
                fma2(a0, w[32 + 4 * k],     p.x); fma2(a1, w[32 + 4 * k + 1], p.y);
                fma2(a2, w[32 + 4 * k + 2], q.x); fma2(a3, w[32 + 4 * k + 3], q.y);
            }
            zbuf[e * 256 + r] = (hsum2(a0) + hsum2(a1)) + (hsum2(a2) + hsum2(a3));
        }
        __syncthreads();   // zbuf complete; all hsh reads done

        // Epilogue: 16 (e,u) pairs per thread, conflict-free stride-1 reads.
        #pragma unroll
        for (int j = 0; j < 16; ++j) {
            const int e = eg * 16 + j;
            float zi = zbuf[e * 256 + u];
            float zf = zbuf[e * 256 + 64 + u];
            float zg = zbuf[e * 256 + 128 + u];
            float zo = zbuf[e * 256 + 192 + u];
            float cn = sigf(zf) * c[j] + sigf(zi) * tanhf_(zg);
            c[j] = cn;
            hsh[e * 68 + u] = sigf(zo) * tanhf_(cn);
        }
    }
    __syncthreads();
    for (int i = tid; i < K2_EPB * HID; i += TPB) {
        int ee = i >> 6, k = i & 63;
        g_h1[(blockBase + ee) * HID + k] = hsh[ee * 68 + k];
    }
    #pragma unroll
    for (int j = 0; j < 16; ++j) {
        const int e = eg * 16 + j;
        g_c1[(blockBase + e) * HID + u] = c[j];
    }
}

// ===========================================================================
// Kernel 3: decoder (SIMT twin scheme, validated round 5 — unchanged).
// ===========================================================================
static constexpr int K3_EPB = 128;
static constexpr int K3_WIH = 0;
static constexpr int K3_WHH = 512;
static constexpr int K3_BS  = K3_WHH + 16384;
static constexpr int K3_OW  = K3_BS + 256;
static constexpr int K3_OB  = K3_OW + 128;
static constexpr int K3_H   = K3_OB + 4;
static constexpr int K3_C   = K3_H + K3_EPB * 68;
static constexpr int K3_X   = K3_C + K3_EPB * 65;
static constexpr int K3_SMEM = (K3_X + K3_EPB * 2) * 4;

__global__ void __launch_bounds__(TPB, 1) k_decoder(
    const float* __restrict__ obs, const float* __restrict__ wih,
    const float* __restrict__ whh, const float* __restrict__ bih,
    const float* __restrict__ bhh, const float* __restrict__ outw,
    const float* __restrict__ outb, float* __restrict__ out, int B)
{
    extern __shared__ float sm[];
    float* wih_s = sm + K3_WIH;
    float* whh_s = sm + K3_WHH;
    float* bs    = sm + K3_BS;
    float* ow    = sm + K3_OW;
    float* ob    = sm + K3_OB;
    float* hsh   = sm + K3_H;
    float* csh   = sm + K3_C;
    float* xsh   = sm + K3_X;

    const int tid = threadIdx.x;
    const size_t blockBase = (size_t)blockIdx.x * K3_EPB;

    for (int i = tid; i < 512; i += TPB) wih_s[i] = wih[i];
    for (int i = tid; i < 16384; i += TPB) whh_s[i] = whh[i];
    for (int i = tid; i < 256; i += TPB) bs[i] = bih[i] + bhh[i];
    for (int i = tid; i < 128; i += TPB) ow[i] = outw[i];
    if (tid < 2) ob[tid] = outb[tid];
    for (int i = tid; i < K3_EPB * HID; i += TPB) {
        int ee = i >> 6, k = i & 63;
        hsh[ee * 68 + k] = g_h1[(blockBase + ee) * HID + k];
        csh[ee * 65 + k] = g_c1[(blockBase + ee) * HID + k];
    }
    for (int i = tid; i < K3_EPB * 2; i += TPB) {
        int ee = i >> 1, j = i & 1;
        xsh[i] = obs[(blockBase + ee) * (OBS * 2) + (OBS - 1) * 2 + j];
    }

    const int lane = tid & 31, warp = tid >> 5;
    const int slot = ((warp & 1) << 5) | lane;
    const int e0 = slot, e1 = slot + 64;
    const int ug = warp >> 1;

    for (int t = 0; t < PRED; ++t) {
        __syncthreads();
        u64 h0[32], h1[32];
        #pragma unroll
        for (int k4 = 0; k4 < 16; ++k4) {
            ulonglong2 p = *(const ulonglong2*)(hsh + e0 * 68 + k4 * 4);
            h0[2 * k4] = p.x; h0[2 * k4 + 1] = p.y;
            ulonglong2 q = *(const ulonglong2*)(hsh + e1 * 68 + k4 * 4);
            h1[2 * k4] = q.x; h1[2 * k4 + 1] = q.y;
        }
        const float x00 = xsh[e0 * 2], x01 = xsh[e0 * 2 + 1];
        const float x10 = xsh[e1 * 2], x11 = xsh[e1 * 2 + 1];
        __syncthreads();

        #pragma unroll 2
        for (int u = 0; u < 16; ++u) {
            const int unit = ug * 16 + u;
            const float bi = bs[unit], bf = bs[64 + unit], bg = bs[128 + unit], bo = bs[192 + unit];
            const float wi0 = wih_s[2*unit],       wi1 = wih_s[2*unit+1];
            const float wf0 = wih_s[2*(64+unit)],  wf1 = wih_s[2*(64+unit)+1];
            const float wg0 = wih_s[2*(128+unit)], wg1 = wih_s[2*(128+unit)+1];
            const float wo0 = wih_s[2*(192+unit)], wo1 = wih_s[2*(192+unit)+1];
            u64 zi0 = pack0(bi + wi0*x00 + wi1*x01), zi1 = pack0(bi + wi0*x10 + wi1*x11);
            u64 zf0 = pack0(bf + wf0*x00 + wf1*x01), zf1 = pack0(bf + wf0*x10 + wf1*x11);
            u64 zg0 = pack0(bg + wg0*x00 + wg1*x01), zg1 = pack0(bg + wg0*x10 + wg1*x11);
            u64 zo0 = pack0(bo + wo0*x00 + wo1*x01), zo1 = pack0(bo + wo0*x10 + wo1*x11);
            const ulonglong2* wi2 = (const ulonglong2*)(whh_s + unit * 64);
            const ulonglong2* wf2 = (const ulonglong2*)(whh_s + (64 + unit) * 64);
            const ulonglong2* wg2 = (const ulonglong2*)(whh_s + (128 + unit) * 64);
            const ulonglong2* wo2 = (const ulonglong2*)(whh_s + (192 + unit) * 64);
            #pragma unroll
            for (int k = 0; k < 16; ++k) {
                ulonglong2 a = wi2[k], b = wf2[k], c2 = wg2[k], d = wo2[k];
                fma2(zi0, a.x, h0[2*k]); fma2(zi0, a.y, h0[2*k+1]);
                fma2(zi1, a.x, h1[2*k]); fma2(zi1, a.y, h1[2*k+1]);
                fma2(zf0, b.x, h0[2*k]); fma2(zf0, b.y, h0[2*k+1]);
                fma2(zf1, b.x, h1[2*k]); fma2(zf1, b.y, h1[2*k+1]);
                fma2(zg0, c2.x, h0[2*k]); fma2(zg0, c2.y, h0[2*k+1]);
                fma2(zg1, c2.x, h1[2*k]); fma2(zg1, c2.y, h1[2*k+1]);
                fma2(zo0, d.x, h0[2*k]); fma2(zo0, d.y, h0[2*k+1]);
                fma2(zo1, d.x, h1[2*k]); fma2(zo1, d.y, h1[2*k+1]);
            }
            float co0 = csh[e0 * 65 + unit];
            float cn0 = sigf(hsum2(zf0)) * co0 + sigf(hsum2(zi0)) * tanhf_(hsum2(zg0));
            csh[e0 * 65 + unit] = cn0;
            hsh[e0 * 68 + unit] = sigf(hsum2(zo0)) * tanhf_(cn0);
            float co1 = csh[e1 * 65 + unit];
            float cn1 = sigf(hsum2(zf1)) * co1 + sigf(hsum2(zi1)) * tanhf_(hsum2(zg1));
            csh[e1 * 65 + unit] = cn1;
            hsh[e1 * 68 + unit] = sigf(hsum2(zo1)) * tanhf_(cn1);
        }
        __syncthreads();
        if (ug == 0) {
            #pragma unroll
            for (int ei = 0; ei < 2; ++ei) {
                const int e = ei ? e1 : e0;
                float o0 = ob[0], o1 = ob[1];
                #pragma unroll
                for (int k4 = 0; k4 < 16; ++k4) {
                    float4 hh = *(const float4*)(hsh + e * 68 + k4 * 4);
                    float4 w0 = *(const float4*)(ow + k4 * 4);
                    float4 w1 = *(const float4*)(ow + 64 + k4 * 4);
                    o0 += w0.x * hh.x + w0.y * hh.y + w0.z * hh.z + w0.w * hh.w;
                    o1 += w1.x * hh.x + w1.y * hh.y + w1.z * hh.z + w1.w * hh.w;
                }
                out[(blockBase + e) * (PRED * 2) + t * 2 + 0] = o0;
                out[(blockBase + e) * (PRED * 2) + t * 2 + 1] = o1;
                xsh[e * 2] = o0;
                xsh[e * 2 + 1] = o1;
            }
        }
    }
}

// ---------------------------------------------------------------------------
extern "C" void kernel_launch(void* const* d_in, const int* in_sizes, int n_in,
                              void* d_out, int out_size)
{
    const float* obs     = (const float*)d_in[0];
    const float* w_ih_l0 = (const float*)d_in[1];
    const float* w_hh_l0 = (const float*)d_in[2];
    const float* b_ih_l0 = (const float*)d_in[3];
    const float* b_hh_l0 = (const float*)d_in[4];
    const float* w_ih_l1 = (const float*)d_in[5];
    const float* w_hh_l1 = (const float*)d_in[6];
    const float* b_ih_l1 = (const float*)d_in[7];
    const float* b_hh_l1 = (const float*)d_in[8];
    const float* dec_w_ih = (const float*)d_in[9];
    const float* dec_w_hh = (const float*)d_in[10];
    const float* dec_b_ih = (const float*)d_in[11];
    const float* dec_b_hh = (const float*)d_in[12];
    const float* out_w   = (const float*)d_in[13];
    const float* out_b   = (const float*)d_in[14];
    float* out = (float*)d_out;

    const int B = in_sizes[0] / (OBS * 2);

    cudaFuncSetAttribute(k_layer0,  cudaFuncAttributeMaxDynamicSharedMemorySize, K1_SMEM);
    cudaFuncSetAttribute(k_layer1,  cudaFuncAttributeMaxDynamicSharedMemorySize, K2_SMEM);
    cudaFuncSetAttribute(k_decoder, cudaFuncAttributeMaxDynamicSharedMemorySize, K3_SMEM);

    k_layer0<<<B / K1_EPB, TPB, K1_SMEM>>>(obs, w_ih_l0, w_hh_l0, b_ih_l0, b_hh_l0, B);
    k_layer1<<<B / K2_EPB, TPB, K2_SMEM>>>(w_ih_l1, w_hh_l1, b_ih_l1, b_hh_l1, B);
    k_decoder<<<B / K3_EPB, TPB, K3_SMEM>>>(obs, dec_w_ih, dec_w_hh, dec_b_ih, dec_b_hh,
                                            out_w, out_b, out, B);
}

// round 9
// speedup vs baseline: 1.6248x; 1.5071x over previous
#include <cuda_runtime.h>
#include <cstdint>

// Problem constants
static constexpr int HID  = 64;
static constexpr int OBS  = 20;
static constexpr int PRED = 12;
static constexpr int BMAX = 32768;

static constexpr int TPB = 256;

// Scratch (allocation-free rule: __device__ globals)
__device__ float g_hs1[(size_t)OBS * BMAX * HID];
__device__ float g_h1[(size_t)BMAX * HID];
__device__ float g_c1[(size_t)BMAX * HID];

using u64 = unsigned long long;

__device__ __forceinline__ void fma2(u64& d, u64 a, u64 b) {
    asm("fma.rn.f32x2 %0, %1, %2, %0;" : "+l"(d) : "l"(a), "l"(b));
}
__device__ __forceinline__ u64 pack0(float x) { return (u64)__float_as_uint(x); }
__device__ __forceinline__ float hsum2(u64 v) {
    return __uint_as_float((unsigned)v) + __uint_as_float((unsigned)(v >> 32));
}
__device__ __forceinline__ float sigf(float x) {
    return __fdividef(1.0f, 1.0f + __expf(-x));
}
__device__ __forceinline__ float tanhf_(float x) {
    return fmaf(2.0f, sigf(2.0f * x), -1.0f);
}

// bf16x2 pack: low 16 bits = lo value, high 16 bits = hi value
__device__ __forceinline__ uint32_t pk_bf2(float lo, float hi) {
    uint32_t r;
    asm("cvt.rn.bf16x2.f32 %0, %1, %2;" : "=r"(r) : "f"(hi), "f"(lo));
    return r;
}
__device__ __forceinline__ float bf_lo(uint32_t p) { return __uint_as_float(p << 16); }
__device__ __forceinline__ float bf_hi(uint32_t p) { return __uint_as_float(p & 0xffff0000u); }

#define MMA_B16(c, a, b0, b1) \
    asm volatile("mma.sync.aligned.m16n8k16.row.col.f32.bf16.bf16.f32 " \
        "{%0,%1,%2,%3}, {%4,%5,%6,%7}, {%8,%9}, {%0,%1,%2,%3};" \
        : "+f"((c)[0]), "+f"((c)[1]), "+f"((c)[2]), "+f"((c)[3]) \
        : "r"((a)[0]), "r"((a)[1]), "r"((a)[2]), "r"((a)[3]), "r"(b0), "r"(b1))

// ===========================================================================
// Kernel 1: encoder layer 0 (SIMT twin scheme, validated — unchanged).
// ===========================================================================
static constexpr int K1_EPB = 128;
static constexpr int K1_WIH = 0;
static constexpr int K1_WHH = 512;
static constexpr int K1_BS  = K1_WHH + 16384;
static constexpr int K1_H   = K1_BS + 256;
static constexpr int K1_C   = K1_H + K1_EPB * 68;
static constexpr int K1_OBS = K1_C + K1_EPB * 65;
static constexpr int K1_SMEM = (K1_OBS + K1_EPB * OBS * 2) * 4;

__global__ void __launch_bounds__(TPB, 1) k_layer0(
    const float* __restrict__ obs, const float* __restrict__ wih,
    const float* __restrict__ whh, const float* __restrict__ bih,
    const float* __restrict__ bhh, int B)
{
    extern __shared__ float sm[];
    float* wih_s = sm + K1_WIH;
    float* whh_s = sm + K1_WHH;
    float* bs    = sm + K1_BS;
    float* hsh   = sm + K1_H;
    float* csh   = sm + K1_C;
    float* obs_s = sm + K1_OBS;

    const int tid = threadIdx.x;
    const size_t blockBase = (size_t)blockIdx.x * K1_EPB;

    for (int i = tid; i < 512; i += TPB) wih_s[i] = wih[i];
    for (int i = tid; i < 16384; i += TPB) whh_s[i] = whh[i];
    for (int i = tid; i < 256; i += TPB) bs[i] = bih[i] + bhh[i];
    for (int i = tid; i < K1_EPB * 68; i += TPB) hsh[i] = 0.f;
    for (int i = tid; i < K1_EPB * 65; i += TPB) csh[i] = 0.f;
    for (int i = tid; i < K1_EPB * OBS * 2; i += TPB) {
        int ee = i / (OBS * 2), j = i % (OBS * 2);
        obs_s[ee * (OBS * 2) + j] = obs[(blockBase + ee) * (OBS * 2) + j];
    }

    const int lane = tid & 31, warp = tid >> 5;
    const int slot = ((warp & 1) << 5) | lane;
    const int e0 = slot, e1 = slot + 64;
    const int ug = warp >> 1;

    for (int t = 0; t < OBS; ++t) {
        __syncthreads();
        if (t > 0) {
            float4* dst = (float4*)(g_hs1 + ((size_t)(t - 1) * B + blockBase) * HID);
            for (int i = tid; i < K1_EPB * 16; i += TPB) {
                int ee = i >> 4, k4 = i & 15;
                dst[i] = *(const float4*)(hsh + ee * 68 + k4 * 4);
            }
        }
        u64 h0[32], h1[32];
        #pragma unroll
        for (int k4 = 0; k4 < 16; ++k4) {
            ulonglong2 p = *(const ulonglong2*)(hsh + e0 * 68 + k4 * 4);
            h0[2 * k4] = p.x; h0[2 * k4 + 1] = p.y;
            ulonglong2 q = *(const ulonglong2*)(hsh + e1 * 68 + k4 * 4);
            h1[2 * k4] = q.x; h1[2 * k4 + 1] = q.y;
        }
        const float x00 = obs_s[e0 * 40 + 2 * t], x01 = obs_s[e0 * 40 + 2 * t + 1];
        const float x10 = obs_s[e1 * 40 + 2 * t], x11 = obs_s[e1 * 40 + 2 * t + 1];
        __syncthreads();

        #pragma unroll 2
        for (int u = 0; u < 16; ++u) {
            const int unit = ug * 16 + u;
            const float bi = bs[unit], bf = bs[64 + unit], bg = bs[128 + unit], bo = bs[192 + unit];
            const float wi0 = wih_s[2*unit],       wi1 = wih_s[2*unit+1];
            const float wf0 = wih_s[2*(64+unit)],  wf1 = wih_s[2*(64+unit)+1];
            const float wg0 = wih_s[2*(128+unit)], wg1 = wih_s[2*(128+unit)+1];
            const float wo0 = wih_s[2*(192+unit)], wo1 = wih_s[2*(192+unit)+1];
            u64 zi0 = pack0(bi + wi0*x00 + wi1*x01), zi1 = pack0(bi + wi0*x10 + wi1*x11);
            u64 zf0 = pack0(bf + wf0*x00 + wf1*x01), zf1 = pack0(bf + wf0*x10 + wf1*x11);
            u64 zg0 = pack0(bg + wg0*x00 + wg1*x01), zg1 = pack0(bg + wg0*x10 + wg1*x11);
            u64 zo0 = pack0(bo + wo0*x00 + wo1*x01), zo1 = pack0(bo + wo0*x10 + wo1*x11);
            const ulonglong2* wi2 = (const ulonglong2*)(whh_s + unit * 64);
            const ulonglong2* wf2 = (const ulonglong2*)(whh_s + (64 + unit) * 64);
            const ulonglong2* wg2 = (const ulonglong2*)(whh_s + (128 + unit) * 64);
            const ulonglong2* wo2 = (const ulonglong2*)(whh_s + (192 + unit) * 64);
            #pragma unroll
            for (int k = 0; k < 16; ++k) {
                ulonglong2 a = wi2[k], b = wf2[k], c2 = wg2[k], d = wo2[k];
                fma2(zi0, a.x, h0[2*k]); fma2(zi0, a.y, h0[2*k+1]);
                fma2(zi1, a.x, h1[2*k]); fma2(zi1, a.y, h1[2*k+1]);
                fma2(zf0, b.x, h0[2*k]); fma2(zf0, b.y, h0[2*k+1]);
                fma2(zf1, b.x, h1[2*k]); fma2(zf1, b.y, h1[2*k+1]);
                fma2(zg0, c2.x, h0[2*k]); fma2(zg0, c2.y, h0[2*k+1]);
                fma2(zg1, c2.x, h1[2*k]); fma2(zg1, c2.y, h1[2*k+1]);
                fma2(zo0, d.x, h0[2*k]); fma2(zo0, d.y, h0[2*k+1]);
                fma2(zo1, d.x, h1[2*k]); fma2(zo1, d.y, h1[2*k+1]);
            }
            float co0 = csh[e0 * 65 + unit];
            float cn0 = sigf(hsum2(zf0)) * co0 + sigf(hsum2(zi0)) * tanhf_(hsum2(zg0));
            csh[e0 * 65 + unit] = cn0;
            hsh[e0 * 68 + unit] = sigf(hsum2(zo0)) * tanhf_(cn0);
            float co1 = csh[e1 * 65 + unit];
            float cn1 = sigf(hsum2(zf1)) * co1 + sigf(hsum2(zi1)) * tanhf_(hsum2(zg1));
            csh[e1 * 65 + unit] = cn1;
            hsh[e1 * 68 + unit] = sigf(hsum2(zo1)) * tanhf_(cn1);
        }
    }
    __syncthreads();
    {
        float4* dst = (float4*)(g_hs1 + ((size_t)(OBS - 1) * B + blockBase) * HID);
        for (int i = tid; i < K1_EPB * 16; i += TPB) {
            int ee = i >> 4, k4 = i & 15;
            dst[i] = *(const float4*)(hsh + ee * 68 + k4 * 4);
        }
    }
}

// ===========================================================================
// Kernel 2 v3: layer 1 via mma.sync m16n8k16 bf16 (hi/lo 3-term split).
// z[256,64] = Wcat[256,128] @ v[128,64] per CTA-step.
// Warp w owns M rows 32w..32w+31 (2 m-tiles) x all N (e) x all K.
// A (weights) persistent in regs: ahi/alo [2mt][8kt][4] = 128 regs, built once.
// B (activations) from smem vsh (fp32, e-major stride 132), converted per use.
// D -> zbuf (r-major stride 66) -> validated round-8 epilogue ownership.
// ===========================================================================
static constexpr int K2_EPB = 64;
static constexpr int VS = 132;                    // vsh row stride (floats)
static constexpr int ZS = 66;                     // zbuf row stride (floats)
static constexpr int K2_V = 0;                    // 64*132   = 8448 floats
static constexpr int K2_Z = K2_EPB * VS;          // 256*66   = 16896 floats
static constexpr int K2_B = K2_Z + 256 * ZS;      // bias 256
static constexpr int K2_SMEM = (K2_B + 256) * 4;  // 102,400 B

__global__ void __launch_bounds__(TPB, 1) k_layer1(
    const float* __restrict__ wih, const float* __restrict__ whh,
    const float* __restrict__ bih, const float* __restrict__ bhh, int B)
{
    extern __shared__ float sm[];
    float* vsh  = sm + K2_V;
    float* zbuf = sm + K2_Z;
    float* bs   = sm + K2_B;

    const int tid = threadIdx.x;
    const size_t blockBase = (size_t)blockIdx.x * K2_EPB;
    const int warp = tid >> 5;
    const int gid  = (tid & 31) >> 2;   // groupID (lane>>2)
    const int tig  = tid & 3;           // thread-in-group
    const int rbase = warp * 32;

    // --- Build persistent A fragments (Wcat rows rbase..rbase+31, hi+lo) ---
    uint32_t ahi[64], alo[64];
    #pragma unroll
    for (int mt = 0; mt < 2; ++mt)
    #pragma unroll
    for (int kt = 0; kt < 8; ++kt)
    #pragma unroll
    for (int j = 0; j < 4; ++j) {
        int row = rbase + 16 * mt + gid + (j & 1) * 8;
        int col = 16 * kt + 2 * tig + (j >> 1) * 8;
        const float* src = (col < 64) ? (wih + row * 64 + col)
                                      : (whh + row * 64 + (col - 64));
        float f0 = src[0], f1 = src[1];
        uint32_t h = pk_bf2(f0, f1);
        uint32_t l = pk_bf2(f0 - bf_lo(h), f1 - bf_hi(h));
        ahi[(mt * 8 + kt) * 4 + j] = h;
        alo[(mt * 8 + kt) * 4 + j] = l;
    }

    for (int i = tid; i < 256; i += TPB) bs[i] = bih[i] + bhh[i];
    for (int i = tid; i < K2_EPB * VS; i += TPB) vsh[i] = 0.f;   // h-part zero init

    // Epilogue ownership (validated round 8): unit u, elems eg*16..+15, c in regs.
    const int u  = tid & 63;
    const int eg = tid >> 6;
    float c[16];
    #pragma unroll
    for (int j = 0; j < 16; ++j) c[j] = 0.f;

    #pragma unroll 1
    for (int t = 0; t < OBS; ++t) {
        __syncthreads();   // prev epilogue h-writes visible; vsh x-part free
        {
            const float4* src = (const float4*)(g_hs1 + ((size_t)t * B + blockBase) * HID);
            for (int i = tid; i < K2_EPB * 16; i += TPB) {
                int ee = i >> 4, k4 = i & 15;
                *(float4*)(vsh + ee * VS + k4 * 4) = src[i];
            }
        }
        __syncthreads();   // full v ready

        #pragma unroll 1
        for (int nh = 0; nh < 2; ++nh) {
            float acc[32];
            #pragma unroll
            for (int i = 0; i < 32; ++i) acc[i] = 0.f;

            #pragma unroll
            for (int kt = 0; kt < 8; ++kt) {
                #pragma unroll
                for (int nt = 0; nt < 4; ++nt) {
                    const int e  = (nh * 4 + nt) * 8 + gid;
                    const int k0 = kt * 16 + 2 * tig;
                    float2 p0 = *(const float2*)(vsh + e * VS + k0);
                    float2 p1 = *(const float2*)(vsh + e * VS + k0 + 8);
                    uint32_t bh0 = pk_bf2(p0.x, p0.y);
                    uint32_t bh1 = pk_bf2(p1.x, p1.y);
                    uint32_t bl0 = pk_bf2(p0.x - bf_lo(bh0), p0.y - bf_hi(bh0));
                    uint32_t bl1 = pk_bf2(p1.x - bf_lo(bh1), p1.y - bf_hi(bh1));
                    #pragma unroll
                    for (int mt = 0; mt < 2; ++mt) {
                        float* a = acc + (mt * 4 + nt) * 4;
                        const uint32_t* Ah = ahi + (mt * 8 + kt) * 4;
                        const uint32_t* Al = alo + (mt * 8 + kt) * 4;
                        MMA_B16(a, Ah, bh0, bh1);
                        MMA_B16(a, Ah, bl0, bl1);
                        MMA_B16(a, Al, bh0, bh1);
                    }
                }
            }
            // store acc -> zbuf  (C frag: c0/c1 = (gid, 2tig/+1), c2/c3 = (+8 row))
            #pragma unroll
            for (int mt = 0; mt < 2; ++mt)
            #pragma unroll
            for (int nt = 0; nt < 4; ++nt) {
                const int e0 = (nh * 4 + nt) * 8 + 2 * tig;
                const int r0 = rbase + 16 * mt + gid;
                const float* a = acc + (mt * 4 + nt) * 4;
                *(float2*)(zbuf + r0 * ZS + e0)       = make_float2(a[0], a[1]);
                *(float2*)(zbuf + (r0 + 8) * ZS + e0) = make_float2(a[2], a[3]);
            }
        }
        __syncthreads();   // zbuf ready; all vsh reads done

        const bool last = (t == OBS - 1);
        #pragma unroll
        for (int j = 0; j < 16; ++j) {
            const int e = eg * 16 + j;
            float zi = zbuf[u * ZS + e]          + bs[u];
            float zf = zbuf[(64 + u) * ZS + e]   + bs[64 + u];
            float zg = zbuf[(128 + u) * ZS + e]  + bs[128 + u];
            float zo = zbuf[(192 + u) * ZS + e]  + bs[192 + u];
            float cn = sigf(zf) * c[j] + sigf(zi) * tanhf_(zg);
            c[j] = cn;
            float hn = sigf(zo) * tanhf_(cn);
            vsh[e * VS + 64 + u] = hn;
            if (last) {
                g_h1[(blockBase + e) * HID + u] = hn;
                g_c1[(blockBase + e) * HID + u] = cn;
            }
        }
    }
}

// ===========================================================================
// Kernel 3: decoder (SIMT twin scheme, validated — unchanged).
// ===========================================================================
static constexpr int K3_EPB = 128;
static constexpr int K3_WIH = 0;
static constexpr int K3_WHH = 512;
static constexpr int K3_BS  = K3_WHH + 16384;
static constexpr int K3_OW  = K3_BS + 256;
static constexpr int K3_OB  = K3_OW + 128;
static constexpr int K3_H   = K3_OB + 4;
static constexpr int K3_C   = K3_H + K3_EPB * 68;
static constexpr int K3_X   = K3_C + K3_EPB * 65;
static constexpr int K3_SMEM = (K3_X + K3_EPB * 2) * 4;

__global__ void __launch_bounds__(TPB, 1) k_decoder(
    const float* __restrict__ obs, const float* __restrict__ wih,
    const float* __restrict__ whh, const float* __restrict__ bih,
    const float* __restrict__ bhh, const float* __restrict__ outw,
    const float* __restrict__ outb, float* __restrict__ out, int B)
{
    extern __shared__ float sm[];
    float* wih_s = sm + K3_WIH;
    float* whh_s = sm + K3_WHH;
    float* bs    = sm + K3_BS;
    float* ow    = sm + K3_OW;
    float* ob    = sm + K3_OB;
    float* hsh   = sm + K3_H;
    float* csh   = sm + K3_C;
    float* xsh   = sm + K3_X;

    const int tid = threadIdx.x;
    const size_t blockBase = (size_t)blockIdx.x * K3_EPB;

    for (int i = tid; i < 512; i += TPB) wih_s[i] = wih[i];
    for (int i = tid; i < 16384; i += TPB) whh_s[i] = whh[i];
    for (int i = tid; i < 256; i += TPB) bs[i] = bih[i] + bhh[i];
    for (int i = tid; i < 128; i += TPB) ow[i] = outw[i];
    if (tid < 2) ob[tid] = outb[tid];
    for (int i = tid; i < K3_EPB * HID; i += TPB) {
        int ee = i >> 6, k = i & 63;
        hsh[ee * 68 + k] = g_h1[(blockBase + ee) * HID + k];
        csh[ee * 65 + k] = g_c1[(blockBase + ee) * HID + k];
    }
    for (int i = tid; i < K3_EPB * 2; i += TPB) {
        int ee = i >> 1, j = i & 1;
        xsh[i] = obs[(blockBase + ee) * (OBS * 2) + (OBS - 1) * 2 + j];
    }

    const int lane = tid & 31, warp = tid >> 5;
    const int slot = ((warp & 1) << 5) | lane;
    const int e0 = slot, e1 = slot + 64;
    const int ug = warp >> 1;

    for (int t = 0; t < PRED; ++t) {
        __syncthreads();
        u64 h0[32], h1[32];
        #pragma unroll
        for (int k4 = 0; k4 < 16; ++k4) {
            ulonglong2 p = *(const ulonglong2*)(hsh + e0 * 68 + k4 * 4);
            h0[2 * k4] = p.x; h0[2 * k4 + 1] = p.y;
            ulonglong2 q = *(const ulonglong2*)(hsh + e1 * 68 + k4 * 4);
            h1[2 * k4] = q.x; h1[2 * k4 + 1] = q.y;
        }
        const float x00 = xsh[e0 * 2], x01 = xsh[e0 * 2 + 1];
        const float x10 = xsh[e1 * 2], x11 = xsh[e1 * 2 + 1];
        __syncthreads();

        #pragma unroll 2
        for (int u = 0; u < 16; ++u) {
            const int unit = ug * 16 + u;
            const float bi = bs[unit], bf = bs[64 + unit], bg = bs[128 + unit], bo = bs[192 + unit];
            const float wi0 = wih_s[2*unit],       wi1 = wih_s[2*unit+1];
            const float wf0 = wih_s[2*(64+unit)],  wf1 = wih_s[2*(64+unit)+1];
            const float wg0 = wih_s[2*(128+unit)], wg1 = wih_s[2*(128+unit)+1];
            const float wo0 = wih_s[2*(192+unit)], wo1 = wih_s[2*(192+unit)+1];
            u64 zi0 = pack0(bi + wi0*x00 + wi1*x01), zi1 = pack0(bi + wi0*x10 + wi1*x11);
            u64 zf0 = pack0(bf + wf0*x00 + wf1*x01), zf1 = pack0(bf + wf0*x10 + wf1*x11);
            u64 zg0 = pack0(bg + wg0*x00 + wg1*x01), zg1 = pack0(bg + wg0*x10 + wg1*x11);
            u64 zo0 = pack0(bo + wo0*x00 + wo1*x01), zo1 = pack0(bo + wo0*x10 + wo1*x11);
            const ulonglong2* wi2 = (const ulonglong2*)(whh_s + unit * 64);
            const ulonglong2* wf2 = (const ulonglong2*)(whh_s + (64 + unit) * 64);
            const ulonglong2* wg2 = (const ulonglong2*)(whh_s + (128 + unit) * 64);
            const ulonglong2* wo2 = (const ulonglong2*)(whh_s + (192 + unit) * 64);
            #pragma unroll
            for (int k = 0; k < 16; ++k) {
                ulonglong2 a = wi2[k], b = wf2[k], c2 = wg2[k], d = wo2[k];
                fma2(zi0, a.x, h0[2*k]); fma2(zi0, a.y, h0[2*k+1]);
                fma2(zi1, a.x, h1[2*k]); fma2(zi1, a.y, h1[2*k+1]);
                fma2(zf0, b.x, h0[2*k]); fma2(zf0, b.y, h0[2*k+1]);
                fma2(zf1, b.x, h1[2*k]); fma2(zf1, b.y, h1[2*k+1]);
                fma2(zg0, c2.x, h0[2*k]); fma2(zg0, c2.y, h0[2*k+1]);
                fma2(zg1, c2.x, h1[2*k]); fma2(zg1, c2.y, h1[2*k+1]);
                fma2(zo0, d.x, h0[2*k]); fma2(zo0, d.y, h0[2*k+1]);
                fma2(zo1, d.x, h1[2*k]); fma2(zo1, d.y, h1[2*k+1]);
            }
            float co0 = csh[e0 * 65 + unit];
            float cn0 = sigf(hsum2(zf0)) * co0 + sigf(hsum2(zi0)) * tanhf_(hsum2(zg0));
            csh[e0 * 65 + unit] = cn0;
            hsh[e0 * 68 + unit] = sigf(hsum2(zo0)) * tanhf_(cn0);
            float co1 = csh[e1 * 65 + unit];
            float cn1 = sigf(hsum2(zf1)) * co1 + sigf(hsum2(zi1)) * tanhf_(hsum2(zg1));
            csh[e1 * 65 + unit] = cn1;
            hsh[e1 * 68 + unit] = sigf(hsum2(zo1)) * tanhf_(cn1);
        }
        __syncthreads();
        if (ug == 0) {
            #pragma unroll
            for (int ei = 0; ei < 2; ++ei) {
                const int e = ei ? e1 : e0;
                float o0 = ob[0], o1 = ob[1];
                #pragma unroll
                for (int k4 = 0; k4 < 16; ++k4) {
                    float4 hh = *(const float4*)(hsh + e * 68 + k4 * 4);
                    float4 w0 = *(const float4*)(ow + k4 * 4);
                    float4 w1 = *(const float4*)(ow + 64 + k4 * 4);
                    o0 += w0.x * hh.x + w0.y * hh.y + w0.z * hh.z + w0.w * hh.w;
                    o1 += w1.x * hh.x + w1.y * hh.y + w1.z * hh.z + w1.w * hh.w;
                }
                out[(blockBase + e) * (PRED * 2) + t * 2 + 0] = o0;
                out[(blockBase + e) * (PRED * 2) + t * 2 + 1] = o1;
                xsh[e * 2] = o0;
                xsh[e * 2 + 1] = o1;
            }
        }
    }
}

// ---------------------------------------------------------------------------
extern "C" void kernel_launch(void* const* d_in, const int* in_sizes, int n_in,
                              void* d_out, int out_size)
{
    const float* obs     = (const float*)d_in[0];
    const float* w_ih_l0 = (const float*)d_in[1];
    const float* w_hh_l0 = (const float*)d_in[2];
    const float* b_ih_l0 = (const float*)d_in[3];
    const float* b_hh_l0 = (const float*)d_in[4];
    const float* w_ih_l1 = (const float*)d_in[5];
    const float* w_hh_l1 = (const float*)d_in[6];
    const float* b_ih_l1 = (const float*)d_in[7];
    const float* b_hh_l1 = (const float*)d_in[8];
    const float* dec_w_ih = (const float*)d_in[9];
    const float* dec_w_hh = (const float*)d_in[10];
    const float* dec_b_ih = (const float*)d_in[11];
    const float* dec_b_hh = (const float*)d_in[12];
    const float* out_w   = (const float*)d_in[13];
    const float* out_b   = (const float*)d_in[14];
    float* out = (float*)d_out;

    const int B = in_sizes[0] / (OBS * 2);

    cudaFuncSetAttribute(k_layer0,  cudaFuncAttributeMaxDynamicSharedMemorySize, K1_SMEM);
    cudaFuncSetAttribute(k_layer1,  cudaFuncAttributeMaxDynamicSharedMemorySize, K2_SMEM);
    cudaFuncSetAttribute(k_decoder, cudaFuncAttributeMaxDynamicSharedMemorySize, K3_SMEM);

    k_layer0<<<B / K1_EPB, TPB, K1_SMEM>>>(obs, w_ih_l0, w_hh_l0, b_ih_l0, b_hh_l0, B);
    k_layer1<<<B / K2_EPB, TPB, K2_SMEM>>>(w_ih_l1, w_hh_l1, b_ih_l1, b_hh_l1, B);
    k_decoder<<<B / K3_EPB, TPB, K3_SMEM>>>(obs, dec_w_ih, dec_w_hh, dec_b_ih, dec_b_hh,
                                            out_w, out_b, out, B);
}

// round 10
// speedup vs baseline: 2.0730x; 1.2758x over previous
#include <cuda_runtime.h>
#include <cstdint>

// Problem constants
static constexpr int HID  = 64;
static constexpr int OBS  = 20;
static constexpr int PRED = 12;
static constexpr int BMAX = 32768;

static constexpr int TPB = 256;

// Scratch (allocation-free rule: __device__ globals)
__device__ float g_hs1[(size_t)OBS * BMAX * HID];
__device__ float g_h1[(size_t)BMAX * HID];
__device__ float g_c1[(size_t)BMAX * HID];

__device__ __forceinline__ float sigf(float x) {
    return __fdividef(1.0f, 1.0f + __expf(-x));
}
__device__ __forceinline__ float tanhf_(float x) {
    return fmaf(2.0f, sigf(2.0f * x), -1.0f);
}

// bf16x2 pack: low 16 bits = lo value, high 16 bits = hi value
__device__ __forceinline__ uint32_t pk_bf2(float lo, float hi) {
    uint32_t r;
    asm("cvt.rn.bf16x2.f32 %0, %1, %2;" : "=r"(r) : "f"(hi), "f"(lo));
    return r;
}
__device__ __forceinline__ float bf_lo(uint32_t p) { return __uint_as_float(p << 16); }
__device__ __forceinline__ float bf_hi(uint32_t p) { return __uint_as_float(p & 0xffff0000u); }

#define MMA_B16(c, a, b0, b1) \
    asm volatile("mma.sync.aligned.m16n8k16.row.col.f32.bf16.bf16.f32 " \
        "{%0,%1,%2,%3}, {%4,%5,%6,%7}, {%8,%9}, {%0,%1,%2,%3};" \
        : "+f"((c)[0]), "+f"((c)[1]), "+f"((c)[2]), "+f"((c)[3]) \
        : "r"((a)[0]), "r"((a)[1]), "r"((a)[2]), "r"((a)[3]), "r"(b0), "r"(b1))

static constexpr int VS = 132;   // layer1 vsh stride
static constexpr int ZS = 66;    // zbuf stride (all kernels)
static constexpr int HS = 68;    // h-only vsh stride (layer0/decoder)

// ===========================================================================
// Kernel 1 v2: encoder layer 0 via mma.sync (K=64 on h; x-term in epilogue).
// Warp w: M rows 32w..32w+31; A = Whh hi/lo persistent (2mt x 4kt x 4).
// ===========================================================================
static constexpr int L0_V   = 0;                       // 64*68  = 4352
static constexpr int L0_Z   = 64 * HS;                 // 256*66 = 16896
static constexpr int L0_OBS = L0_Z + 256 * ZS;         // 64*40  = 2560
static constexpr int L0_SMEM = (L0_OBS + 64 * 40) * 4; // 95,232 B

__global__ void __launch_bounds__(TPB, 1) k_layer0(
    const float* __restrict__ obs, const float* __restrict__ wih,
    const float* __restrict__ whh, const float* __restrict__ bih,
    const float* __restrict__ bhh, int B)
{
    extern __shared__ float sm[];
    float* vsh   = sm + L0_V;
    float* zbuf  = sm + L0_Z;
    float* obs_s = sm + L0_OBS;

    const int tid = threadIdx.x;
    const size_t blockBase = (size_t)blockIdx.x * 64;
    const int warp = tid >> 5;
    const int gid  = (tid & 31) >> 2;
    const int tig  = tid & 3;
    const int rbase = warp * 32;

    // Persistent A fragments from Whh (K=64 -> 4 k-tiles)
    uint32_t ahi[32], alo[32];
    #pragma unroll
    for (int mt = 0; mt < 2; ++mt)
    #pragma unroll
    for (int kt = 0; kt < 4; ++kt)
    #pragma unroll
    for (int j = 0; j < 4; ++j) {
        int row = rbase + 16 * mt + gid + (j & 1) * 8;
        int col = 16 * kt + 2 * tig + (j >> 1) * 8;
        float f0 = whh[row * 64 + col], f1 = whh[row * 64 + col + 1];
        uint32_t h = pk_bf2(f0, f1);
        uint32_t l = pk_bf2(f0 - bf_lo(h), f1 - bf_hi(h));
        ahi[(mt * 4 + kt) * 4 + j] = h;
        alo[(mt * 4 + kt) * 4 + j] = l;
    }

    // Epilogue constants (unit u): x-weights + combined bias, in registers
    const int u  = tid & 63;
    const int eg = tid >> 6;
    const float wxi0 = wih[2*u],           wxi1 = wih[2*u+1];
    const float wxf0 = wih[2*(64+u)],      wxf1 = wih[2*(64+u)+1];
    const float wxg0 = wih[2*(128+u)],     wxg1 = wih[2*(128+u)+1];
    const float wxo0 = wih[2*(192+u)],     wxo1 = wih[2*(192+u)+1];
    const float bi = bih[u]       + bhh[u];
    const float bf = bih[64+u]    + bhh[64+u];
    const float bg = bih[128+u]   + bhh[128+u];
    const float bo = bih[192+u]   + bhh[192+u];

    for (int i = tid; i < 64 * HS; i += TPB) vsh[i] = 0.f;   // h0 = 0
    for (int i = tid; i < 64 * 40; i += TPB) {
        int ee = i / 40, j = i % 40;
        obs_s[i] = obs[(blockBase + ee) * 40 + j];
    }

    float c[16];
    #pragma unroll
    for (int j = 0; j < 16; ++j) c[j] = 0.f;

    #pragma unroll 1
    for (int t = 0; t < OBS; ++t) {
        __syncthreads();   // h(t-1) in vsh visible; zbuf free
        if (t > 0) {       // coalesced store of h(t-1)
            float4* dst = (float4*)(g_hs1 + ((size_t)(t - 1) * B + blockBase) * HID);
            for (int i = tid; i < 64 * 16; i += TPB) {
                int ee = i >> 4, k4 = i & 15;
                dst[i] = *(const float4*)(vsh + ee * HS + k4 * 4);
            }
        }

        // GEMM: z[256,64] += Whh @ h
        #pragma unroll 1
        for (int nh = 0; nh < 2; ++nh) {
            float acc[32];
            #pragma unroll
            for (int i = 0; i < 32; ++i) acc[i] = 0.f;
            #pragma unroll
            for (int kt = 0; kt < 4; ++kt) {
                #pragma unroll
                for (int nt = 0; nt < 4; ++nt) {
                    const int e  = (nh * 4 + nt) * 8 + gid;
                    const int k0 = kt * 16 + 2 * tig;
                    float2 p0 = *(const float2*)(vsh + e * HS + k0);
                    float2 p1 = *(const float2*)(vsh + e * HS + k0 + 8);
                    uint32_t bh0 = pk_bf2(p0.x, p0.y);
                    uint32_t bh1 = pk_bf2(p1.x, p1.y);
                    uint32_t bl0 = pk_bf2(p0.x - bf_lo(bh0), p0.y - bf_hi(bh0));
                    uint32_t bl1 = pk_bf2(p1.x - bf_lo(bh1), p1.y - bf_hi(bh1));
                    #pragma unroll
                    for (int mt = 0; mt < 2; ++mt) {
                        float* a = acc + (mt * 4 + nt) * 4;
                        const uint32_t* Ah = ahi + (mt * 4 + kt) * 4;
                        const uint32_t* Al = alo + (mt * 4 + kt) * 4;
                        MMA_B16(a, Ah, bh0, bh1);
                        MMA_B16(a, Ah, bl0, bl1);
                        MMA_B16(a, Al, bh0, bh1);
                    }
                }
            }
            #pragma unroll
            for (int mt = 0; mt < 2; ++mt)
            #pragma unroll
            for (int nt = 0; nt < 4; ++nt) {
                const int e0 = (nh * 4 + nt) * 8 + 2 * tig;
                const int r0 = rbase + 16 * mt + gid;
                const float* a = acc + (mt * 4 + nt) * 4;
                *(float2*)(zbuf + r0 * ZS + e0)       = make_float2(a[0], a[1]);
                *(float2*)(zbuf + (r0 + 8) * ZS + e0) = make_float2(a[2], a[3]);
            }
        }
        __syncthreads();   // zbuf ready; vsh reads (GEMM + store) done

        #pragma unroll
        for (int j = 0; j < 16; ++j) {
            const int e = eg * 16 + j;
            const float x0 = obs_s[e * 40 + 2 * t], x1 = obs_s[e * 40 + 2 * t + 1];
            float zi = zbuf[u * ZS + e]         + fmaf(wxi1, x1, fmaf(wxi0, x0, bi));
            float zf = zbuf[(64 + u) * ZS + e]  + fmaf(wxf1, x1, fmaf(wxf0, x0, bf));
            float zg = zbuf[(128 + u) * ZS + e] + fmaf(wxg1, x1, fmaf(wxg0, x0, bg));
            float zo = zbuf[(192 + u) * ZS + e] + fmaf(wxo1, x1, fmaf(wxo0, x0, bo));
            float cn = sigf(zf) * c[j] + sigf(zi) * tanhf_(zg);
            c[j] = cn;
            vsh[e * HS + u] = sigf(zo) * tanhf_(cn);
        }
    }
    __syncthreads();
    {
        float4* dst = (float4*)(g_hs1 + ((size_t)(OBS - 1) * B + blockBase) * HID);
        for (int i = tid; i < 64 * 16; i += TPB) {
            int ee = i >> 4, k4 = i & 15;
            dst[i] = *(const float4*)(vsh + ee * HS + k4 * 4);
        }
    }
}

// ===========================================================================
// Kernel 2: layer 1 via mma.sync — VERBATIM round 9 (validated WIN).
// ===========================================================================
static constexpr int K2_EPB = 64;
static constexpr int K2_V = 0;
static constexpr int K2_Z = K2_EPB * VS;
static constexpr int K2_B = K2_Z + 256 * ZS;
static constexpr int K2_SMEM = (K2_B + 256) * 4;

__global__ void __launch_bounds__(TPB, 1) k_layer1(
    const float* __restrict__ wih, const float* __restrict__ whh,
    const float* __restrict__ bih, const float* __restrict__ bhh, int B)
{
    extern __shared__ float sm[];
    float* vsh  = sm + K2_V;
    float* zbuf = sm + K2_Z;
    float* bs   = sm + K2_B;

    const int tid = threadIdx.x;
    const size_t blockBase = (size_t)blockIdx.x * K2_EPB;
    const int warp = tid >> 5;
    const int gid  = (tid & 31) >> 2;
    const int tig  = tid & 3;
    const int rbase = warp * 32;

    uint32_t ahi[64], alo[64];
    #pragma unroll
    for (int mt = 0; mt < 2; ++mt)
    #pragma unroll
    for (int kt = 0; kt < 8; ++kt)
    #pragma unroll
    for (int j = 0; j < 4; ++j) {
        int row = rbase + 16 * mt + gid + (j & 1) * 8;
        int col = 16 * kt + 2 * tig + (j >> 1) * 8;
        const float* src = (col < 64) ? (wih + row * 64 + col)
                                      : (whh + row * 64 + (col - 64));
        float f0 = src[0], f1 = src[1];
        uint32_t h = pk_bf2(f0, f1);
        uint32_t l = pk_bf2(f0 - bf_lo(h), f1 - bf_hi(h));
        ahi[(mt * 8 + kt) * 4 + j] = h;
        alo[(mt * 8 + kt) * 4 + j] = l;
    }

    for (int i = tid; i < 256; i += TPB) bs[i] = bih[i] + bhh[i];
    for (int i = tid; i < K2_EPB * VS; i += TPB) vsh[i] = 0.f;

    const int u  = tid & 63;
    const int eg = tid >> 6;
    float c[16];
    #pragma unroll
    for (int j = 0; j < 16; ++j) c[j] = 0.f;

    #pragma unroll 1
    for (int t = 0; t < OBS; ++t) {
        __syncthreads();
        {
            const float4* src = (const float4*)(g_hs1 + ((size_t)t * B + blockBase) * HID);
            for (int i = tid; i < K2_EPB * 16; i += TPB) {
                int ee = i >> 4, k4 = i & 15;
                *(float4*)(vsh + ee * VS + k4 * 4) = src[i];
            }
        }
        __syncthreads();

        #pragma unroll 1
        for (int nh = 0; nh < 2; ++nh) {
            float acc[32];
            #pragma unroll
            for (int i = 0; i < 32; ++i) acc[i] = 0.f;

            #pragma unroll
            for (int kt = 0; kt < 8; ++kt) {
                #pragma unroll
                for (int nt = 0; nt < 4; ++nt) {
                    const int e  = (nh * 4 + nt) * 8 + gid;
                    const int k0 = kt * 16 + 2 * tig;
                    float2 p0 = *(const float2*)(vsh + e * VS + k0);
                    float2 p1 = *(const float2*)(vsh + e * VS + k0 + 8);
                    uint32_t bh0 = pk_bf2(p0.x, p0.y);
                    uint32_t bh1 = pk_bf2(p1.x, p1.y);
                    uint32_t bl0 = pk_bf2(p0.x - bf_lo(bh0), p0.y - bf_hi(bh0));
                    uint32_t bl1 = pk_bf2(p1.x - bf_lo(bh1), p1.y - bf_hi(bh1));
                    #pragma unroll
                    for (int mt = 0; mt < 2; ++mt) {
                        float* a = acc + (mt * 4 + nt) * 4;
                        const uint32_t* Ah = ahi + (mt * 8 + kt) * 4;
                        const uint32_t* Al = alo + (mt * 8 + kt) * 4;
                        MMA_B16(a, Ah, bh0, bh1);
                        MMA_B16(a, Ah, bl0, bl1);
                        MMA_B16(a, Al, bh0, bh1);
                    }
                }
            }
            #pragma unroll
            for (int mt = 0; mt < 2; ++mt)
            #pragma unroll
            for (int nt = 0; nt < 4; ++nt) {
                const int e0 = (nh * 4 + nt) * 8 + 2 * tig;
                const int r0 = rbase + 16 * mt + gid;
                const float* a = acc + (mt * 4 + nt) * 4;
                *(float2*)(zbuf + r0 * ZS + e0)       = make_float2(a[0], a[1]);
                *(float2*)(zbuf + (r0 + 8) * ZS + e0) = make_float2(a[2], a[3]);
            }
        }
        __syncthreads();

        const bool last = (t == OBS - 1);
        #pragma unroll
        for (int j = 0; j < 16; ++j) {
            const int e = eg * 16 + j;
            float zi = zbuf[u * ZS + e]          + bs[u];
            float zf = zbuf[(64 + u) * ZS + e]   + bs[64 + u];
            float zg = zbuf[(128 + u) * ZS + e]  + bs[128 + u];
            float zo = zbuf[(192 + u) * ZS + e]  + bs[192 + u];
            float cn = sigf(zf) * c[j] + sigf(zi) * tanhf_(zg);
            c[j] = cn;
            float hn = sigf(zo) * tanhf_(cn);
            vsh[e * VS + 64 + u] = hn;
            if (last) {
                g_h1[(blockBase + e) * HID + u] = hn;
                g_c1[(blockBase + e) * HID + u] = cn;
            }
        }
    }
}

// ===========================================================================
// Kernel 3 v2: decoder via mma.sync (K=64 on h; x-term + out-proj in epilogue).
// ===========================================================================
static constexpr int D_V  = 0;                 // 64*68  = 4352
static constexpr int D_Z  = 64 * HS;           // 256*66 = 16896
static constexpr int D_OW = D_Z + 256 * ZS;    // 128
static constexpr int D_OB = D_OW + 128;        // 2
static constexpr int D_X  = D_OB + 2;          // 128
static constexpr int D_SMEM = (D_X + 128) * 4;

__global__ void __launch_bounds__(TPB, 1) k_decoder(
    const float* __restrict__ obs, const float* __restrict__ wih,
    const float* __restrict__ whh, const float* __restrict__ bih,
    const float* __restrict__ bhh, const float* __restrict__ outw,
    const float* __restrict__ outb, float* __restrict__ out, int B)
{
    extern __shared__ float sm[];
    float* vsh  = sm + D_V;
    float* zbuf = sm + D_Z;
    float* ow   = sm + D_OW;
    float* ob   = sm + D_OB;
    float* xbuf = sm + D_X;

    const int tid = threadIdx.x;
    const size_t blockBase = (size_t)blockIdx.x * 64;
    const int warp = tid >> 5;
    const int gid  = (tid & 31) >> 2;
    const int tig  = tid & 3;
    const int rbase = warp * 32;

    uint32_t ahi[32], alo[32];
    #pragma unroll
    for (int mt = 0; mt < 2; ++mt)
    #pragma unroll
    for (int kt = 0; kt < 4; ++kt)
    #pragma unroll
    for (int j = 0; j < 4; ++j) {
        int row = rbase + 16 * mt + gid + (j & 1) * 8;
        int col = 16 * kt + 2 * tig + (j >> 1) * 8;
        float f0 = whh[row * 64 + col], f1 = whh[row * 64 + col + 1];
        uint32_t h = pk_bf2(f0, f1);
        uint32_t l = pk_bf2(f0 - bf_lo(h), f1 - bf_hi(h));
        ahi[(mt * 4 + kt) * 4 + j] = h;
        alo[(mt * 4 + kt) * 4 + j] = l;
    }

    const int u  = tid & 63;
    const int eg = tid >> 6;
    const float wxi0 = wih[2*u],           wxi1 = wih[2*u+1];
    const float wxf0 = wih[2*(64+u)],      wxf1 = wih[2*(64+u)+1];
    const float wxg0 = wih[2*(128+u)],     wxg1 = wih[2*(128+u)+1];
    const float wxo0 = wih[2*(192+u)],     wxo1 = wih[2*(192+u)+1];
    const float bi = bih[u]       + bhh[u];
    const float bf = bih[64+u]    + bhh[64+u];
    const float bg = bih[128+u]   + bhh[128+u];
    const float bo = bih[192+u]   + bhh[192+u];

    for (int i = tid; i < 128; i += TPB) ow[i] = outw[i];
    if (tid < 2) ob[tid] = outb[tid];
    // h init (coalesced) + x init
    {
        const float4* src = (const float4*)(g_h1 + blockBase * HID);
        for (int i = tid; i < 64 * 16; i += TPB) {
            int ee = i >> 4, k4 = i & 15;
            *(float4*)(vsh + ee * HS + k4 * 4) = src[i];
        }
        for (int i = tid; i < 128; i += TPB) {
            int ee = i >> 1, j = i & 1;
            xbuf[i] = obs[(blockBase + ee) * 40 + 38 + j];
        }
    }
    float c[16];
    #pragma unroll
    for (int j = 0; j < 16; ++j)
        c[j] = g_c1[(blockBase + eg * 16 + j) * HID + u];
    __syncthreads();

    #pragma unroll 1
    for (int t = 0; t < PRED; ++t) {
        // GEMM: z = Whh @ h   (vsh holds h(t-1), xbuf holds x(t))
        #pragma unroll 1
        for (int nh = 0; nh < 2; ++nh) {
            float acc[32];
            #pragma unroll
            for (int i = 0; i < 32; ++i) acc[i] = 0.f;
            #pragma unroll
            for (int kt = 0; kt < 4; ++kt) {
                #pragma unroll
                for (int nt = 0; nt < 4; ++nt) {
                    const int e  = (nh * 4 + nt) * 8 + gid;
                    const int k0 = kt * 16 + 2 * tig;
                    float2 p0 = *(const float2*)(vsh + e * HS + k0);
                    float2 p1 = *(const float2*)(vsh + e * HS + k0 + 8);
                    uint32_t bh0 = pk_bf2(p0.x, p0.y);
                    uint32_t bh1 = pk_bf2(p1.x, p1.y);
                    uint32_t bl0 = pk_bf2(p0.x - bf_lo(bh0), p0.y - bf_hi(bh0));
                    uint32_t bl1 = pk_bf2(p1.x - bf_lo(bh1), p1.y - bf_hi(bh1));
                    #pragma unroll
                    for (int mt = 0; mt < 2; ++mt) {
                        float* a = acc + (mt * 4 + nt) * 4;
                        const uint32_t* Ah = ahi + (mt * 4 + kt) * 4;
                        const uint32_t* Al = alo + (mt * 4 + kt) * 4;
                        MMA_B16(a, Ah, bh0, bh1);
                        MMA_B16(a, Ah, bl0, bl1);
                        MMA_B16(a, Al, bh0, bh1);
                    }
                }
            }
            #pragma unroll
            for (int mt = 0; mt < 2; ++mt)
            #pragma unroll
            for (int nt = 0; nt < 4; ++nt) {
                const int e0 = (nh * 4 + nt) * 8 + 2 * tig;
                const int r0 = rbase + 16 * mt + gid;
                const float* a = acc + (mt * 4 + nt) * 4;
                *(float2*)(zbuf + r0 * ZS + e0)       = make_float2(a[0], a[1]);
                *(float2*)(zbuf + (r0 + 8) * ZS + e0) = make_float2(a[2], a[3]);
            }
        }
        __syncthreads();   // zbuf ready; vsh reads done

        #pragma unroll
        for (int j = 0; j < 16; ++j) {
            const int e = eg * 16 + j;
            const float x0 = xbuf[e * 2], x1 = xbuf[e * 2 + 1];
            float zi = zbuf[u * ZS + e]         + fmaf(wxi1, x1, fmaf(wxi0, x0, bi));
            float zf = zbuf[(64 + u) * ZS + e]  + fmaf(wxf1, x1, fmaf(wxf0, x0, bf));
            float zg = zbuf[(128 + u) * ZS + e] + fmaf(wxg1, x1, fmaf(wxg0, x0, bg));
            float zo = zbuf[(192 + u) * ZS + e] + fmaf(wxo1, x1, fmaf(wxo0, x0, bo));
            float cn = sigf(zf) * c[j] + sigf(zi) * tanhf_(zg);
            c[j] = cn;
            vsh[e * HS + u] = sigf(zo) * tanhf_(cn);
        }
        __syncthreads();   // h(t) ready; all xbuf/zbuf reads done

        // Out-projection + feedback (threads 0..127: e = tid>>1, od = tid&1)
        if (tid < 128) {
            const int e = tid >> 1, od = tid & 1;
            float o = ob[od];
            #pragma unroll
            for (int k4 = 0; k4 < 16; ++k4) {
                float4 hh = *(const float4*)(vsh + e * HS + k4 * 4);
                float4 w  = *(const float4*)(ow + od * 64 + k4 * 4);
                o += w.x * hh.x + w.y * hh.y + w.z * hh.z + w.w * hh.w;
            }
            out[(blockBase + e) * (PRED * 2) + t * 2 + od] = o;
            xbuf[e * 2 + od] = o;
        }
        __syncthreads();   // xbuf(t+1) ready before next epilogue; vsh reads done
    }
}

// ---------------------------------------------------------------------------
extern "C" void kernel_launch(void* const* d_in, const int* in_sizes, int n_in,
                              void* d_out, int out_size)
{
    const float* obs     = (const float*)d_in[0];
    const float* w_ih_l0 = (const float*)d_in[1];
    const float* w_hh_l0 = (const float*)d_in[2];
    const float* b_ih_l0 = (const float*)d_in[3];
    const float* b_hh_l0 = (const float*)d_in[4];
    const float* w_ih_l1 = (const float*)d_in[5];
    const float* w_hh_l1 = (const float*)d_in[6];
    const float* b_ih_l1 = (const float*)d_in[7];
    const float* b_hh_l1 = (const float*)d_in[8];
    const float* dec_w_ih = (const float*)d_in[9];
    const float* dec_w_hh = (const float*)d_in[10];
    const float* dec_b_ih = (const float*)d_in[11];
    const float* dec_b_hh = (const float*)d_in[12];
    const float* out_w   = (const float*)d_in[13];
    const float* out_b   = (const float*)d_in[14];
    float* out = (float*)d_out;

    const int B = in_sizes[0] / (OBS * 2);

    cudaFuncSetAttribute(k_layer0,  cudaFuncAttributeMaxDynamicSharedMemorySize, L0_SMEM);
    cudaFuncSetAttribute(k_layer1,  cudaFuncAttributeMaxDynamicSharedMemorySize, K2_SMEM);
    cudaFuncSetAttribute(k_decoder, cudaFuncAttributeMaxDynamicSharedMemorySize, D_SMEM);

    k_layer0<<<B / 64, TPB, L0_SMEM>>>(obs, w_ih_l0, w_hh_l0, b_ih_l0, b_hh_l0, B);
    k_layer1<<<B / 64, TPB, K2_SMEM>>>(w_ih_l1, w_hh_l1, b_ih_l1, b_hh_l1, B);
    k_decoder<<<B / 64, TPB, D_SMEM>>>(obs, dec_w_ih, dec_w_hh, dec_b_ih, dec_b_hh,
                                       out_w, out_b, out, B);
}

// round 11
// speedup vs baseline: 2.2257x; 1.0737x over previous
#include <cuda_runtime.h>
#include <cstdint>

// Problem constants
static constexpr int HID  = 64;
static constexpr int OBS  = 20;
static constexpr int PRED = 12;
static constexpr int BMAX = 32768;

static constexpr int TPB = 512;   // 16 warps: 16 M-rows per warp

// Scratch (allocation-free rule: __device__ globals)
__device__ float g_hs1[(size_t)OBS * BMAX * HID];
__device__ float g_h1[(size_t)BMAX * HID];
__device__ float g_c1[(size_t)BMAX * HID];

__device__ __forceinline__ float sigf(float x) {
    return __fdividef(1.0f, 1.0f + __expf(-x));
}
__device__ __forceinline__ float tanhf_(float x) {
    return fmaf(2.0f, sigf(2.0f * x), -1.0f);
}

// bf16x2 pack: low 16 bits = lo value, high 16 bits = hi value
__device__ __forceinline__ uint32_t pk_bf2(float lo, float hi) {
    uint32_t r;
    asm("cvt.rn.bf16x2.f32 %0, %1, %2;" : "=r"(r) : "f"(hi), "f"(lo));
    return r;
}
__device__ __forceinline__ float bf_lo(uint32_t p) { return __uint_as_float(p << 16); }
__device__ __forceinline__ float bf_hi(uint32_t p) { return __uint_as_float(p & 0xffff0000u); }

#define MMA_B16(c, a, b0, b1) \
    asm volatile("mma.sync.aligned.m16n8k16.row.col.f32.bf16.bf16.f32 " \
        "{%0,%1,%2,%3}, {%4,%5,%6,%7}, {%8,%9}, {%0,%1,%2,%3};" \
        : "+f"((c)[0]), "+f"((c)[1]), "+f"((c)[2]), "+f"((c)[3]) \
        : "r"((a)[0]), "r"((a)[1]), "r"((a)[2]), "r"((a)[3]), "r"(b0), "r"(b1))

static constexpr int VS = 132;   // layer1 vsh stride
static constexpr int ZS = 66;    // zbuf stride (all kernels)
static constexpr int HS = 68;    // h-only vsh stride (layer0/decoder)

// ===========================================================================
// Kernel 1: encoder layer 0 via mma.sync, 16-warp M-split.
// Warp w: M rows 16w..16w+15 (1 m-tile); A = Whh hi/lo persistent (4kt x 4).
// ===========================================================================
static constexpr int L0_V   = 0;                       // 64*68
static constexpr int L0_Z   = 64 * HS;                 // 256*66
static constexpr int L0_OBS = L0_Z + 256 * ZS;         // 64*40
static constexpr int L0_SMEM = (L0_OBS + 64 * 40) * 4;

__global__ void __launch_bounds__(TPB, 1) k_layer0(
    const float* __restrict__ obs, const float* __restrict__ wih,
    const float* __restrict__ whh, const float* __restrict__ bih,
    const float* __restrict__ bhh, int B)
{
    extern __shared__ float sm[];
    float* vsh   = sm + L0_V;
    float* zbuf  = sm + L0_Z;
    float* obs_s = sm + L0_OBS;

    const int tid = threadIdx.x;
    const size_t blockBase = (size_t)blockIdx.x * 64;
    const int warp = tid >> 5;
    const int gid  = (tid & 31) >> 2;
    const int tig  = tid & 3;
    const int rbase = warp * 16;

    // Persistent A fragments from Whh (K=64 -> 4 k-tiles, 1 m-tile)
    uint32_t ahi[16], alo[16];
    #pragma unroll
    for (int kt = 0; kt < 4; ++kt)
    #pragma unroll
    for (int j = 0; j < 4; ++j) {
        int row = rbase + gid + (j & 1) * 8;
        int col = 16 * kt + 2 * tig + (j >> 1) * 8;
        float f0 = whh[row * 64 + col], f1 = whh[row * 64 + col + 1];
        uint32_t h = pk_bf2(f0, f1);
        uint32_t l = pk_bf2(f0 - bf_lo(h), f1 - bf_hi(h));
        ahi[kt * 4 + j] = h;
        alo[kt * 4 + j] = l;
    }

    // Epilogue constants (unit u): x-weights + combined bias, in registers
    const int u  = tid & 63;
    const int eg = tid >> 6;        // 0..7
    const float wxi0 = wih[2*u],           wxi1 = wih[2*u+1];
    const float wxf0 = wih[2*(64+u)],      wxf1 = wih[2*(64+u)+1];
    const float wxg0 = wih[2*(128+u)],     wxg1 = wih[2*(128+u)+1];
    const float wxo0 = wih[2*(192+u)],     wxo1 = wih[2*(192+u)+1];
    const float bi = bih[u]       + bhh[u];
    const float bf = bih[64+u]    + bhh[64+u];
    const float bg = bih[128+u]   + bhh[128+u];
    const float bo = bih[192+u]   + bhh[192+u];

    for (int i = tid; i < 64 * HS; i += TPB) vsh[i] = 0.f;   // h0 = 0
    for (int i = tid; i < 64 * 40; i += TPB) {
        int ee = i / 40, j = i % 40;
        obs_s[i] = obs[(blockBase + ee) * 40 + j];
    }

    float c[8];
    #pragma unroll
    for (int j = 0; j < 8; ++j) c[j] = 0.f;

    #pragma unroll 1
    for (int t = 0; t < OBS; ++t) {
        __syncthreads();   // h(t-1) in vsh visible; zbuf free
        if (t > 0) {       // coalesced store of h(t-1)
            float4* dst = (float4*)(g_hs1 + ((size_t)(t - 1) * B + blockBase) * HID);
            for (int i = tid; i < 64 * 16; i += TPB) {
                int ee = i >> 4, k4 = i & 15;
                dst[i] = *(const float4*)(vsh + ee * HS + k4 * 4);
            }
        }

        // GEMM: z[256,64] = Whh @ h
        #pragma unroll 1
        for (int nh = 0; nh < 2; ++nh) {
            float acc[16];
            #pragma unroll
            for (int i = 0; i < 16; ++i) acc[i] = 0.f;
            #pragma unroll
            for (int kt = 0; kt < 4; ++kt) {
                #pragma unroll
                for (int nt = 0; nt < 4; ++nt) {
                    const int e  = (nh * 4 + nt) * 8 + gid;
                    const int k0 = kt * 16 + 2 * tig;
                    float2 p0 = *(const float2*)(vsh + e * HS + k0);
                    float2 p1 = *(const float2*)(vsh + e * HS + k0 + 8);
                    uint32_t bh0 = pk_bf2(p0.x, p0.y);
                    uint32_t bh1 = pk_bf2(p1.x, p1.y);
                    uint32_t bl0 = pk_bf2(p0.x - bf_lo(bh0), p0.y - bf_hi(bh0));
                    uint32_t bl1 = pk_bf2(p1.x - bf_lo(bh1), p1.y - bf_hi(bh1));
                    float* a = acc + nt * 4;
                    const uint32_t* Ah = ahi + kt * 4;
                    const uint32_t* Al = alo + kt * 4;
                    MMA_B16(a, Ah, bh0, bh1);
                    MMA_B16(a, Ah, bl0, bl1);
                    MMA_B16(a, Al, bh0, bh1);
                }
            }
            #pragma unroll
            for (int nt = 0; nt < 4; ++nt) {
                const int e0 = (nh * 4 + nt) * 8 + 2 * tig;
                const int r0 = rbase + gid;
                const float* a = acc + nt * 4;
                *(float2*)(zbuf + r0 * ZS + e0)       = make_float2(a[0], a[1]);
                *(float2*)(zbuf + (r0 + 8) * ZS + e0) = make_float2(a[2], a[3]);
            }
        }
        __syncthreads();   // zbuf ready; vsh reads (GEMM + store) done

        #pragma unroll
        for (int j = 0; j < 8; ++j) {
            const int e = eg * 8 + j;
            const float x0 = obs_s[e * 40 + 2 * t], x1 = obs_s[e * 40 + 2 * t + 1];
            float zi = zbuf[u * ZS + e]         + fmaf(wxi1, x1, fmaf(wxi0, x0, bi));
            float zf = zbuf[(64 + u) * ZS + e]  + fmaf(wxf1, x1, fmaf(wxf0, x0, bf));
            float zg = zbuf[(128 + u) * ZS + e] + fmaf(wxg1, x1, fmaf(wxg0, x0, bg));
            float zo = zbuf[(192 + u) * ZS + e] + fmaf(wxo1, x1, fmaf(wxo0, x0, bo));
            float cn = sigf(zf) * c[j] + sigf(zi) * tanhf_(zg);
            c[j] = cn;
            vsh[e * HS + u] = sigf(zo) * tanhf_(cn);
        }
    }
    __syncthreads();
    {
        float4* dst = (float4*)(g_hs1 + ((size_t)(OBS - 1) * B + blockBase) * HID);
        for (int i = tid; i < 64 * 16; i += TPB) {
            int ee = i >> 4, k4 = i & 15;
            dst[i] = *(const float4*)(vsh + ee * HS + k4 * 4);
        }
    }
}

// ===========================================================================
// Kernel 2: layer 1 via mma.sync, 16-warp M-split (K=128 -> 8 k-tiles).
// ===========================================================================
static constexpr int K2_EPB = 64;
static constexpr int K2_V = 0;
static constexpr int K2_Z = K2_EPB * VS;
static constexpr int K2_B = K2_Z + 256 * ZS;
static constexpr int K2_SMEM = (K2_B + 256) * 4;

__global__ void __launch_bounds__(TPB, 1) k_layer1(
    const float* __restrict__ wih, const float* __restrict__ whh,
    const float* __restrict__ bih, const float* __restrict__ bhh, int B)
{
    extern __shared__ float sm[];
    float* vsh  = sm + K2_V;
    float* zbuf = sm + K2_Z;
    float* bs   = sm + K2_B;

    const int tid = threadIdx.x;
    const size_t blockBase = (size_t)blockIdx.x * K2_EPB;
    const int warp = tid >> 5;
    const int gid  = (tid & 31) >> 2;
    const int tig  = tid & 3;
    const int rbase = warp * 16;

    uint32_t ahi[32], alo[32];
    #pragma unroll
    for (int kt = 0; kt < 8; ++kt)
    #pragma unroll
    for (int j = 0; j < 4; ++j) {
        int row = rbase + gid + (j & 1) * 8;
        int col = 16 * kt + 2 * tig + (j >> 1) * 8;
        const float* src = (col < 64) ? (wih + row * 64 + col)
                                      : (whh + row * 64 + (col - 64));
        float f0 = src[0], f1 = src[1];
        uint32_t h = pk_bf2(f0, f1);
        uint32_t l = pk_bf2(f0 - bf_lo(h), f1 - bf_hi(h));
        ahi[kt * 4 + j] = h;
        alo[kt * 4 + j] = l;
    }

    for (int i = tid; i < 256; i += TPB) bs[i] = bih[i] + bhh[i];
    for (int i = tid; i < K2_EPB * VS; i += TPB) vsh[i] = 0.f;

    const int u  = tid & 63;
    const int eg = tid >> 6;
    float c[8];
    #pragma unroll
    for (int j = 0; j < 8; ++j) c[j] = 0.f;

    #pragma unroll 1
    for (int t = 0; t < OBS; ++t) {
        __syncthreads();
        {
            const float4* src = (const float4*)(g_hs1 + ((size_t)t * B + blockBase) * HID);
            for (int i = tid; i < K2_EPB * 16; i += TPB) {
                int ee = i >> 4, k4 = i & 15;
                *(float4*)(vsh + ee * VS + k4 * 4) = src[i];
            }
        }
        __syncthreads();

        #pragma unroll 1
        for (int nh = 0; nh < 2; ++nh) {
            float acc[16];
            #pragma unroll
            for (int i = 0; i < 16; ++i) acc[i] = 0.f;

            #pragma unroll
            for (int kt = 0; kt < 8; ++kt) {
                #pragma unroll
                for (int nt = 0; nt < 4; ++nt) {
                    const int e  = (nh * 4 + nt) * 8 + gid;
                    const int k0 = kt * 16 + 2 * tig;
                    float2 p0 = *(const float2*)(vsh + e * VS + k0);
                    float2 p1 = *(const float2*)(vsh + e * VS + k0 + 8);
                    uint32_t bh0 = pk_bf2(p0.x, p0.y);
                    uint32_t bh1 = pk_bf2(p1.x, p1.y);
                    uint32_t bl0 = pk_bf2(p0.x - bf_lo(bh0), p0.y - bf_hi(bh0));
                    uint32_t bl1 = pk_bf2(p1.x - bf_lo(bh1), p1.y - bf_hi(bh1));
                    float* a = acc + nt * 4;
                    const uint32_t* Ah = ahi + kt * 4;
                    const uint32_t* Al = alo + kt * 4;
                    MMA_B16(a, Ah, bh0, bh1);
                    MMA_B16(a, Ah, bl0, bl1);
                    MMA_B16(a, Al, bh0, bh1);
                }
            }
            #pragma unroll
            for (int nt = 0; nt < 4; ++nt) {
                const int e0 = (nh * 4 + nt) * 8 + 2 * tig;
                const int r0 = rbase + gid;
                const float* a = acc + nt * 4;
                *(float2*)(zbuf + r0 * ZS + e0)       = make_float2(a[0], a[1]);
                *(float2*)(zbuf + (r0 + 8) * ZS + e0) = make_float2(a[2], a[3]);
            }
        }
        __syncthreads();

        const bool last = (t == OBS - 1);
        #pragma unroll
        for (int j = 0; j < 8; ++j) {
            const int e = eg * 8 + j;
            float zi = zbuf[u * ZS + e]          + bs[u];
            float zf = zbuf[(64 + u) * ZS + e]   + bs[64 + u];
            float zg = zbuf[(128 + u) * ZS + e]  + bs[128 + u];
            float zo = zbuf[(192 + u) * ZS + e]  + bs[192 + u];
            float cn = sigf(zf) * c[j] + sigf(zi) * tanhf_(zg);
            c[j] = cn;
            float hn = sigf(zo) * tanhf_(cn);
            vsh[e * VS + 64 + u] = hn;
            if (last) {
                g_h1[(blockBase + e) * HID + u] = hn;
                g_c1[(blockBase + e) * HID + u] = cn;
            }
        }
    }
}

// ===========================================================================
// Kernel 3: decoder via mma.sync, 16-warp M-split (K=64).
// ===========================================================================
static constexpr int D_V  = 0;
static constexpr int D_Z  = 64 * HS;
static constexpr int D_OW = D_Z + 256 * ZS;
static constexpr int D_OB = D_OW + 128;
static constexpr int D_X  = D_OB + 2;
static constexpr int D_SMEM = (D_X + 128) * 4;

__global__ void __launch_bounds__(TPB, 1) k_decoder(
    const float* __restrict__ obs, const float* __restrict__ wih,
    const float* __restrict__ whh, const float* __restrict__ bih,
    const float* __restrict__ bhh, const float* __restrict__ outw,
    const float* __restrict__ outb, float* __restrict__ out, int B)
{
    extern __shared__ float sm[];
    float* vsh  = sm + D_V;
    float* zbuf = sm + D_Z;
    float* ow   = sm + D_OW;
    float* ob   = sm + D_OB;
    float* xbuf = sm + D_X;

    const int tid = threadIdx.x;
    const size_t blockBase = (size_t)blockIdx.x * 64;
    const int warp = tid >> 5;
    const int gid  = (tid & 31) >> 2;
    const int tig  = tid & 3;
    const int rbase = warp * 16;

    uint32_t ahi[16], alo[16];
    #pragma unroll
    for (int kt = 0; kt < 4; ++kt)
    #pragma unroll
    for (int j = 0; j < 4; ++j) {
        int row = rbase + gid + (j & 1) * 8;
        int col = 16 * kt + 2 * tig + (j >> 1) * 8;
        float f0 = whh[row * 64 + col], f1 = whh[row * 64 + col + 1];
        uint32_t h = pk_bf2(f0, f1);
        uint32_t l = pk_bf2(f0 - bf_lo(h), f1 - bf_hi(h));
        ahi[kt * 4 + j] = h;
        alo[kt * 4 + j] = l;
    }

    const int u  = tid & 63;
    const int eg = tid >> 6;
    const float wxi0 = wih[2*u],           wxi1 = wih[2*u+1];
    const float wxf0 = wih[2*(64+u)],      wxf1 = wih[2*(64+u)+1];
    const float wxg0 = wih[2*(128+u)],     wxg1 = wih[2*(128+u)+1];
    const float wxo0 = wih[2*(192+u)],     wxo1 = wih[2*(192+u)+1];
    const float bi = bih[u]       + bhh[u];
    const float bf = bih[64+u]    + bhh[64+u];
    const float bg = bih[128+u]   + bhh[128+u];
    const float bo = bih[192+u]   + bhh[192+u];

    for (int i = tid; i < 128; i += TPB) ow[i] = outw[i];
    if (tid < 2) ob[tid] = outb[tid];
    {
        const float4* src = (const float4*)(g_h1 + blockBase * HID);
        for (int i = tid; i < 64 * 16; i += TPB) {
            int ee = i >> 4, k4 = i & 15;
            *(float4*)(vsh + ee * HS + k4 * 4) = src[i];
        }
        for (int i = tid; i < 128; i += TPB) {
            int ee = i >> 1, j = i & 1;
            xbuf[i] = obs[(blockBase + ee) * 40 + 38 + j];
        }
    }
    float c[8];
    #pragma unroll
    for (int j = 0; j < 8; ++j)
        c[j] = g_c1[(blockBase + eg * 8 + j) * HID + u];
    __syncthreads();

    #pragma unroll 1
    for (int t = 0; t < PRED; ++t) {
        #pragma unroll 1
        for (int nh = 0; nh < 2; ++nh) {
            float acc[16];
            #pragma unroll
            for (int i = 0; i < 16; ++i) acc[i] = 0.f;
            #pragma unroll
            for (int kt = 0; kt < 4; ++kt) {
                #pragma unroll
                for (int nt = 0; nt < 4; ++nt) {
                    const int e  = (nh * 4 + nt) * 8 + gid;
                    const int k0 = kt * 16 + 2 * tig;
                    float2 p0 = *(const float2*)(vsh + e * HS + k0);
                    float2 p1 = *(const float2*)(vsh + e * HS + k0 + 8);
                    uint32_t bh0 = pk_bf2(p0.x, p0.y);
                    uint32_t bh1 = pk_bf2(p1.x, p1.y);
                    uint32_t bl0 = pk_bf2(p0.x - bf_lo(bh0), p0.y - bf_hi(bh0));
                    uint32_t bl1 = pk_bf2(p1.x - bf_lo(bh1), p1.y - bf_hi(bh1));
                    float* a = acc + nt * 4;
                    const uint32_t* Ah = ahi + kt * 4;
                    const uint32_t* Al = alo + kt * 4;
                    MMA_B16(a, Ah, bh0, bh1);
                    MMA_B16(a, Ah, bl0, bl1);
                    MMA_B16(a, Al, bh0, bh1);
                }
            }
            #pragma unroll
            for (int nt = 0; nt < 4; ++nt) {
                const int e0 = (nh * 4 + nt) * 8 + 2 * tig;
                const int r0 = rbase + gid;
                const float* a = acc + nt * 4;
                *(float2*)(zbuf + r0 * ZS + e0)       = make_float2(a[0], a[1]);
                *(float2*)(zbuf + (r0 + 8) * ZS + e0) = make_float2(a[2], a[3]);
            }
        }
        __syncthreads();   // zbuf ready; vsh reads done

        #pragma unroll
        for (int j = 0; j < 8; ++j) {
            const int e = eg * 8 + j;
            const float x0 = xbuf[e * 2], x1 = xbuf[e * 2 + 1];
            float zi = zbuf[u * ZS + e]         + fmaf(wxi1, x1, fmaf(wxi0, x0, bi));
            float zf = zbuf[(64 + u) * ZS + e]  + fmaf(wxf1, x1, fmaf(wxf0, x0, bf));
            float zg = zbuf[(128 + u) * ZS + e] + fmaf(wxg1, x1, fmaf(wxg0, x0, bg));
            float zo = zbuf[(192 + u) * ZS + e] + fmaf(wxo1, x1, fmaf(wxo0, x0, bo));
            float cn = sigf(zf) * c[j] + sigf(zi) * tanhf_(zg);
            c[j] = cn;
            vsh[e * HS + u] = sigf(zo) * tanhf_(cn);
        }
        __syncthreads();   // h(t) ready; xbuf/zbuf reads done

        // Out-projection + feedback (threads 0..127: e = tid>>1, od = tid&1)
        if (tid < 128) {
            const int e = tid >> 1, od = tid & 1;
            float o = ob[od];
            #pragma unroll
            for (int k4 = 0; k4 < 16; ++k4) {
                float4 hh = *(const float4*)(vsh + e * HS + k4 * 4);
                float4 w  = *(const float4*)(ow + od * 64 + k4 * 4);
                o += w.x * hh.x + w.y * hh.y + w.z * hh.z + w.w * hh.w;
            }
            out[(blockBase + e) * (PRED * 2) + t * 2 + od] = o;
            xbuf[e * 2 + od] = o;
        }
        __syncthreads();   // xbuf(t+1) ready before next epilogue
    }
}

// ---------------------------------------------------------------------------
extern "C" void kernel_launch(void* const* d_in, const int* in_sizes, int n_in,
                              void* d_out, int out_size)
{
    const float* obs     = (const float*)d_in[0];
    const float* w_ih_l0 = (const float*)d_in[1];
    const float* w_hh_l0 = (const float*)d_in[2];
    const float* b_ih_l0 = (const float*)d_in[3];
    const float* b_hh_l0 = (const float*)d_in[4];
    const float* w_ih_l1 = (const float*)d_in[5];
    const float* w_hh_l1 = (const float*)d_in[6];
    const float* b_ih_l1 = (const float*)d_in[7];
    const float* b_hh_l1 = (const float*)d_in[8];
    const float* dec_w_ih = (const float*)d_in[9];
    const float* dec_w_hh = (const float*)d_in[10];
    const float* dec_b_ih = (const float*)d_in[11];
    const float* dec_b_hh = (const float*)d_in[12];
    const float* out_w   = (const float*)d_in[13];
    const float* out_b   = (const float*)d_in[14];
    float* out = (float*)d_out;

    const int B = in_sizes[0] / (OBS * 2);

    cudaFuncSetAttribute(k_layer0,  cudaFuncAttributeMaxDynamicSharedMemorySize, L0_SMEM);
    cudaFuncSetAttribute(k_layer1,  cudaFuncAttributeMaxDynamicSharedMemorySize, K2_SMEM);
    cudaFuncSetAttribute(k_decoder, cudaFuncAttributeMaxDynamicSharedMemorySize, D_SMEM);

    k_layer0<<<B / 64, TPB, L0_SMEM>>>(obs, w_ih_l0, w_hh_l0, b_ih_l0, b_hh_l0, B);
    k_layer1<<<B / 64, TPB, K2_SMEM>>>(w_ih_l1, w_hh_l1, b_ih_l1, b_hh_l1, B);
    k_decoder<<<B / 64, TPB, D_SMEM>>>(obs, dec_w_ih, dec_w_hh, dec_b_ih, dec_b_hh,
                                       out_w, out_b, out, B);
}

// round 12
// speedup vs baseline: 2.4065x; 1.0812x over previous
#include <cuda_runtime.h>
#include <cstdint>

// Problem constants
static constexpr int HID  = 64;
static constexpr int OBS  = 20;
static constexpr int PRED = 12;
static constexpr int BMAX = 32768;

static constexpr int TPB = 512;   // 16 warps: 16 M-rows per warp

// Scratch (allocation-free rule: __device__ globals)
__device__ float g_hs1[(size_t)OBS * BMAX * HID];
__device__ float g_h1[(size_t)BMAX * HID];
__device__ float g_c1[(size_t)BMAX * HID];

__device__ __forceinline__ float sigf(float x) {
    return __fdividef(1.0f, 1.0f + __expf(-x));
}
__device__ __forceinline__ float tanhf_(float x) {
    return fmaf(2.0f, sigf(2.0f * x), -1.0f);
}

// bf16x2 pack: low 16 bits = lo value, high 16 bits = hi value
__device__ __forceinline__ uint32_t pk_bf2(float lo, float hi) {
    uint32_t r;
    asm("cvt.rn.bf16x2.f32 %0, %1, %2;" : "=r"(r) : "f"(hi), "f"(lo));
    return r;
}
__device__ __forceinline__ float bf_lo(uint32_t p) { return __uint_as_float(p << 16); }
__device__ __forceinline__ float bf_hi(uint32_t p) { return __uint_as_float(p & 0xffff0000u); }

#define MMA_B16(c, a, b0, b1) \
    asm volatile("mma.sync.aligned.m16n8k16.row.col.f32.bf16.bf16.f32 " \
        "{%0,%1,%2,%3}, {%4,%5,%6,%7}, {%8,%9}, {%0,%1,%2,%3};" \
        : "+f"((c)[0]), "+f"((c)[1]), "+f"((c)[2]), "+f"((c)[3]) \
        : "r"((a)[0]), "r"((a)[1]), "r"((a)[2]), "r"((a)[3]), "r"(b0), "r"(b1))

static constexpr int ZS = 66;    // zbuf stride (floats)
static constexpr int HS = 68;    // fp32 h staging stride (floats)
// bf16x2 activation strides (u32 per batch elem): (stride*gid+tig) mod 32 must
// be a permutation over the warp -> stride ≡ 4 (mod 32).
static constexpr int BS0 = 36;   // layer0/decoder: 32 k-pairs
static constexpr int BS1 = 68;   // layer1: 64 k-pairs

// ===========================================================================
// Kernel 1: encoder layer 0. 16-warp M-split + single-conversion bf16 B.
// ===========================================================================
static constexpr int L0_V   = 0;                         // 64*68 fp32 h staging
static constexpr int L0_BH  = 64 * HS;                   // 64*36 u32 (hi)
static constexpr int L0_BL  = L0_BH + 64 * BS0;          // 64*36 u32 (lo)
static constexpr int L0_Z   = L0_BL + 64 * BS0;          // 256*66 fp32
static constexpr int L0_OBS = L0_Z + 256 * ZS;           // 64*40 fp32
static constexpr int L0_SMEM = (L0_OBS + 64 * 40) * 4;

__global__ void __launch_bounds__(TPB, 1) k_layer0(
    const float* __restrict__ obs, const float* __restrict__ wih,
    const float* __restrict__ whh, const float* __restrict__ bih,
    const float* __restrict__ bhh, int B)
{
    extern __shared__ float sm[];
    float*    vsh   = sm + L0_V;
    uint32_t* vbh   = (uint32_t*)(sm + L0_BH);
    uint32_t* vbl   = (uint32_t*)(sm + L0_BL);
    float*    zbuf  = sm + L0_Z;
    float*    obs_s = sm + L0_OBS;

    const int tid = threadIdx.x;
    const size_t blockBase = (size_t)blockIdx.x * 64;
    const int warp = tid >> 5;
    const int gid  = (tid & 31) >> 2;
    const int tig  = tid & 3;
    const int rbase = warp * 16;

    // Persistent A fragments from Whh (K=64 -> 4 k-tiles, 1 m-tile)
    uint32_t ahi[16], alo[16];
    #pragma unroll
    for (int kt = 0; kt < 4; ++kt)
    #pragma unroll
    for (int j = 0; j < 4; ++j) {
        int row = rbase + gid + (j & 1) * 8;
        int col = 16 * kt + 2 * tig + (j >> 1) * 8;
        float f0 = whh[row * 64 + col], f1 = whh[row * 64 + col + 1];
        uint32_t h = pk_bf2(f0, f1);
        uint32_t l = pk_bf2(f0 - bf_lo(h), f1 - bf_hi(h));
        ahi[kt * 4 + j] = h;
        alo[kt * 4 + j] = l;
    }

    // Epilogue constants (unit u)
    const int u  = tid & 63;
    const int eg = tid >> 6;        // 0..7
    const float wxi0 = wih[2*u],           wxi1 = wih[2*u+1];
    const float wxf0 = wih[2*(64+u)],      wxf1 = wih[2*(64+u)+1];
    const float wxg0 = wih[2*(128+u)],     wxg1 = wih[2*(128+u)+1];
    const float wxo0 = wih[2*(192+u)],     wxo1 = wih[2*(192+u)+1];
    const float bi = bih[u]       + bhh[u];
    const float bf = bih[64+u]    + bhh[64+u];
    const float bg = bih[128+u]   + bhh[128+u];
    const float bo = bih[192+u]   + bhh[192+u];

    for (int i = tid; i < 64 * HS; i += TPB) vsh[i] = 0.f;   // h0 = 0
    for (int i = tid; i < 64 * 40; i += TPB) {
        int ee = i / 40, j = i % 40;
        obs_s[i] = obs[(blockBase + ee) * 40 + j];
    }

    float c[8];
    #pragma unroll
    for (int j = 0; j < 8; ++j) c[j] = 0.f;

    #pragma unroll 1
    for (int t = 0; t < OBS; ++t) {
        __syncthreads();   // epilogue h(t-1) in vsh visible; vbf/zbuf free
        if (t > 0) {       // coalesced store of h(t-1)
            float4* dst = (float4*)(g_hs1 + ((size_t)(t - 1) * B + blockBase) * HID);
            for (int i = tid; i < 64 * 16; i += TPB) {
                int ee = i >> 4, k4 = i & 15;
                dst[i] = *(const float4*)(vsh + ee * HS + k4 * 4);
            }
        }
        // Convert h(t-1) fp32 -> bf16 hi/lo (ONCE per step)
        for (int i = tid; i < 64 * 32; i += TPB) {
            int e = i >> 5, kp = i & 31;
            float2 p = *(const float2*)(vsh + e * HS + 2 * kp);
            uint32_t h = pk_bf2(p.x, p.y);
            vbh[e * BS0 + kp] = h;
            vbl[e * BS0 + kp] = pk_bf2(p.x - bf_lo(h), p.y - bf_hi(h));
        }
        __syncthreads();   // vbf ready

        // GEMM: z[256,64] = Whh @ h   (pure LDS.32 + MMA)
        #pragma unroll 1
        for (int nh = 0; nh < 2; ++nh) {
            float acc[16];
            #pragma unroll
            for (int i = 0; i < 16; ++i) acc[i] = 0.f;
            #pragma unroll
            for (int kt = 0; kt < 4; ++kt) {
                #pragma unroll
                for (int nt = 0; nt < 4; ++nt) {
                    const int e = (nh * 4 + nt) * 8 + gid;
                    const int base = e * BS0 + 8 * kt + tig;
                    uint32_t bh0 = vbh[base], bh1 = vbh[base + 4];
                    uint32_t bl0 = vbl[base], bl1 = vbl[base + 4];
                    float* a = acc + nt * 4;
                    const uint32_t* Ah = ahi + kt * 4;
                    const uint32_t* Al = alo + kt * 4;
                    MMA_B16(a, Ah, bh0, bh1);
                    MMA_B16(a, Ah, bl0, bl1);
                    MMA_B16(a, Al, bh0, bh1);
                }
            }
            #pragma unroll
            for (int nt = 0; nt < 4; ++nt) {
                const int e0 = (nh * 4 + nt) * 8 + 2 * tig;
                const int r0 = rbase + gid;
                const float* a = acc + nt * 4;
                *(float2*)(zbuf + r0 * ZS + e0)       = make_float2(a[0], a[1]);
                *(float2*)(zbuf + (r0 + 8) * ZS + e0) = make_float2(a[2], a[3]);
            }
        }
        __syncthreads();   // zbuf ready; vsh/vbf reads done

        #pragma unroll
        for (int j = 0; j < 8; ++j) {
            const int e = eg * 8 + j;
            const float x0 = obs_s[e * 40 + 2 * t], x1 = obs_s[e * 40 + 2 * t + 1];
            float zi = zbuf[u * ZS + e]         + fmaf(wxi1, x1, fmaf(wxi0, x0, bi));
            float zf = zbuf[(64 + u) * ZS + e]  + fmaf(wxf1, x1, fmaf(wxf0, x0, bf));
            float zg = zbuf[(128 + u) * ZS + e] + fmaf(wxg1, x1, fmaf(wxg0, x0, bg));
            float zo = zbuf[(192 + u) * ZS + e] + fmaf(wxo1, x1, fmaf(wxo0, x0, bo));
            float cn = sigf(zf) * c[j] + sigf(zi) * tanhf_(zg);
            c[j] = cn;
            vsh[e * HS + u] = sigf(zo) * tanhf_(cn);
        }
    }
    __syncthreads();
    {
        float4* dst = (float4*)(g_hs1 + ((size_t)(OBS - 1) * B + blockBase) * HID);
        for (int i = tid; i < 64 * 16; i += TPB) {
            int ee = i >> 4, k4 = i & 15;
            dst[i] = *(const float4*)(vsh + ee * HS + k4 * 4);
        }
    }
}

// ===========================================================================
// Kernel 2: layer 1. 16-warp M-split + single-conversion bf16 B (K=128).
// vbf k-pairs: 0..31 = x (converted straight from g_hs1), 32..63 = h.
// ===========================================================================
static constexpr int K2_HST = 0;                          // 64*68 fp32 h staging
static constexpr int K2_BH  = 64 * HS;                    // 64*68 u32 hi
static constexpr int K2_BL  = K2_BH + 64 * BS1;           // 64*68 u32 lo
static constexpr int K2_Z   = K2_BL + 64 * BS1;           // 256*66
static constexpr int K2_B   = K2_Z + 256 * ZS;            // 256
static constexpr int K2_SMEM = (K2_B + 256) * 4;

__global__ void __launch_bounds__(TPB, 1) k_layer1(
    const float* __restrict__ wih, const float* __restrict__ whh,
    const float* __restrict__ bih, const float* __restrict__ bhh, int B)
{
    extern __shared__ float sm[];
    float*    hst  = sm + K2_HST;
    uint32_t* vbh  = (uint32_t*)(sm + K2_BH);
    uint32_t* vbl  = (uint32_t*)(sm + K2_BL);
    float*    zbuf = sm + K2_Z;
    float*    bs   = sm + K2_B;

    const int tid = threadIdx.x;
    const size_t blockBase = (size_t)blockIdx.x * 64;
    const int warp = tid >> 5;
    const int gid  = (tid & 31) >> 2;
    const int tig  = tid & 3;
    const int rbase = warp * 16;

    uint32_t ahi[32], alo[32];
    #pragma unroll
    for (int kt = 0; kt < 8; ++kt)
    #pragma unroll
    for (int j = 0; j < 4; ++j) {
        int row = rbase + gid + (j & 1) * 8;
        int col = 16 * kt + 2 * tig + (j >> 1) * 8;
        const float* src = (col < 64) ? (wih + row * 64 + col)
                                      : (whh + row * 64 + (col - 64));
        float f0 = src[0], f1 = src[1];
        uint32_t h = pk_bf2(f0, f1);
        uint32_t l = pk_bf2(f0 - bf_lo(h), f1 - bf_hi(h));
        ahi[kt * 4 + j] = h;
        alo[kt * 4 + j] = l;
    }

    for (int i = tid; i < 256; i += TPB) bs[i] = bih[i] + bhh[i];
    for (int i = tid; i < 64 * HS; i += TPB) hst[i] = 0.f;   // h0 = 0

    const int u  = tid & 63;
    const int eg = tid >> 6;
    float c[8];
    #pragma unroll
    for (int j = 0; j < 8; ++j) c[j] = 0.f;

    #pragma unroll 1
    for (int t = 0; t < OBS; ++t) {
        __syncthreads();   // epilogue h writes in hst visible; vbf/zbuf free
        // x: load fp32 from g_hs1, convert straight to bf16 hi/lo (k-pairs 0..31)
        {
            const float4* src = (const float4*)(g_hs1 + ((size_t)t * B + blockBase) * HID);
            for (int i = tid; i < 64 * 16; i += TPB) {
                int ee = i >> 4, k4 = i & 15;
                float4 v = src[i];
                uint32_t h0 = pk_bf2(v.x, v.y), h1 = pk_bf2(v.z, v.w);
                vbh[ee * BS1 + 2 * k4]     = h0;
                vbh[ee * BS1 + 2 * k4 + 1] = h1;
                vbl[ee * BS1 + 2 * k4]     = pk_bf2(v.x - bf_lo(h0), v.y - bf_hi(h0));
                vbl[ee * BS1 + 2 * k4 + 1] = pk_bf2(v.z - bf_lo(h1), v.w - bf_hi(h1));
            }
        }
        // h: convert staging fp32 -> bf16 hi/lo (k-pairs 32..63)
        for (int i = tid; i < 64 * 32; i += TPB) {
            int e = i >> 5, kp = i & 31;
            float2 p = *(const float2*)(hst + e * HS + 2 * kp);
            uint32_t h = pk_bf2(p.x, p.y);
            vbh[e * BS1 + 32 + kp] = h;
            vbl[e * BS1 + 32 + kp] = pk_bf2(p.x - bf_lo(h), p.y - bf_hi(h));
        }
        __syncthreads();   // vbf ready

        #pragma unroll 1
        for (int nh = 0; nh < 2; ++nh) {
            float acc[16];
            #pragma unroll
            for (int i = 0; i < 16; ++i) acc[i] = 0.f;

            #pragma unroll
            for (int kt = 0; kt < 8; ++kt) {
                #pragma unroll
                for (int nt = 0; nt < 4; ++nt) {
                    const int e = (nh * 4 + nt) * 8 + gid;
                    const int base = e * BS1 + 8 * kt + tig;
                    uint32_t bh0 = vbh[base], bh1 = vbh[base + 4];
                    uint32_t bl0 = vbl[base], bl1 = vbl[base + 4];
                    float* a = acc + nt * 4;
                    const uint32_t* Ah = ahi + kt * 4;
                    const uint32_t* Al = alo + kt * 4;
                    MMA_B16(a, Ah, bh0, bh1);
                    MMA_B16(a, Ah, bl0, bl1);
                    MMA_B16(a, Al, bh0, bh1);
                }
            }
            #pragma unroll
            for (int nt = 0; nt < 4; ++nt) {
                const int e0 = (nh * 4 + nt) * 8 + 2 * tig;
                const int r0 = rbase + gid;
                const float* a = acc + nt * 4;
                *(float2*)(zbuf + r0 * ZS + e0)       = make_float2(a[0], a[1]);
                *(float2*)(zbuf + (r0 + 8) * ZS + e0) = make_float2(a[2], a[3]);
            }
        }
        __syncthreads();   // zbuf ready; hst/vbf reads done

        const bool last = (t == OBS - 1);
        #pragma unroll
        for (int j = 0; j < 8; ++j) {
            const int e = eg * 8 + j;
            float zi = zbuf[u * ZS + e]          + bs[u];
            float zf = zbuf[(64 + u) * ZS + e]   + bs[64 + u];
            float zg = zbuf[(128 + u) * ZS + e]  + bs[128 + u];
            float zo = zbuf[(192 + u) * ZS + e]  + bs[192 + u];
            float cn = sigf(zf) * c[j] + sigf(zi) * tanhf_(zg);
            c[j] = cn;
            float hn = sigf(zo) * tanhf_(cn);
            hst[e * HS + u] = hn;
            if (last) {
                g_h1[(blockBase + e) * HID + u] = hn;
                g_c1[(blockBase + e) * HID + u] = cn;
            }
        }
    }
}

// ===========================================================================
// Kernel 3: decoder — VERBATIM round 11 (validated).
// ===========================================================================
static constexpr int D_V  = 0;
static constexpr int D_Z  = 64 * HS;
static constexpr int D_OW = D_Z + 256 * ZS;
static constexpr int D_OB = D_OW + 128;
static constexpr int D_X  = D_OB + 2;
static constexpr int D_SMEM = (D_X + 128) * 4;

__global__ void __launch_bounds__(TPB, 1) k_decoder(
    const float* __restrict__ obs, const float* __restrict__ wih,
    const float* __restrict__ whh, const float* __restrict__ bih,
    const float* __restrict__ bhh, const float* __restrict__ outw,
    const float* __restrict__ outb, float* __restrict__ out, int B)
{
    extern __shared__ float sm[];
    float* vsh  = sm + D_V;
    float* zbuf = sm + D_Z;
    float* ow   = sm + D_OW;
    float* ob   = sm + D_OB;
    float* xbuf = sm + D_X;

    const int tid = threadIdx.x;
    const size_t blockBase = (size_t)blockIdx.x * 64;
    const int warp = tid >> 5;
    const int gid  = (tid & 31) >> 2;
    const int tig  = tid & 3;
    const int rbase = warp * 16;

    uint32_t ahi[16], alo[16];
    #pragma unroll
    for (int kt = 0; kt < 4; ++kt)
    #pragma unroll
    for (int j = 0; j < 4; ++j) {
        int row = rbase + gid + (j & 1) * 8;
        int col = 16 * kt + 2 * tig + (j >> 1) * 8;
        float f0 = whh[row * 64 + col], f1 = whh[row * 64 + col + 1];
        uint32_t h = pk_bf2(f0, f1);
        uint32_t l = pk_bf2(f0 - bf_lo(h), f1 - bf_hi(h));
        ahi[kt * 4 + j] = h;
        alo[kt * 4 + j] = l;
    }

    const int u  = tid & 63;
    const int eg = tid >> 6;
    const float wxi0 = wih[2*u],           wxi1 = wih[2*u+1];
    const float wxf0 = wih[2*(64+u)],      wxf1 = wih[2*(64+u)+1];
    const float wxg0 = wih[2*(128+u)],     wxg1 = wih[2*(128+u)+1];
    const float wxo0 = wih[2*(192+u)],     wxo1 = wih[2*(192+u)+1];
    const float bi = bih[u]       + bhh[u];
    const float bf = bih[64+u]    + bhh[64+u];
    const float bg = bih[128+u]   + bhh[128+u];
    const float bo = bih[192+u]   + bhh[192+u];

    for (int i = tid; i < 128; i += TPB) ow[i] = outw[i];
    if (tid < 2) ob[tid] = outb[tid];
    {
        const float4* src = (const float4*)(g_h1 + blockBase * HID);
        for (int i = tid; i < 64 * 16; i += TPB) {
            int ee = i >> 4, k4 = i & 15;
            *(float4*)(vsh + ee * HS + k4 * 4) = src[i];
        }
        for (int i = tid; i < 128; i += TPB) {
            int ee = i >> 1, j = i & 1;
            xbuf[i] = obs[(blockBase + ee) * 40 + 38 + j];
        }
    }
    float c[8];
    #pragma unroll
    for (int j = 0; j < 8; ++j)
        c[j] = g_c1[(blockBase + eg * 8 + j) * HID + u];
    __syncthreads();

    #pragma unroll 1
    for (int t = 0; t < PRED; ++t) {
        #pragma unroll 1
        for (int nh = 0; nh < 2; ++nh) {
            float acc[16];
            #pragma unroll
            for (int i = 0; i < 16; ++i) acc[i] = 0.f;
            #pragma unroll
            for (int kt = 0; kt < 4; ++kt) {
                #pragma unroll
                for (int nt = 0; nt < 4; ++nt) {
                    const int e  = (nh * 4 + nt) * 8 + gid;
                    const int k0 = kt * 16 + 2 * tig;
                    float2 p0 = *(const float2*)(vsh + e * HS + k0);
                    float2 p1 = *(const float2*)(vsh + e * HS + k0 + 8);
                    uint32_t bh0 = pk_bf2(p0.x, p0.y);
                    uint32_t bh1 = pk_bf2(p1.x, p1.y);
                    uint32_t bl0 = pk_bf2(p0.x - bf_lo(bh0), p0.y - bf_hi(bh0));
                    uint32_t bl1 = pk_bf2(p1.x - bf_lo(bh1), p1.y - bf_hi(bh1));
                    float* a = acc + nt * 4;
                    const uint32_t* Ah = ahi + kt * 4;
                    const uint32_t* Al = alo + kt * 4;
                    MMA_B16(a, Ah, bh0, bh1);
                    MMA_B16(a, Ah, bl0, bl1);
                    MMA_B16(a, Al, bh0, bh1);
                }
            }
            #pragma unroll
            for (int nt = 0; nt < 4; ++nt) {
                const int e0 = (nh * 4 + nt) * 8 + 2 * tig;
                const int r0 = rbase + gid;
                const float* a = acc + nt * 4;
                *(float2*)(zbuf + r0 * ZS + e0)       = make_float2(a[0], a[1]);
                *(float2*)(zbuf + (r0 + 8) * ZS + e0) = make_float2(a[2], a[3]);
            }
        }
        __syncthreads();

        #pragma unroll
        for (int j = 0; j < 8; ++j) {
            const int e = eg * 8 + j;
            const float x0 = xbuf[e * 2], x1 = xbuf[e * 2 + 1];
            float zi = zbuf[u * ZS + e]         + fmaf(wxi1, x1, fmaf(wxi0, x0, bi));
            float zf = zbuf[(64 + u) * ZS + e]  + fmaf(wxf1, x1, fmaf(wxf0, x0, bf));
            float zg = zbuf[(128 + u) * ZS + e] + fmaf(wxg1, x1, fmaf(wxg0, x0, bg));
            float zo = zbuf[(192 + u) * ZS + e] + fmaf(wxo1, x1, fmaf(wxo0, x0, bo));
            float cn = sigf(zf) * c[j] + sigf(zi) * tanhf_(zg);
            c[j] = cn;
            vsh[e * HS + u] = sigf(zo) * tanhf_(cn);
        }
        __syncthreads();

        if (tid < 128) {
            const int e = tid >> 1, od = tid & 1;
            float o = ob[od];
            #pragma unroll
            for (int k4 = 0; k4 < 16; ++k4) {
                float4 hh = *(const float4*)(vsh + e * HS + k4 * 4);
                float4 w  = *(const float4*)(ow + od * 64 + k4 * 4);
                o += w.x * hh.x + w.y * hh.y + w.z * hh.z + w.w * hh.w;
            }
            out[(blockBase + e) * (PRED * 2) + t * 2 + od] = o;
            xbuf[e * 2 + od] = o;
        }
        __syncthreads();
    }
}

// ---------------------------------------------------------------------------
extern "C" void kernel_launch(void* const* d_in, const int* in_sizes, int n_in,
                              void* d_out, int out_size)
{
    const float* obs     = (const float*)d_in[0];
    const float* w_ih_l0 = (const float*)d_in[1];
    const float* w_hh_l0 = (const float*)d_in[2];
    const float* b_ih_l0 = (const float*)d_in[3];
    const float* b_hh_l0 = (const float*)d_in[4];
    const float* w_ih_l1 = (const float*)d_in[5];
    const float* w_hh_l1 = (const float*)d_in[6];
    const float* b_ih_l1 = (const float*)d_in[7];
    const float* b_hh_l1 = (const float*)d_in[8];
    const float* dec_w_ih = (const float*)d_in[9];
    const float* dec_w_hh = (const float*)d_in[10];
    const float* dec_b_ih = (const float*)d_in[11];
    const float* dec_b_hh = (const float*)d_in[12];
    const float* out_w   = (const float*)d_in[13];
    const float* out_b   = (const float*)d_in[14];
    float* out = (float*)d_out;

    const int B = in_sizes[0] / (OBS * 2);

    cudaFuncSetAttribute(k_layer0,  cudaFuncAttributeMaxDynamicSharedMemorySize, L0_SMEM);
    cudaFuncSetAttribute(k_layer1,  cudaFuncAttributeMaxDynamicSharedMemorySize, K2_SMEM);
    cudaFuncSetAttribute(k_decoder, cudaFuncAttributeMaxDynamicSharedMemorySize, D_SMEM);

    k_layer0<<<B / 64, TPB, L0_SMEM>>>(obs, w_ih_l0, w_hh_l0, b_ih_l0, b_hh_l0, B);
    k_layer1<<<B / 64, TPB, K2_SMEM>>>(w_ih_l1, w_hh_l1, b_ih_l1, b_hh_l1, B);
    k_decoder<<<B / 64, TPB, D_SMEM>>>(obs, dec_w_ih, dec_w_hh, dec_b_ih, dec_b_hh,
                                       out_w, out_b, out, B);
}

// round 13
// speedup vs baseline: 2.5188x; 1.0467x over previous
#include <cuda_runtime.h>
#include <cstdint>

// Problem constants
static constexpr int HID  = 64;
static constexpr int OBS  = 20;
static constexpr int PRED = 12;
static constexpr int BMAX = 32768;

static constexpr int TPB = 512;   // 16 warps: 16 M-rows per warp

// Scratch (allocation-free rule: __device__ globals)
__device__ float g_hs1[(size_t)OBS * BMAX * HID];
__device__ float g_h1[(size_t)BMAX * HID];
__device__ float g_c1[(size_t)BMAX * HID];

__device__ __forceinline__ float sigf(float x) {
    return __fdividef(1.0f, 1.0f + __expf(-x));
}
__device__ __forceinline__ float tanhf_(float x) {
    return fmaf(2.0f, sigf(2.0f * x), -1.0f);
}

// bf16x2 pack: low 16 bits = lo value, high 16 bits = hi value
__device__ __forceinline__ uint32_t pk_bf2(float lo, float hi) {
    uint32_t r;
    asm("cvt.rn.bf16x2.f32 %0, %1, %2;" : "=r"(r) : "f"(hi), "f"(lo));
    return r;
}
__device__ __forceinline__ float bf_lo(uint32_t p) { return __uint_as_float(p << 16); }
__device__ __forceinline__ float bf_hi(uint32_t p) { return __uint_as_float(p & 0xffff0000u); }

#define MMA_B16(c, a, b0, b1) \
    asm volatile("mma.sync.aligned.m16n8k16.row.col.f32.bf16.bf16.f32 " \
        "{%0,%1,%2,%3}, {%4,%5,%6,%7}, {%8,%9}, {%0,%1,%2,%3};" \
        : "+f"((c)[0]), "+f"((c)[1]), "+f"((c)[2]), "+f"((c)[3]) \
        : "r"((a)[0]), "r"((a)[1]), "r"((a)[2]), "r"((a)[3]), "r"(b0), "r"(b1))

static constexpr int HS  = 68;    // fp32 h staging stride (floats)
static constexpr int BS0 = 36;    // bf16x2 stride, 32 k-pairs (≡4 mod 32)
static constexpr int BS1 = 68;    // bf16x2 stride, 64 k-pairs (layer1)
static constexpr int ZSA = 130;   // zbuf stride for EPB=128 kernels
static constexpr int ZS1 = 66;    // zbuf stride for layer1 (EPB=64)

// ===========================================================================
// Kernel 1: encoder layer 0. EPB=128, 16-warp M-split, single-conversion B.
// ===========================================================================
static constexpr int L0_EPB = 128;
static constexpr int L0_V   = 0;                          // 128*68 fp32
static constexpr int L0_BH  = L0_EPB * HS;                // 128*36 u32
static constexpr int L0_BL  = L0_BH + L0_EPB * BS0;       // 128*36 u32
static constexpr int L0_Z   = L0_BL + L0_EPB * BS0;       // 256*130 fp32
static constexpr int L0_OBS = L0_Z + 256 * ZSA;           // 128*40 fp32
static constexpr int L0_SMEM = (L0_OBS + L0_EPB * 40) * 4;  // 225,280 B

__global__ void __launch_bounds__(TPB, 1) k_layer0(
    const float* __restrict__ obs, const float* __restrict__ wih,
    const float* __restrict__ whh, const float* __restrict__ bih,
    const float* __restrict__ bhh, int B)
{
    extern __shared__ float sm[];
    float*    vsh   = sm + L0_V;
    uint32_t* vbh   = (uint32_t*)(sm + L0_BH);
    uint32_t* vbl   = (uint32_t*)(sm + L0_BL);
    float*    zbuf  = sm + L0_Z;
    float*    obs_s = sm + L0_OBS;

    const int tid = threadIdx.x;
    const size_t blockBase = (size_t)blockIdx.x * L0_EPB;
    const int warp = tid >> 5;
    const int gid  = (tid & 31) >> 2;
    const int tig  = tid & 3;
    const int rbase = warp * 16;

    // Persistent A fragments from Whh (K=64 -> 4 k-tiles, 1 m-tile)
    uint32_t ahi[16], alo[16];
    #pragma unroll
    for (int kt = 0; kt < 4; ++kt)
    #pragma unroll
    for (int j = 0; j < 4; ++j) {
        int row = rbase + gid + (j & 1) * 8;
        int col = 16 * kt + 2 * tig + (j >> 1) * 8;
        float f0 = whh[row * 64 + col], f1 = whh[row * 64 + col + 1];
        uint32_t h = pk_bf2(f0, f1);
        uint32_t l = pk_bf2(f0 - bf_lo(h), f1 - bf_hi(h));
        ahi[kt * 4 + j] = h;
        alo[kt * 4 + j] = l;
    }

    // Epilogue constants (unit u); 16 elems per thread
    const int u  = tid & 63;
    const int eg = tid >> 6;        // 0..7
    const float wxi0 = wih[2*u],           wxi1 = wih[2*u+1];
    const float wxf0 = wih[2*(64+u)],      wxf1 = wih[2*(64+u)+1];
    const float wxg0 = wih[2*(128+u)],     wxg1 = wih[2*(128+u)+1];
    const float wxo0 = wih[2*(192+u)],     wxo1 = wih[2*(192+u)+1];
    const float bi = bih[u]       + bhh[u];
    const float bf = bih[64+u]    + bhh[64+u];
    const float bg = bih[128+u]   + bhh[128+u];
    const float bo = bih[192+u]   + bhh[192+u];

    for (int i = tid; i < L0_EPB * HS; i += TPB) vsh[i] = 0.f;   // h0 = 0
    for (int i = tid; i < L0_EPB * 40; i += TPB) {
        int ee = i / 40, j = i % 40;
        obs_s[i] = obs[(blockBase + ee) * 40 + j];
    }

    float c[16];
    #pragma unroll
    for (int j = 0; j < 16; ++j) c[j] = 0.f;

    #pragma unroll 1
    for (int t = 0; t < OBS; ++t) {
        __syncthreads();   // epilogue h(t-1) in vsh visible; vbf/zbuf free
        if (t > 0) {       // coalesced store of h(t-1)
            float4* dst = (float4*)(g_hs1 + ((size_t)(t - 1) * B + blockBase) * HID);
            for (int i = tid; i < L0_EPB * 16; i += TPB) {
                int ee = i >> 4, k4 = i & 15;
                dst[i] = *(const float4*)(vsh + ee * HS + k4 * 4);
            }
        }
        // Convert h(t-1) fp32 -> bf16 hi/lo (ONCE per step)
        for (int i = tid; i < L0_EPB * 32; i += TPB) {
            int e = i >> 5, kp = i & 31;
            float2 p = *(const float2*)(vsh + e * HS + 2 * kp);
            uint32_t h = pk_bf2(p.x, p.y);
            vbh[e * BS0 + kp] = h;
            vbl[e * BS0 + kp] = pk_bf2(p.x - bf_lo(h), p.y - bf_hi(h));
        }
        __syncthreads();   // vbf ready

        // GEMM: z[256,128] = Whh @ h   (pure LDS.32 + MMA)
        #pragma unroll 1
        for (int nh = 0; nh < 4; ++nh) {
            float acc[16];
            #pragma unroll
            for (int i = 0; i < 16; ++i) acc[i] = 0.f;
            #pragma unroll
            for (int kt = 0; kt < 4; ++kt) {
                #pragma unroll
                for (int nt = 0; nt < 4; ++nt) {
                    const int e = (nh * 4 + nt) * 8 + gid;
                    const int base = e * BS0 + 8 * kt + tig;
                    uint32_t bh0 = vbh[base], bh1 = vbh[base + 4];
                    uint32_t bl0 = vbl[base], bl1 = vbl[base + 4];
                    float* a = acc + nt * 4;
                    const uint32_t* Ah = ahi + kt * 4;
                    const uint32_t* Al = alo + kt * 4;
                    MMA_B16(a, Ah, bh0, bh1);
                    MMA_B16(a, Ah, bl0, bl1);
                    MMA_B16(a, Al, bh0, bh1);
                }
            }
            #pragma unroll
            for (int nt = 0; nt < 4; ++nt) {
                const int e0 = (nh * 4 + nt) * 8 + 2 * tig;
                const int r0 = rbase + gid;
                const float* a = acc + nt * 4;
                *(float2*)(zbuf + r0 * ZSA + e0)       = make_float2(a[0], a[1]);
                *(float2*)(zbuf + (r0 + 8) * ZSA + e0) = make_float2(a[2], a[3]);
            }
        }
        __syncthreads();   // zbuf ready; vsh/vbf reads done

        #pragma unroll
        for (int j = 0; j < 16; ++j) {
            const int e = eg * 16 + j;
            const float x0 = obs_s[e * 40 + 2 * t], x1 = obs_s[e * 40 + 2 * t + 1];
            float zi = zbuf[u * ZSA + e]         + fmaf(wxi1, x1, fmaf(wxi0, x0, bi));
            float zf = zbuf[(64 + u) * ZSA + e]  + fmaf(wxf1, x1, fmaf(wxf0, x0, bf));
            float zg = zbuf[(128 + u) * ZSA + e] + fmaf(wxg1, x1, fmaf(wxg0, x0, bg));
            float zo = zbuf[(192 + u) * ZSA + e] + fmaf(wxo1, x1, fmaf(wxo0, x0, bo));
            float cn = sigf(zf) * c[j] + sigf(zi) * tanhf_(zg);
            c[j] = cn;
            vsh[e * HS + u] = sigf(zo) * tanhf_(cn);
        }
    }
    __syncthreads();
    {
        float4* dst = (float4*)(g_hs1 + ((size_t)(OBS - 1) * B + blockBase) * HID);
        for (int i = tid; i < L0_EPB * 16; i += TPB) {
            int ee = i >> 4, k4 = i & 15;
            dst[i] = *(const float4*)(vsh + ee * HS + k4 * 4);
        }
    }
}

// ===========================================================================
// Kernel 2: layer 1 — VERBATIM round 12 (EPB=64, single-conversion bf16 B).
// ===========================================================================
static constexpr int K2_HST = 0;                          // 64*68 fp32
static constexpr int K2_BH  = 64 * HS;                    // 64*68 u32 hi
static constexpr int K2_BL  = K2_BH + 64 * BS1;           // 64*68 u32 lo
static constexpr int K2_Z   = K2_BL + 64 * BS1;           // 256*66
static constexpr int K2_B   = K2_Z + 256 * ZS1;           // 256
static constexpr int K2_SMEM = (K2_B + 256) * 4;

__global__ void __launch_bounds__(TPB, 1) k_layer1(
    const float* __restrict__ wih, const float* __restrict__ whh,
    const float* __restrict__ bih, const float* __restrict__ bhh, int B)
{
    extern __shared__ float sm[];
    float*    hst  = sm + K2_HST;
    uint32_t* vbh  = (uint32_t*)(sm + K2_BH);
    uint32_t* vbl  = (uint32_t*)(sm + K2_BL);
    float*    zbuf = sm + K2_Z;
    float*    bs   = sm + K2_B;

    const int tid = threadIdx.x;
    const size_t blockBase = (size_t)blockIdx.x * 64;
    const int warp = tid >> 5;
    const int gid  = (tid & 31) >> 2;
    const int tig  = tid & 3;
    const int rbase = warp * 16;

    uint32_t ahi[32], alo[32];
    #pragma unroll
    for (int kt = 0; kt < 8; ++kt)
    #pragma unroll
    for (int j = 0; j < 4; ++j) {
        int row = rbase + gid + (j & 1) * 8;
        int col = 16 * kt + 2 * tig + (j >> 1) * 8;
        const float* src = (col < 64) ? (wih + row * 64 + col)
                                      : (whh + row * 64 + (col - 64));
        float f0 = src[0], f1 = src[1];
        uint32_t h = pk_bf2(f0, f1);
        uint32_t l = pk_bf2(f0 - bf_lo(h), f1 - bf_hi(h));
        ahi[kt * 4 + j] = h;
        alo[kt * 4 + j] = l;
    }

    for (int i = tid; i < 256; i += TPB) bs[i] = bih[i] + bhh[i];
    for (int i = tid; i < 64 * HS; i += TPB) hst[i] = 0.f;   // h0 = 0

    const int u  = tid & 63;
    const int eg = tid >> 6;
    float c[8];
    #pragma unroll
    for (int j = 0; j < 8; ++j) c[j] = 0.f;

    #pragma unroll 1
    for (int t = 0; t < OBS; ++t) {
        __syncthreads();
        {
            const float4* src = (const float4*)(g_hs1 + ((size_t)t * B + blockBase) * HID);
            for (int i = tid; i < 64 * 16; i += TPB) {
                int ee = i >> 4, k4 = i & 15;
                float4 v = src[i];
                uint32_t h0 = pk_bf2(v.x, v.y), h1 = pk_bf2(v.z, v.w);
                vbh[ee * BS1 + 2 * k4]     = h0;
                vbh[ee * BS1 + 2 * k4 + 1] = h1;
                vbl[ee * BS1 + 2 * k4]     = pk_bf2(v.x - bf_lo(h0), v.y - bf_hi(h0));
                vbl[ee * BS1 + 2 * k4 + 1] = pk_bf2(v.z - bf_lo(h1), v.w - bf_hi(h1));
            }
        }
        for (int i = tid; i < 64 * 32; i += TPB) {
            int e = i >> 5, kp = i & 31;
            float2 p = *(const float2*)(hst + e * HS + 2 * kp);
            uint32_t h = pk_bf2(p.x, p.y);
            vbh[e * BS1 + 32 + kp] = h;
            vbl[e * BS1 + 32 + kp] = pk_bf2(p.x - bf_lo(h), p.y - bf_hi(h));
        }
        __syncthreads();

        #pragma unroll 1
        for (int nh = 0; nh < 2; ++nh) {
            float acc[16];
            #pragma unroll
            for (int i = 0; i < 16; ++i) acc[i] = 0.f;

            #pragma unroll
            for (int kt = 0; kt < 8; ++kt) {
                #pragma unroll
                for (int nt = 0; nt < 4; ++nt) {
                    const int e = (nh * 4 + nt) * 8 + gid;
                    const int base = e * BS1 + 8 * kt + tig;
                    uint32_t bh0 = vbh[base], bh1 = vbh[base + 4];
                    uint32_t bl0 = vbl[base], bl1 = vbl[base + 4];
                    float* a = acc + nt * 4;
                    const uint32_t* Ah = ahi + kt * 4;
                    const uint32_t* Al = alo + kt * 4;
                    MMA_B16(a, Ah, bh0, bh1);
                    MMA_B16(a, Ah, bl0, bl1);
                    MMA_B16(a, Al, bh0, bh1);
                }
            }
            #pragma unroll
            for (int nt = 0; nt < 4; ++nt) {
                const int e0 = (nh * 4 + nt) * 8 + 2 * tig;
                const int r0 = rbase + gid;
                const float* a = acc + nt * 4;
                *(float2*)(zbuf + r0 * ZS1 + e0)       = make_float2(a[0], a[1]);
                *(float2*)(zbuf + (r0 + 8) * ZS1 + e0) = make_float2(a[2], a[3]);
            }
        }
        __syncthreads();

        const bool last = (t == OBS - 1);
        #pragma unroll
        for (int j = 0; j < 8; ++j) {
            const int e = eg * 8 + j;
            float zi = zbuf[u * ZS1 + e]          + bs[u];
            float zf = zbuf[(64 + u) * ZS1 + e]   + bs[64 + u];
            float zg = zbuf[(128 + u) * ZS1 + e]  + bs[128 + u];
            float zo = zbuf[(192 + u) * ZS1 + e]  + bs[192 + u];
            float cn = sigf(zf) * c[j] + sigf(zi) * tanhf_(zg);
            c[j] = cn;
            float hn = sigf(zo) * tanhf_(cn);
            hst[e * HS + u] = hn;
            if (last) {
                g_h1[(blockBase + e) * HID + u] = hn;
                g_c1[(blockBase + e) * HID + u] = cn;
            }
        }
    }
}

// ===========================================================================
// Kernel 3: decoder. EPB=128, in-loop conversion (round-11 style), ZSA zbuf.
// ===========================================================================
static constexpr int D_EPB = 128;
static constexpr int D_V  = 0;                    // 128*68
static constexpr int D_Z  = D_EPB * HS;           // 256*130
static constexpr int D_OW = D_Z + 256 * ZSA;      // 128
static constexpr int D_OB = D_OW + 128;           // 2
static constexpr int D_X  = D_OB + 2;             // 256
static constexpr int D_SMEM = (D_X + 256) * 4;    // ~201 KB

__global__ void __launch_bounds__(TPB, 1) k_decoder(
    const float* __restrict__ obs, const float* __restrict__ wih,
    const float* __restrict__ whh, const float* __restrict__ bih,
    const float* __restrict__ bhh, const float* __restrict__ outw,
    const float* __restrict__ outb, float* __restrict__ out, int B)
{
    extern __shared__ float sm[];
    float* vsh  = sm + D_V;
    float* zbuf = sm + D_Z;
    float* ow   = sm + D_OW;
    float* ob   = sm + D_OB;
    float* xbuf = sm + D_X;

    const int tid = threadIdx.x;
    const size_t blockBase = (size_t)blockIdx.x * D_EPB;
    const int warp = tid >> 5;
    const int gid  = (tid & 31) >> 2;
    const int tig  = tid & 3;
    const int rbase = warp * 16;

    uint32_t ahi[16], alo[16];
    #pragma unroll
    for (int kt = 0; kt < 4; ++kt)
    #pragma unroll
    for (int j = 0; j < 4; ++j) {
        int row = rbase + gid + (j & 1) * 8;
        int col = 16 * kt + 2 * tig + (j >> 1) * 8;
        float f0 = whh[row * 64 + col], f1 = whh[row * 64 + col + 1];
        uint32_t h = pk_bf2(f0, f1);
        uint32_t l = pk_bf2(f0 - bf_lo(h), f1 - bf_hi(h));
        ahi[kt * 4 + j] = h;
        alo[kt * 4 + j] = l;
    }

    const int u  = tid & 63;
    const int eg = tid >> 6;
    const float wxi0 = wih[2*u],           wxi1 = wih[2*u+1];
    const float wxf0 = wih[2*(64+u)],      wxf1 = wih[2*(64+u)+1];
    const float wxg0 = wih[2*(128+u)],     wxg1 = wih[2*(128+u)+1];
    const float wxo0 = wih[2*(192+u)],     wxo1 = wih[2*(192+u)+1];
    const float bi = bih[u]       + bhh[u];
    const float bf = bih[64+u]    + bhh[64+u];
    const float bg = bih[128+u]   + bhh[128+u];
    const float bo = bih[192+u]   + bhh[192+u];

    for (int i = tid; i < 128; i += TPB) ow[i] = outw[i];
    if (tid < 2) ob[tid] = outb[tid];
    {
        const float4* src = (const float4*)(g_h1 + blockBase * HID);
        for (int i = tid; i < D_EPB * 16; i += TPB) {
            int ee = i >> 4, k4 = i & 15;
            *(float4*)(vsh + ee * HS + k4 * 4) = src[i];
        }
        for (int i = tid; i < D_EPB * 2; i += TPB) {
            int ee = i >> 1, j = i & 1;
            xbuf[i] = obs[(blockBase + ee) * 40 + 38 + j];
        }
    }
    float c[16];
    #pragma unroll
    for (int j = 0; j < 16; ++j)
        c[j] = g_c1[(blockBase + eg * 16 + j) * HID + u];
    __syncthreads();

    #pragma unroll 1
    for (int t = 0; t < PRED; ++t) {
        #pragma unroll 1
        for (int nh = 0; nh < 4; ++nh) {
            float acc[16];
            #pragma unroll
            for (int i = 0; i < 16; ++i) acc[i] = 0.f;
            #pragma unroll
            for (int kt = 0; kt < 4; ++kt) {
                #pragma unroll
                for (int nt = 0; nt < 4; ++nt) {
                    const int e  = (nh * 4 + nt) * 8 + gid;
                    const int k0 = kt * 16 + 2 * tig;
                    float2 p0 = *(const float2*)(vsh + e * HS + k0);
                    float2 p1 = *(const float2*)(vsh + e * HS + k0 + 8);
                    uint32_t bh0 = pk_bf2(p0.x, p0.y);
                    uint32_t bh1 = pk_bf2(p1.x, p1.y);
                    uint32_t bl0 = pk_bf2(p0.x - bf_lo(bh0), p0.y - bf_hi(bh0));
                    uint32_t bl1 = pk_bf2(p1.x - bf_lo(bh1), p1.y - bf_hi(bh1));
                    float* a = acc + nt * 4;
                    const uint32_t* Ah = ahi + kt * 4;
                    const uint32_t* Al = alo + kt * 4;
                    MMA_B16(a, Ah, bh0, bh1);
                    MMA_B16(a, Ah, bl0, bl1);
                    MMA_B16(a, Al, bh0, bh1);
                }
            }
            #pragma unroll
            for (int nt = 0; nt < 4; ++nt) {
                const int e0 = (nh * 4 + nt) * 8 + 2 * tig;
                const int r0 = rbase + gid;
                const float* a = acc + nt * 4;
                *(float2*)(zbuf + r0 * ZSA + e0)       = make_float2(a[0], a[1]);
                *(float2*)(zbuf + (r0 + 8) * ZSA + e0) = make_float2(a[2], a[3]);
            }
        }
        __syncthreads();   // zbuf ready; vsh reads done

        #pragma unroll
        for (int j = 0; j < 16; ++j) {
            const int e = eg * 16 + j;
            const float x0 = xbuf[e * 2], x1 = xbuf[e * 2 + 1];
            float zi = zbuf[u * ZSA + e]         + fmaf(wxi1, x1, fmaf(wxi0, x0, bi));
            float zf = zbuf[(64 + u) * ZSA + e]  + fmaf(wxf1, x1, fmaf(wxf0, x0, bf));
            float zg = zbuf[(128 + u) * ZSA + e] + fmaf(wxg1, x1, fmaf(wxg0, x0, bg));
            float zo = zbuf[(192 + u) * ZSA + e] + fmaf(wxo1, x1, fmaf(wxo0, x0, bo));
            float cn = sigf(zf) * c[j] + sigf(zi) * tanhf_(zg);
            c[j] = cn;
            vsh[e * HS + u] = sigf(zo) * tanhf_(cn);
        }
        __syncthreads();   // h(t) ready; xbuf/zbuf reads done

        // Out-projection + feedback (threads 0..255: e = tid>>1, od = tid&1)
        if (tid < 2 * D_EPB) {
            const int e = tid >> 1, od = tid & 1;
            float o = ob[od];
            #pragma unroll
            for (int k4 = 0; k4 < 16; ++k4) {
                float4 hh = *(const float4*)(vsh + e * HS + k4 * 4);
                float4 w  = *(const float4*)(ow + od * 64 + k4 * 4);
                o += w.x * hh.x + w.y * hh.y + w.z * hh.z + w.w * hh.w;
            }
            out[(blockBase + e) * (PRED * 2) + t * 2 + od] = o;
            xbuf[e * 2 + od] = o;
        }
        __syncthreads();   // xbuf(t+1) ready before next epilogue
    }
}

// ---------------------------------------------------------------------------
extern "C" void kernel_launch(void* const* d_in, const int* in_sizes, int n_in,
                              void* d_out, int out_size)
{
    const float* obs     = (const float*)d_in[0];
    const float* w_ih_l0 = (const float*)d_in[1];
    const float* w_hh_l0 = (const float*)d_in[2];
    const float* b_ih_l0 = (const float*)d_in[3];
    const float* b_hh_l0 = (const float*)d_in[4];
    const float* w_ih_l1 = (const float*)d_in[5];
    const float* w_hh_l1 = (const float*)d_in[6];
    const float* b_ih_l1 = (const float*)d_in[7];
    const float* b_hh_l1 = (const float*)d_in[8];
    const float* dec_w_ih = (const float*)d_in[9];
    const float* dec_w_hh = (const float*)d_in[10];
    const float* dec_b_ih = (const float*)d_in[11];
    const float* dec_b_hh = (const float*)d_in[12];
    const float* out_w   = (const float*)d_in[13];
    const float* out_b   = (const float*)d_in[14];
    float* out = (float*)d_out;

    const int B = in_sizes[0] / (OBS * 2);

    cudaFuncSetAttribute(k_layer0,  cudaFuncAttributeMaxDynamicSharedMemorySize, L0_SMEM);
    cudaFuncSetAttribute(k_layer1,  cudaFuncAttributeMaxDynamicSharedMemorySize, K2_SMEM);
    cudaFuncSetAttribute(k_decoder, cudaFuncAttributeMaxDynamicSharedMemorySize, D_SMEM);

    k_layer0<<<B / L0_EPB, TPB, L0_SMEM>>>(obs, w_ih_l0, w_hh_l0, b_ih_l0, b_hh_l0, B);
    k_layer1<<<B / 64, TPB, K2_SMEM>>>(w_ih_l1, w_hh_l1, b_ih_l1, b_hh_l1, B);
    k_decoder<<<B / D_EPB, TPB, D_SMEM>>>(obs, dec_w_ih, dec_w_hh, dec_b_ih, dec_b_hh,
                                          out_w, out_b, out, B);
}

// round 14
// speedup vs baseline: 2.5726x; 1.0213x over previous
#include <cuda_runtime.h>
#include <cstdint>

// Problem constants
static constexpr int HID  = 64;
static constexpr int OBS  = 20;
static constexpr int PRED = 12;
static constexpr int BMAX = 32768;

static constexpr int TPB = 512;   // 16 warps: 16 M-rows per warp

// Scratch (allocation-free rule: __device__ globals)
__device__ float g_hs1[(size_t)OBS * BMAX * HID];
__device__ float g_h1[(size_t)BMAX * HID];
__device__ float g_c1[(size_t)BMAX * HID];

__device__ __forceinline__ float sigf(float x) {
    return __fdividef(1.0f, 1.0f + __expf(-x));
}
__device__ __forceinline__ float tanhf_(float x) {
    return fmaf(2.0f, sigf(2.0f * x), -1.0f);
}

// bf16x2 pack: low 16 bits = lo value, high 16 bits = hi value
__device__ __forceinline__ uint32_t pk_bf2(float lo, float hi) {
    uint32_t r;
    asm("cvt.rn.bf16x2.f32 %0, %1, %2;" : "=r"(r) : "f"(hi), "f"(lo));
    return r;
}
__device__ __forceinline__ float bf_lo(uint32_t p) { return __uint_as_float(p << 16); }
__device__ __forceinline__ float bf_hi(uint32_t p) { return __uint_as_float(p & 0xffff0000u); }

#define MMA_B16(c, a, b0, b1) \
    asm volatile("mma.sync.aligned.m16n8k16.row.col.f32.bf16.bf16.f32 " \
        "{%0,%1,%2,%3}, {%4,%5,%6,%7}, {%8,%9}, {%0,%1,%2,%3};" \
        : "+f"((c)[0]), "+f"((c)[1]), "+f"((c)[2]), "+f"((c)[3]) \
        : "r"((a)[0]), "r"((a)[1]), "r"((a)[2]), "r"((a)[3]), "r"(b0), "r"(b1))

static constexpr int HS  = 68;    // fp32 h staging stride (floats)
static constexpr int BS0 = 36;    // bf16x2 stride, 32 k-pairs (≡4 mod 32)
static constexpr int BS1 = 68;    // bf16x2 stride, 64 k-pairs (layer1)
static constexpr int ZSA = 130;   // zbuf stride for EPB=128 kernels

// ===========================================================================
// Kernel 1: encoder layer 0 — VERBATIM round 13 (EPB=128).
// ===========================================================================
static constexpr int L0_EPB = 128;
static constexpr int L0_V   = 0;
static constexpr int L0_BH  = L0_EPB * HS;
static constexpr int L0_BL  = L0_BH + L0_EPB * BS0;
static constexpr int L0_Z   = L0_BL + L0_EPB * BS0;
static constexpr int L0_OBS = L0_Z + 256 * ZSA;
static constexpr int L0_SMEM = (L0_OBS + L0_EPB * 40) * 4;

__global__ void __launch_bounds__(TPB, 1) k_layer0(
    const float* __restrict__ obs, const float* __restrict__ wih,
    const float* __restrict__ whh, const float* __restrict__ bih,
    const float* __restrict__ bhh, int B)
{
    extern __shared__ float sm[];
    float*    vsh   = sm + L0_V;
    uint32_t* vbh   = (uint32_t*)(sm + L0_BH);
    uint32_t* vbl   = (uint32_t*)(sm + L0_BL);
    float*    zbuf  = sm + L0_Z;
    float*    obs_s = sm + L0_OBS;

    const int tid = threadIdx.x;
    const size_t blockBase = (size_t)blockIdx.x * L0_EPB;
    const int warp = tid >> 5;
    const int gid  = (tid & 31) >> 2;
    const int tig  = tid & 3;
    const int rbase = warp * 16;

    uint32_t ahi[16], alo[16];
    #pragma unroll
    for (int kt = 0; kt < 4; ++kt)
    #pragma unroll
    for (int j = 0; j < 4; ++j) {
        int row = rbase + gid + (j & 1) * 8;
        int col = 16 * kt + 2 * tig + (j >> 1) * 8;
        float f0 = whh[row * 64 + col], f1 = whh[row * 64 + col + 1];
        uint32_t h = pk_bf2(f0, f1);
        uint32_t l = pk_bf2(f0 - bf_lo(h), f1 - bf_hi(h));
        ahi[kt * 4 + j] = h;
        alo[kt * 4 + j] = l;
    }

    const int u  = tid & 63;
    const int eg = tid >> 6;
    const float wxi0 = wih[2*u],           wxi1 = wih[2*u+1];
    const float wxf0 = wih[2*(64+u)],      wxf1 = wih[2*(64+u)+1];
    const float wxg0 = wih[2*(128+u)],     wxg1 = wih[2*(128+u)+1];
    const float wxo0 = wih[2*(192+u)],     wxo1 = wih[2*(192+u)+1];
    const float bi = bih[u]       + bhh[u];
    const float bf = bih[64+u]    + bhh[64+u];
    const float bg = bih[128+u]   + bhh[128+u];
    const float bo = bih[192+u]   + bhh[192+u];

    for (int i = tid; i < L0_EPB * HS; i += TPB) vsh[i] = 0.f;
    for (int i = tid; i < L0_EPB * 40; i += TPB) {
        int ee = i / 40, j = i % 40;
        obs_s[i] = obs[(blockBase + ee) * 40 + j];
    }

    float c[16];
    #pragma unroll
    for (int j = 0; j < 16; ++j) c[j] = 0.f;

    #pragma unroll 1
    for (int t = 0; t < OBS; ++t) {
        __syncthreads();
        if (t > 0) {
            float4* dst = (float4*)(g_hs1 + ((size_t)(t - 1) * B + blockBase) * HID);
            for (int i = tid; i < L0_EPB * 16; i += TPB) {
                int ee = i >> 4, k4 = i & 15;
                dst[i] = *(const float4*)(vsh + ee * HS + k4 * 4);
            }
        }
        for (int i = tid; i < L0_EPB * 32; i += TPB) {
            int e = i >> 5, kp = i & 31;
            float2 p = *(const float2*)(vsh + e * HS + 2 * kp);
            uint32_t h = pk_bf2(p.x, p.y);
            vbh[e * BS0 + kp] = h;
            vbl[e * BS0 + kp] = pk_bf2(p.x - bf_lo(h), p.y - bf_hi(h));
        }
        __syncthreads();

        #pragma unroll 1
        for (int nh = 0; nh < 4; ++nh) {
            float acc[16];
            #pragma unroll
            for (int i = 0; i < 16; ++i) acc[i] = 0.f;
            #pragma unroll
            for (int kt = 0; kt < 4; ++kt) {
                #pragma unroll
                for (int nt = 0; nt < 4; ++nt) {
                    const int e = (nh * 4 + nt) * 8 + gid;
                    const int base = e * BS0 + 8 * kt + tig;
                    uint32_t bh0 = vbh[base], bh1 = vbh[base + 4];
                    uint32_t bl0 = vbl[base], bl1 = vbl[base + 4];
                    float* a = acc + nt * 4;
                    const uint32_t* Ah = ahi + kt * 4;
                    const uint32_t* Al = alo + kt * 4;
                    MMA_B16(a, Ah, bh0, bh1);
                    MMA_B16(a, Ah, bl0, bl1);
                    MMA_B16(a, Al, bh0, bh1);
                }
            }
            #pragma unroll
            for (int nt = 0; nt < 4; ++nt) {
                const int e0 = (nh * 4 + nt) * 8 + 2 * tig;
                const int r0 = rbase + gid;
                const float* a = acc + nt * 4;
                *(float2*)(zbuf + r0 * ZSA + e0)       = make_float2(a[0], a[1]);
                *(float2*)(zbuf + (r0 + 8) * ZSA + e0) = make_float2(a[2], a[3]);
            }
        }
        __syncthreads();

        #pragma unroll
        for (int j = 0; j < 16; ++j) {
            const int e = eg * 16 + j;
            const float x0 = obs_s[e * 40 + 2 * t], x1 = obs_s[e * 40 + 2 * t + 1];
            float zi = zbuf[u * ZSA + e]         + fmaf(wxi1, x1, fmaf(wxi0, x0, bi));
            float zf = zbuf[(64 + u) * ZSA + e]  + fmaf(wxf1, x1, fmaf(wxf0, x0, bf));
            float zg = zbuf[(128 + u) * ZSA + e] + fmaf(wxg1, x1, fmaf(wxg0, x0, bg));
            float zo = zbuf[(192 + u) * ZSA + e] + fmaf(wxo1, x1, fmaf(wxo0, x0, bo));
            float cn = sigf(zf) * c[j] + sigf(zi) * tanhf_(zg);
            c[j] = cn;
            vsh[e * HS + u] = sigf(zo) * tanhf_(cn);
        }
    }
    __syncthreads();
    {
        float4* dst = (float4*)(g_hs1 + ((size_t)(OBS - 1) * B + blockBase) * HID);
        for (int i = tid; i < L0_EPB * 16; i += TPB) {
            int ee = i >> 4, k4 = i & 15;
            dst[i] = *(const float4*)(vsh + ee * HS + k4 * 4);
        }
    }
}

// ===========================================================================
// Kernel 2 v4: layer 1, EPB=128, NO fp32 staging — epilogue writes bf16 h
// directly via shfl-paired packing. smem ~204 KB.
// ===========================================================================
static constexpr int K2_EPB = 128;
static constexpr int K2_BH  = 0;                          // 128*68 u32
static constexpr int K2_BL  = K2_BH + K2_EPB * BS1;       // 128*68 u32
static constexpr int K2_Z   = K2_BL + K2_EPB * BS1;       // 256*130 fp32
static constexpr int K2_B   = K2_Z + 256 * ZSA;           // 256
static constexpr int K2_SMEM = (K2_B + 256) * 4;          // 203,776 B

__global__ void __launch_bounds__(TPB, 1) k_layer1(
    const float* __restrict__ wih, const float* __restrict__ whh,
    const float* __restrict__ bih, const float* __restrict__ bhh, int B)
{
    extern __shared__ float sm[];
    uint32_t* vbh  = (uint32_t*)(sm + K2_BH);
    uint32_t* vbl  = (uint32_t*)(sm + K2_BL);
    float*    zbuf = sm + K2_Z;
    float*    bs   = sm + K2_B;

    const int tid = threadIdx.x;
    const size_t blockBase = (size_t)blockIdx.x * K2_EPB;
    const int warp = tid >> 5;
    const int gid  = (tid & 31) >> 2;
    const int tig  = tid & 3;
    const int rbase = warp * 16;

    uint32_t ahi[32], alo[32];
    #pragma unroll
    for (int kt = 0; kt < 8; ++kt)
    #pragma unroll
    for (int j = 0; j < 4; ++j) {
        int row = rbase + gid + (j & 1) * 8;
        int col = 16 * kt + 2 * tig + (j >> 1) * 8;
        const float* src = (col < 64) ? (wih + row * 64 + col)
                                      : (whh + row * 64 + (col - 64));
        float f0 = src[0], f1 = src[1];
        uint32_t h = pk_bf2(f0, f1);
        uint32_t l = pk_bf2(f0 - bf_lo(h), f1 - bf_hi(h));
        ahi[kt * 4 + j] = h;
        alo[kt * 4 + j] = l;
    }

    for (int i = tid; i < 256; i += TPB) bs[i] = bih[i] + bhh[i];
    // h0 = 0: zero the h k-pairs (32..63) of vbh/vbl
    for (int i = tid; i < K2_EPB * 32; i += TPB) {
        int e = i >> 5, kp = i & 31;
        vbh[e * BS1 + 32 + kp] = 0u;
        vbl[e * BS1 + 32 + kp] = 0u;
    }

    const int u  = tid & 63;
    const int eg = tid >> 6;
    float c[16];
    #pragma unroll
    for (int j = 0; j < 16; ++j) c[j] = 0.f;

    #pragma unroll 1
    for (int t = 0; t < OBS; ++t) {
        __syncthreads();   // epilogue h-writes visible; x k-pairs free
        // x: load fp32 from g_hs1, convert straight to bf16 hi/lo (k-pairs 0..31)
        {
            const float4* src = (const float4*)(g_hs1 + ((size_t)t * B + blockBase) * HID);
            for (int i = tid; i < K2_EPB * 16; i += TPB) {
                int ee = i >> 4, k4 = i & 15;
                float4 v = src[i];
                uint32_t h0 = pk_bf2(v.x, v.y), h1 = pk_bf2(v.z, v.w);
                vbh[ee * BS1 + 2 * k4]     = h0;
                vbh[ee * BS1 + 2 * k4 + 1] = h1;
                vbl[ee * BS1 + 2 * k4]     = pk_bf2(v.x - bf_lo(h0), v.y - bf_hi(h0));
                vbl[ee * BS1 + 2 * k4 + 1] = pk_bf2(v.z - bf_lo(h1), v.w - bf_hi(h1));
            }
        }
        __syncthreads();   // full v ready

        // GEMM: z[256,128] = Wcat @ v
        #pragma unroll 1
        for (int nh = 0; nh < 4; ++nh) {
            float acc[16];
            #pragma unroll
            for (int i = 0; i < 16; ++i) acc[i] = 0.f;

            #pragma unroll
            for (int kt = 0; kt < 8; ++kt) {
                #pragma unroll
                for (int nt = 0; nt < 4; ++nt) {
                    const int e = (nh * 4 + nt) * 8 + gid;
                    const int base = e * BS1 + 8 * kt + tig;
                    uint32_t bh0 = vbh[base], bh1 = vbh[base + 4];
                    uint32_t bl0 = vbl[base], bl1 = vbl[base + 4];
                    float* a = acc + nt * 4;
                    const uint32_t* Ah = ahi + kt * 4;
                    const uint32_t* Al = alo + kt * 4;
                    MMA_B16(a, Ah, bh0, bh1);
                    MMA_B16(a, Ah, bl0, bl1);
                    MMA_B16(a, Al, bh0, bh1);
                }
            }
            #pragma unroll
            for (int nt = 0; nt < 4; ++nt) {
                const int e0 = (nh * 4 + nt) * 8 + 2 * tig;
                const int r0 = rbase + gid;
                const float* a = acc + nt * 4;
                *(float2*)(zbuf + r0 * ZSA + e0)       = make_float2(a[0], a[1]);
                *(float2*)(zbuf + (r0 + 8) * ZSA + e0) = make_float2(a[2], a[3]);
            }
        }
        __syncthreads();   // zbuf ready; all vbf reads done

        const bool last = (t == OBS - 1);
        #pragma unroll
        for (int j = 0; j < 16; ++j) {
            const int e = eg * 16 + j;
            float zi = zbuf[u * ZSA + e]          + bs[u];
            float zf = zbuf[(64 + u) * ZSA + e]   + bs[64 + u];
            float zg = zbuf[(128 + u) * ZSA + e]  + bs[128 + u];
            float zo = zbuf[(192 + u) * ZSA + e]  + bs[192 + u];
            float cn = sigf(zf) * c[j] + sigf(zi) * tanhf_(zg);
            c[j] = cn;
            float hn = sigf(zo) * tanhf_(cn);
            // pair h[u], h[u+1] via lane partner (tid^1 owns u^1, same e)
            float hp = __shfl_xor_sync(0xffffffffu, hn, 1);
            if ((u & 1) == 0) {
                uint32_t hh = pk_bf2(hn, hp);
                vbh[e * BS1 + 32 + (u >> 1)] = hh;
                vbl[e * BS1 + 32 + (u >> 1)] = pk_bf2(hn - bf_lo(hh), hp - bf_hi(hh));
            }
            if (last) {
                g_h1[(blockBase + e) * HID + u] = hn;
                g_c1[(blockBase + e) * HID + u] = cn;
            }
        }
    }
}

// ===========================================================================
// Kernel 3: decoder — VERBATIM round 13 (EPB=128).
// ===========================================================================
static constexpr int D_EPB = 128;
static constexpr int D_V  = 0;
static constexpr int D_Z  = D_EPB * HS;
static constexpr int D_OW = D_Z + 256 * ZSA;
static constexpr int D_OB = D_OW + 128;
static constexpr int D_X  = D_OB + 2;
static constexpr int D_SMEM = (D_X + 256) * 4;

__global__ void __launch_bounds__(TPB, 1) k_decoder(
    const float* __restrict__ obs, const float* __restrict__ wih,
    const float* __restrict__ whh, const float* __restrict__ bih,
    const float* __restrict__ bhh, const float* __restrict__ outw,
    const float* __restrict__ outb, float* __restrict__ out, int B)
{
    extern __shared__ float sm[];
    float* vsh  = sm + D_V;
    float* zbuf = sm + D_Z;
    float* ow   = sm + D_OW;
    float* ob   = sm + D_OB;
    float* xbuf = sm + D_X;

    const int tid = threadIdx.x;
    const size_t blockBase = (size_t)blockIdx.x * D_EPB;
    const int warp = tid >> 5;
    const int gid  = (tid & 31) >> 2;
    const int tig  = tid & 3;
    const int rbase = warp * 16;

    uint32_t ahi[16], alo[16];
    #pragma unroll
    for (int kt = 0; kt < 4; ++kt)
    #pragma unroll
    for (int j = 0; j < 4; ++j) {
        int row = rbase + gid + (j & 1) * 8;
        int col = 16 * kt + 2 * tig + (j >> 1) * 8;
        float f0 = whh[row * 64 + col], f1 = whh[row * 64 + col + 1];
        uint32_t h = pk_bf2(f0, f1);
        uint32_t l = pk_bf2(f0 - bf_lo(h), f1 - bf_hi(h));
        ahi[kt * 4 + j] = h;
        alo[kt * 4 + j] = l;
    }

    const int u  = tid & 63;
    const int eg = tid >> 6;
    const float wxi0 = wih[2*u],           wxi1 = wih[2*u+1];
    const float wxf0 = wih[2*(64+u)],      wxf1 = wih[2*(64+u)+1];
    const float wxg0 = wih[2*(128+u)],     wxg1 = wih[2*(128+u)+1];
    const float wxo0 = wih[2*(192+u)],     wxo1 = wih[2*(192+u)+1];
    const float bi = bih[u]       + bhh[u];
    const float bf = bih[64+u]    + bhh[64+u];
    const float bg = bih[128+u]   + bhh[128+u];
    const float bo = bih[192+u]   + bhh[192+u];

    for (int i = tid; i < 128; i += TPB) ow[i] = outw[i];
    if (tid < 2) ob[tid] = outb[tid];
    {
        const float4* src = (const float4*)(g_h1 + blockBase * HID);
        for (int i = tid; i < D_EPB * 16; i += TPB) {
            int ee = i >> 4, k4 = i & 15;
            *(float4*)(vsh + ee * HS + k4 * 4) = src[i];
        }
        for (int i = tid; i < D_EPB * 2; i += TPB) {
            int ee = i >> 1, j = i & 1;
            xbuf[i] = obs[(blockBase + ee) * 40 + 38 + j];
        }
    }
    float c[16];
    #pragma unroll
    for (int j = 0; j < 16; ++j)
        c[j] = g_c1[(blockBase + eg * 16 + j) * HID + u];
    __syncthreads();

    #pragma unroll 1
    for (int t = 0; t < PRED; ++t) {
        #pragma unroll 1
        for (int nh = 0; nh < 4; ++nh) {
            float acc[16];
            #pragma unroll
            for (int i = 0; i < 16; ++i) acc[i] = 0.f;
            #pragma unroll
            for (int kt = 0; kt < 4; ++kt) {
                #pragma unroll
                for (int nt = 0; nt < 4; ++nt) {
                    const int e  = (nh * 4 + nt) * 8 + gid;
                    const int k0 = kt * 16 + 2 * tig;
                    float2 p0 = *(const float2*)(vsh + e * HS + k0);
                    float2 p1 = *(const float2*)(vsh + e * HS + k0 + 8);
                    uint32_t bh0 = pk_bf2(p0.x, p0.y);
                    uint32_t bh1 = pk_bf2(p1.x, p1.y);
                    uint32_t bl0 = pk_bf2(p0.x - bf_lo(bh0), p0.y - bf_hi(bh0));
                    uint32_t bl1 = pk_bf2(p1.x - bf_lo(bh1), p1.y - bf_hi(bh1));
                    float* a = acc + nt * 4;
                    const uint32_t* Ah = ahi + kt * 4;
                    const uint32_t* Al = alo + kt * 4;
                    MMA_B16(a, Ah, bh0, bh1);
                    MMA_B16(a, Ah, bl0, bl1);
                    MMA_B16(a, Al, bh0, bh1);
                }
            }
            #pragma unroll
            for (int nt = 0; nt < 4; ++nt) {
                const int e0 = (nh * 4 + nt) * 8 + 2 * tig;
                const int r0 = rbase + gid;
                const float* a = acc + nt * 4;
                *(float2*)(zbuf + r0 * ZSA + e0)       = make_float2(a[0], a[1]);
                *(float2*)(zbuf + (r0 + 8) * ZSA + e0) = make_float2(a[2], a[3]);
            }
        }
        __syncthreads();

        #pragma unroll
        for (int j = 0; j < 16; ++j) {
            const int e = eg * 16 + j;
            const float x0 = xbuf[e * 2], x1 = xbuf[e * 2 + 1];
            float zi = zbuf[u * ZSA + e]         + fmaf(wxi1, x1, fmaf(wxi0, x0, bi));
            float zf = zbuf[(64 + u) * ZSA + e]  + fmaf(wxf1, x1, fmaf(wxf0, x0, bf));
            float zg = zbuf[(128 + u) * ZSA + e] + fmaf(wxg1, x1, fmaf(wxg0, x0, bg));
            float zo = zbuf[(192 + u) * ZSA + e] + fmaf(wxo1, x1, fmaf(wxo0, x0, bo));
            float cn = sigf(zf) * c[j] + sigf(zi) * tanhf_(zg);
            c[j] = cn;
            vsh[e * HS + u] = sigf(zo) * tanhf_(cn);
        }
        __syncthreads();

        if (tid < 2 * D_EPB) {
            const int e = tid >> 1, od = tid & 1;
            float o = ob[od];
            #pragma unroll
            for (int k4 = 0; k4 < 16; ++k4) {
                float4 hh = *(const float4*)(vsh + e * HS + k4 * 4);
                float4 w  = *(const float4*)(ow + od * 64 + k4 * 4);
                o += w.x * hh.x + w.y * hh.y + w.z * hh.z + w.w * hh.w;
            }
            out[(blockBase + e) * (PRED * 2) + t * 2 + od] = o;
            xbuf[e * 2 + od] = o;
        }
        __syncthreads();
    }
}

// ---------------------------------------------------------------------------
extern "C" void kernel_launch(void* const* d_in, const int* in_sizes, int n_in,
                              void* d_out, int out_size)
{
    const float* obs     = (const float*)d_in[0];
    const float* w_ih_l0 = (const float*)d_in[1];
    const float* w_hh_l0 = (const float*)d_in[2];
    const float* b_ih_l0 = (const float*)d_in[3];
    const float* b_hh_l0 = (const float*)d_in[4];
    const float* w_ih_l1 = (const float*)d_in[5];
    const float* w_hh_l1 = (const float*)d_in[6];
    const float* b_ih_l1 = (const float*)d_in[7];
    const float* b_hh_l1 = (const float*)d_in[8];
    const float* dec_w_ih = (const float*)d_in[9];
    const float* dec_w_hh = (const float*)d_in[10];
    const float* dec_b_ih = (const float*)d_in[11];
    const float* dec_b_hh = (const float*)d_in[12];
    const float* out_w   = (const float*)d_in[13];
    const float* out_b   = (const float*)d_in[14];
    float* out = (float*)d_out;

    const int B = in_sizes[0] / (OBS * 2);

    cudaFuncSetAttribute(k_layer0,  cudaFuncAttributeMaxDynamicSharedMemorySize, L0_SMEM);
    cudaFuncSetAttribute(k_layer1,  cudaFuncAttributeMaxDynamicSharedMemorySize, K2_SMEM);
    cudaFuncSetAttribute(k_decoder, cudaFuncAttributeMaxDynamicSharedMemorySize, D_SMEM);

    k_layer0<<<B / L0_EPB, TPB, L0_SMEM>>>(obs, w_ih_l0, w_hh_l0, b_ih_l0, b_hh_l0, B);
    k_layer1<<<B / K2_EPB, TPB, K2_SMEM>>>(w_ih_l1, w_hh_l1, b_ih_l1, b_hh_l1, B);
    k_decoder<<<B / D_EPB, TPB, D_SMEM>>>(obs, dec_w_ih, dec_w_hh, dec_b_ih, dec_b_hh,
                                          out_w, out_b, out, B);
}

// round 15
// speedup vs baseline: 2.6147x; 1.0164x over previous
#include <cuda_runtime.h>
#include <cstdint>

// Problem constants
static constexpr int HID  = 64;
static constexpr int OBS  = 20;
static constexpr int PRED = 12;
static constexpr int BMAX = 32768;

static constexpr int TPB = 512;   // 16 warps: 16 M-rows per warp

// Scratch (allocation-free rule: __device__ globals)
// layer0 hidden states stored PRE-CONVERTED as bf16 hi/lo pairs (u32 each)
__device__ uint32_t g_hs1h[(size_t)OBS * BMAX * 32];
__device__ uint32_t g_hs1l[(size_t)OBS * BMAX * 32];
__device__ float g_h1[(size_t)BMAX * HID];
__device__ float g_c1[(size_t)BMAX * HID];

__device__ __forceinline__ float sigf(float x) {
    return __fdividef(1.0f, 1.0f + __expf(-x));
}
__device__ __forceinline__ float tanhf_(float x) {
    return fmaf(2.0f, sigf(2.0f * x), -1.0f);
}

// bf16x2 pack: low 16 bits = lo value, high 16 bits = hi value
__device__ __forceinline__ uint32_t pk_bf2(float lo, float hi) {
    uint32_t r;
    asm("cvt.rn.bf16x2.f32 %0, %1, %2;" : "=r"(r) : "f"(hi), "f"(lo));
    return r;
}
__device__ __forceinline__ float bf_lo(uint32_t p) { return __uint_as_float(p << 16); }
__device__ __forceinline__ float bf_hi(uint32_t p) { return __uint_as_float(p & 0xffff0000u); }

#define MMA_B16(c, a, b0, b1) \
    asm volatile("mma.sync.aligned.m16n8k16.row.col.f32.bf16.bf16.f32 " \
        "{%0,%1,%2,%3}, {%4,%5,%6,%7}, {%8,%9}, {%0,%1,%2,%3};" \
        : "+f"((c)[0]), "+f"((c)[1]), "+f"((c)[2]), "+f"((c)[3]) \
        : "r"((a)[0]), "r"((a)[1]), "r"((a)[2]), "r"((a)[3]), "r"(b0), "r"(b1))

static constexpr int HS  = 68;    // fp32 h stride (decoder vsh)
static constexpr int BS0 = 36;    // bf16x2 stride, 32 k-pairs (≡4 mod 32)
static constexpr int BS1 = 68;    // bf16x2 stride, 64 k-pairs (layer1)
static constexpr int ZSA = 130;   // zbuf stride, EPB=128

// ===========================================================================
// Kernel 1: encoder layer 0. EPB=128, bf16 end-to-end: epilogue writes h
// directly as hi/lo pairs (shfl-paired); no fp32 staging, no convert phase.
// ===========================================================================
static constexpr int L0_EPB = 128;
static constexpr int L0_BH  = 0;                          // 128*36 u32
static constexpr int L0_BL  = L0_BH + L0_EPB * BS0;       // 128*36 u32
static constexpr int L0_Z   = L0_BL + L0_EPB * BS0;       // 256*130 fp32
static constexpr int L0_OBS = L0_Z + 256 * ZSA;           // 128*40 fp32
static constexpr int L0_SMEM = (L0_OBS + L0_EPB * 40) * 4;  // 190,464 B

__global__ void __launch_bounds__(TPB, 1) k_layer0(
    const float* __restrict__ obs, const float* __restrict__ wih,
    const float* __restrict__ whh, const float* __restrict__ bih,
    const float* __restrict__ bhh, int B)
{
    extern __shared__ float sm[];
    uint32_t* vbh   = (uint32_t*)(sm + L0_BH);
    uint32_t* vbl   = (uint32_t*)(sm + L0_BL);
    float*    zbuf  = sm + L0_Z;
    float*    obs_s = sm + L0_OBS;

    const int tid = threadIdx.x;
    const size_t blockBase = (size_t)blockIdx.x * L0_EPB;
    const int warp = tid >> 5;
    const int gid  = (tid & 31) >> 2;
    const int tig  = tid & 3;
    const int rbase = warp * 16;

    // Persistent A fragments from Whh (K=64 -> 4 k-tiles, 1 m-tile)
    uint32_t ahi[16], alo[16];
    #pragma unroll
    for (int kt = 0; kt < 4; ++kt)
    #pragma unroll
    for (int j = 0; j < 4; ++j) {
        int row = rbase + gid + (j & 1) * 8;
        int col = 16 * kt + 2 * tig + (j >> 1) * 8;
        float f0 = whh[row * 64 + col], f1 = whh[row * 64 + col + 1];
        uint32_t h = pk_bf2(f0, f1);
        uint32_t l = pk_bf2(f0 - bf_lo(h), f1 - bf_hi(h));
        ahi[kt * 4 + j] = h;
        alo[kt * 4 + j] = l;
    }

    // Epilogue constants (unit u); 16 elems per thread
    const int u  = tid & 63;
    const int eg = tid >> 6;        // 0..7
    const float wxi0 = wih[2*u],           wxi1 = wih[2*u+1];
    const float wxf0 = wih[2*(64+u)],      wxf1 = wih[2*(64+u)+1];
    const float wxg0 = wih[2*(128+u)],     wxg1 = wih[2*(128+u)+1];
    const float wxo0 = wih[2*(192+u)],     wxo1 = wih[2*(192+u)+1];
    const float bi = bih[u]       + bhh[u];
    const float bf = bih[64+u]    + bhh[64+u];
    const float bg = bih[128+u]   + bhh[128+u];
    const float bo = bih[192+u]   + bhh[192+u];

    // h0 = 0
    for (int i = tid; i < L0_EPB * 32; i += TPB) {
        int e = i >> 5, kp = i & 31;
        vbh[e * BS0 + kp] = 0u;
        vbl[e * BS0 + kp] = 0u;
    }
    for (int i = tid; i < L0_EPB * 40; i += TPB) {
        int ee = i / 40, j = i % 40;
        obs_s[i] = obs[(blockBase + ee) * 40 + j];
    }

    float c[16];
    #pragma unroll
    for (int j = 0; j < 16; ++j) c[j] = 0.f;

    #pragma unroll 1
    for (int t = 0; t < OBS; ++t) {
        __syncthreads();   // epilogue bf16 h(t-1) visible; zbuf free
        if (t > 0) {       // coalesced store of pre-converted h(t-1)
            const size_t gb = ((size_t)(t - 1) * B + blockBase) * 32;
            for (int i = tid; i < L0_EPB * 32; i += TPB) {
                int e = i >> 5, kp = i & 31;
                g_hs1h[gb + (size_t)e * 32 + kp] = vbh[e * BS0 + kp];
                g_hs1l[gb + (size_t)e * 32 + kp] = vbl[e * BS0 + kp];
            }
        }

        // GEMM: z[256,128] = Whh @ h   (pure LDS.32 + MMA)
        #pragma unroll 1
        for (int nh = 0; nh < 4; ++nh) {
            float acc[16];
            #pragma unroll
            for (int i = 0; i < 16; ++i) acc[i] = 0.f;
            #pragma unroll
            for (int kt = 0; kt < 4; ++kt) {
                #pragma unroll
                for (int nt = 0; nt < 4; ++nt) {
                    const int e = (nh * 4 + nt) * 8 + gid;
                    const int base = e * BS0 + 8 * kt + tig;
                    uint32_t bh0 = vbh[base], bh1 = vbh[base + 4];
                    uint32_t bl0 = vbl[base], bl1 = vbl[base + 4];
                    float* a = acc + nt * 4;
                    const uint32_t* Ah = ahi + kt * 4;
                    const uint32_t* Al = alo + kt * 4;
                    MMA_B16(a, Ah, bh0, bh1);
                    MMA_B16(a, Ah, bl0, bl1);
                    MMA_B16(a, Al, bh0, bh1);
                }
            }
            #pragma unroll
            for (int nt = 0; nt < 4; ++nt) {
                const int e0 = (nh * 4 + nt) * 8 + 2 * tig;
                const int r0 = rbase + gid;
                const float* a = acc + nt * 4;
                *(float2*)(zbuf + r0 * ZSA + e0)       = make_float2(a[0], a[1]);
                *(float2*)(zbuf + (r0 + 8) * ZSA + e0) = make_float2(a[2], a[3]);
            }
        }
        __syncthreads();   // zbuf ready; vbf reads (GEMM + store) done

        #pragma unroll
        for (int j = 0; j < 16; ++j) {
            const int e = eg * 16 + j;
            const float x0 = obs_s[e * 40 + 2 * t], x1 = obs_s[e * 40 + 2 * t + 1];
            float zi = zbuf[u * ZSA + e]         + fmaf(wxi1, x1, fmaf(wxi0, x0, bi));
            float zf = zbuf[(64 + u) * ZSA + e]  + fmaf(wxf1, x1, fmaf(wxf0, x0, bf));
            float zg = zbuf[(128 + u) * ZSA + e] + fmaf(wxg1, x1, fmaf(wxg0, x0, bg));
            float zo = zbuf[(192 + u) * ZSA + e] + fmaf(wxo1, x1, fmaf(wxo0, x0, bo));
            float cn = sigf(zf) * c[j] + sigf(zi) * tanhf_(zg);
            c[j] = cn;
            float hn = sigf(zo) * tanhf_(cn);
            float hp = __shfl_xor_sync(0xffffffffu, hn, 1);   // partner = u^1
            if ((u & 1) == 0) {
                uint32_t hh = pk_bf2(hn, hp);
                vbh[e * BS0 + (u >> 1)] = hh;
                vbl[e * BS0 + (u >> 1)] = pk_bf2(hn - bf_lo(hh), hp - bf_hi(hh));
            }
        }
    }
    __syncthreads();
    {
        const size_t gb = ((size_t)(OBS - 1) * B + blockBase) * 32;
        for (int i = tid; i < L0_EPB * 32; i += TPB) {
            int e = i >> 5, kp = i & 31;
            g_hs1h[gb + (size_t)e * 32 + kp] = vbh[e * BS0 + kp];
            g_hs1l[gb + (size_t)e * 32 + kp] = vbl[e * BS0 + kp];
        }
    }
}

// ===========================================================================
// Kernel 2: layer 1. EPB=128; x-phase is a PURE COPY of pre-converted bf16;
// epilogue writes bf16 h via shfl (round-14 validated).
// ===========================================================================
static constexpr int K2_EPB = 128;
static constexpr int K2_BH  = 0;                          // 128*68 u32
static constexpr int K2_BL  = K2_BH + K2_EPB * BS1;       // 128*68 u32
static constexpr int K2_Z   = K2_BL + K2_EPB * BS1;       // 256*130 fp32
static constexpr int K2_B   = K2_Z + 256 * ZSA;           // 256
static constexpr int K2_SMEM = (K2_B + 256) * 4;          // 203,776 B

__global__ void __launch_bounds__(TPB, 1) k_layer1(
    const float* __restrict__ wih, const float* __restrict__ whh,
    const float* __restrict__ bih, const float* __restrict__ bhh, int B)
{
    extern __shared__ float sm[];
    uint32_t* vbh  = (uint32_t*)(sm + K2_BH);
    uint32_t* vbl  = (uint32_t*)(sm + K2_BL);
    float*    zbuf = sm + K2_Z;
    float*    bs   = sm + K2_B;

    const int tid = threadIdx.x;
    const size_t blockBase = (size_t)blockIdx.x * K2_EPB;
    const int warp = tid >> 5;
    const int gid  = (tid & 31) >> 2;
    const int tig  = tid & 3;
    const int rbase = warp * 16;

    uint32_t ahi[32], alo[32];
    #pragma unroll
    for (int kt = 0; kt < 8; ++kt)
    #pragma unroll
    for (int j = 0; j < 4; ++j) {
        int row = rbase + gid + (j & 1) * 8;
        int col = 16 * kt + 2 * tig + (j >> 1) * 8;
        const float* src = (col < 64) ? (wih + row * 64 + col)
                                      : (whh + row * 64 + (col - 64));
        float f0 = src[0], f1 = src[1];
        uint32_t h = pk_bf2(f0, f1);
        uint32_t l = pk_bf2(f0 - bf_lo(h), f1 - bf_hi(h));
        ahi[kt * 4 + j] = h;
        alo[kt * 4 + j] = l;
    }

    for (int i = tid; i < 256; i += TPB) bs[i] = bih[i] + bhh[i];
    for (int i = tid; i < K2_EPB * 32; i += TPB) {   // h0 = 0 (k-pairs 32..63)
        int e = i >> 5, kp = i & 31;
        vbh[e * BS1 + 32 + kp] = 0u;
        vbl[e * BS1 + 32 + kp] = 0u;
    }

    const int u  = tid & 63;
    const int eg = tid >> 6;
    float c[16];
    #pragma unroll
    for (int j = 0; j < 16; ++j) c[j] = 0.f;

    #pragma unroll 1
    for (int t = 0; t < OBS; ++t) {
        __syncthreads();   // epilogue h-writes visible; x k-pairs free
        {   // x: pure copy of pre-converted bf16 hi/lo (k-pairs 0..31)
            const size_t gb = ((size_t)t * B + blockBase) * 32;
            for (int i = tid; i < K2_EPB * 32; i += TPB) {
                int e = i >> 5, kp = i & 31;
                vbh[e * BS1 + kp] = g_hs1h[gb + (size_t)e * 32 + kp];
                vbl[e * BS1 + kp] = g_hs1l[gb + (size_t)e * 32 + kp];
            }
        }
        __syncthreads();   // full v ready

        #pragma unroll 1
        for (int nh = 0; nh < 4; ++nh) {
            float acc[16];
            #pragma unroll
            for (int i = 0; i < 16; ++i) acc[i] = 0.f;

            #pragma unroll
            for (int kt = 0; kt < 8; ++kt) {
                #pragma unroll
                for (int nt = 0; nt < 4; ++nt) {
                    const int e = (nh * 4 + nt) * 8 + gid;
                    const int base = e * BS1 + 8 * kt + tig;
                    uint32_t bh0 = vbh[base], bh1 = vbh[base + 4];
                    uint32_t bl0 = vbl[base], bl1 = vbl[base + 4];
                    float* a = acc + nt * 4;
                    const uint32_t* Ah = ahi + kt * 4;
                    const uint32_t* Al = alo + kt * 4;
                    MMA_B16(a, Ah, bh0, bh1);
                    MMA_B16(a, Ah, bl0, bl1);
                    MMA_B16(a, Al, bh0, bh1);
                }
            }
            #pragma unroll
            for (int nt = 0; nt < 4; ++nt) {
                const int e0 = (nh * 4 + nt) * 8 + 2 * tig;
                const int r0 = rbase + gid;
                const float* a = acc + nt * 4;
                *(float2*)(zbuf + r0 * ZSA + e0)       = make_float2(a[0], a[1]);
                *(float2*)(zbuf + (r0 + 8) * ZSA + e0) = make_float2(a[2], a[3]);
            }
        }
        __syncthreads();   // zbuf ready; all vbf reads done

        const bool last = (t == OBS - 1);
        #pragma unroll
        for (int j = 0; j < 16; ++j) {
            const int e = eg * 16 + j;
            float zi = zbuf[u * ZSA + e]          + bs[u];
            float zf = zbuf[(64 + u) * ZSA + e]   + bs[64 + u];
            float zg = zbuf[(128 + u) * ZSA + e]  + bs[128 + u];
            float zo = zbuf[(192 + u) * ZSA + e]  + bs[192 + u];
            float cn = sigf(zf) * c[j] + sigf(zi) * tanhf_(zg);
            c[j] = cn;
            float hn = sigf(zo) * tanhf_(cn);
            float hp = __shfl_xor_sync(0xffffffffu, hn, 1);
            if ((u & 1) == 0) {
                uint32_t hh = pk_bf2(hn, hp);
                vbh[e * BS1 + 32 + (u >> 1)] = hh;
                vbl[e * BS1 + 32 + (u >> 1)] = pk_bf2(hn - bf_lo(hh), hp - bf_hi(hh));
            }
            if (last) {
                g_h1[(blockBase + e) * HID + u] = hn;
                g_c1[(blockBase + e) * HID + u] = cn;
            }
        }
    }
}

// ===========================================================================
// Kernel 3: decoder. EPB=128, single-conversion bf16 B (vbh/vbl) + fp32 vsh
// kept only for the out-projection.
// ===========================================================================
static constexpr int D_EPB = 128;
static constexpr int D_V  = 0;                    // 128*68 fp32
static constexpr int D_BH = D_EPB * HS;           // 128*36 u32
static constexpr int D_BL = D_BH + D_EPB * BS0;   // 128*36 u32
static constexpr int D_Z  = D_BL + D_EPB * BS0;   // 256*130 fp32
static constexpr int D_OW = D_Z + 256 * ZSA;      // 128
static constexpr int D_OB = D_OW + 128;           // 2
static constexpr int D_X  = D_OB + 2;             // 256
static constexpr int D_SMEM = (D_X + 256) * 4;    // 206,344 B

__global__ void __launch_bounds__(TPB, 1) k_decoder(
    const float* __restrict__ obs, const float* __restrict__ wih,
    const float* __restrict__ whh, const float* __restrict__ bih,
    const float* __restrict__ bhh, const float* __restrict__ outw,
    const float* __restrict__ outb, float* __restrict__ out, int B)
{
    extern __shared__ float sm[];
    float*    vsh  = sm + D_V;
    uint32_t* vbh  = (uint32_t*)(sm + D_BH);
    uint32_t* vbl  = (uint32_t*)(sm + D_BL);
    float*    zbuf = sm + D_Z;
    float*    ow   = sm + D_OW;
    float*    ob   = sm + D_OB;
    float*    xbuf = sm + D_X;

    const int tid = threadIdx.x;
    const size_t blockBase = (size_t)blockIdx.x * D_EPB;
    const int warp = tid >> 5;
    const int gid  = (tid & 31) >> 2;
    const int tig  = tid & 3;
    const int rbase = warp * 16;

    uint32_t ahi[16], alo[16];
    #pragma unroll
    for (int kt = 0; kt < 4; ++kt)
    #pragma unroll
    for (int j = 0; j < 4; ++j) {
        int row = rbase + gid + (j & 1) * 8;
        int col = 16 * kt + 2 * tig + (j >> 1) * 8;
        float f0 = whh[row * 64 + col], f1 = whh[row * 64 + col + 1];
        uint32_t h = pk_bf2(f0, f1);
        uint32_t l = pk_bf2(f0 - bf_lo(h), f1 - bf_hi(h));
        ahi[kt * 4 + j] = h;
        alo[kt * 4 + j] = l;
    }

    const int u  = tid & 63;
    const int eg = tid >> 6;
    const float wxi0 = wih[2*u],           wxi1 = wih[2*u+1];
    const float wxf0 = wih[2*(64+u)],      wxf1 = wih[2*(64+u)+1];
    const float wxg0 = wih[2*(128+u)],     wxg1 = wih[2*(128+u)+1];
    const float wxo0 = wih[2*(192+u)],     wxo1 = wih[2*(192+u)+1];
    const float bi = bih[u]       + bhh[u];
    const float bf = bih[64+u]    + bhh[64+u];
    const float bg = bih[128+u]   + bhh[128+u];
    const float bo = bih[192+u]   + bhh[192+u];

    for (int i = tid; i < 128; i += TPB) ow[i] = outw[i];
    if (tid < 2) ob[tid] = outb[tid];
    // init: h1 fp32 -> vsh + one-time bf16 conversion into vbh/vbl
    {
        const float4* src = (const float4*)(g_h1 + blockBase * HID);
        for (int i = tid; i < D_EPB * 16; i += TPB) {
            int ee = i >> 4, k4 = i & 15;
            float4 v = src[i];
            *(float4*)(vsh + ee * HS + k4 * 4) = v;
            uint32_t h0 = pk_bf2(v.x, v.y), h1 = pk_bf2(v.z, v.w);
            vbh[ee * BS0 + 2 * k4]     = h0;
            vbh[ee * BS0 + 2 * k4 + 1] = h1;
            vbl[ee * BS0 + 2 * k4]     = pk_bf2(v.x - bf_lo(h0), v.y - bf_hi(h0));
            vbl[ee * BS0 + 2 * k4 + 1] = pk_bf2(v.z - bf_lo(h1), v.w - bf_hi(h1));
        }
        for (int i = tid; i < D_EPB * 2; i += TPB) {
            int ee = i >> 1, j = i & 1;
            xbuf[i] = obs[(blockBase + ee) * 40 + 38 + j];
        }
    }
    float c[16];
    #pragma unroll
    for (int j = 0; j < 16; ++j)
        c[j] = g_c1[(blockBase + eg * 16 + j) * HID + u];
    __syncthreads();

    #pragma unroll 1
    for (int t = 0; t < PRED; ++t) {
        // GEMM: z = Whh @ h (pure LDS.32 + MMA)
        #pragma unroll 1
        for (int nh = 0; nh < 4; ++nh) {
            float acc[16];
            #pragma unroll
            for (int i = 0; i < 16; ++i) acc[i] = 0.f;
            #pragma unroll
            for (int kt = 0; kt < 4; ++kt) {
                #pragma unroll
                for (int nt = 0; nt < 4; ++nt) {
                    const int e = (nh * 4 + nt) * 8 + gid;
                    const int base = e * BS0 + 8 * kt + tig;
                    uint32_t bh0 = vbh[base], bh1 = vbh[base + 4];
                    uint32_t bl0 = vbl[base], bl1 = vbl[base + 4];
                    float* a = acc + nt * 4;
                    const uint32_t* Ah = ahi + kt * 4;
                    const uint32_t* Al = alo + kt * 4;
                    MMA_B16(a, Ah, bh0, bh1);
                    MMA_B16(a, Ah, bl0, bl1);
                    MMA_B16(a, Al, bh0, bh1);
                }
            }
            #pragma unroll
            for (int nt = 0; nt < 4; ++nt) {
                const int e0 = (nh * 4 + nt) * 8 + 2 * tig;
                const int r0 = rbase + gid;
                const float* a = acc + nt * 4;
                *(float2*)(zbuf + r0 * ZSA + e0)       = make_float2(a[0], a[1]);
                *(float2*)(zbuf + (r0 + 8) * ZSA + e0) = make_float2(a[2], a[3]);
            }
        }
        __syncthreads();   // zbuf ready; vbf reads done

        #pragma unroll
        for (int j = 0; j < 16; ++j) {
            const int e = eg * 16 + j;
            const float x0 = xbuf[e * 2], x1 = xbuf[e * 2 + 1];
            float zi = zbuf[u * ZSA + e]         + fmaf(wxi1, x1, fmaf(wxi0, x0, bi));
            float zf = zbuf[(64 + u) * ZSA + e]  + fmaf(wxf1, x1, fmaf(wxf0, x0, bf));
            float zg = zbuf[(128 + u) * ZSA + e] + fmaf(wxg1, x1, fmaf(wxg0, x0, bg));
            float zo = zbuf[(192 + u) * ZSA + e] + fmaf(wxo1, x1, fmaf(wxo0, x0, bo));
            float cn = sigf(zf) * c[j] + sigf(zi) * tanhf_(zg);
            c[j] = cn;
            float hn = sigf(zo) * tanhf_(cn);
            vsh[e * HS + u] = hn;                        // fp32 for out-proj
            float hp = __shfl_xor_sync(0xffffffffu, hn, 1);
            if ((u & 1) == 0) {                          // bf16 for next GEMM
                uint32_t hh = pk_bf2(hn, hp);
                vbh[e * BS0 + (u >> 1)] = hh;
                vbl[e * BS0 + (u >> 1)] = pk_bf2(hn - bf_lo(hh), hp - bf_hi(hh));
            }
        }
        __syncthreads();   // h(t) ready (vsh + vbf); xbuf/zbuf reads done

        // Out-projection + feedback (threads 0..255: e = tid>>1, od = tid&1)
        if (tid < 2 * D_EPB) {
            const int e = tid >> 1, od = tid & 1;
            float o = ob[od];
            #pragma unroll
            for (int k4 = 0; k4 < 16; ++k4) {
                float4 hh = *(const float4*)(vsh + e * HS + k4 * 4);
                float4 w  = *(const float4*)(ow + od * 64 + k4 * 4);
                o += w.x * hh.x + w.y * hh.y + w.z * hh.z + w.w * hh.w;
            }
            out[(blockBase + e) * (PRED * 2) + t * 2 + od] = o;
            xbuf[e * 2 + od] = o;
        }
        __syncthreads();   // xbuf(t+1) ready before next epilogue
    }
}

// ---------------------------------------------------------------------------
extern "C" void kernel_launch(void* const* d_in, const int* in_sizes, int n_in,
                              void* d_out, int out_size)
{
    const float* obs     = (const float*)d_in[0];
    const float* w_ih_l0 = (const float*)d_in[1];
    const float* w_hh_l0 = (const float*)d_in[2];
    const float* b_ih_l0 = (const float*)d_in[3];
    const float* b_hh_l0 = (const float*)d_in[4];
    const float* w_ih_l1 = (const float*)d_in[5];
    const float* w_hh_l1 = (const float*)d_in[6];
    const float* b_ih_l1 = (const float*)d_in[7];
    const float* b_hh_l1 = (const float*)d_in[8];
    const float* dec_w_ih = (const float*)d_in[9];
    const float* dec_w_hh = (const float*)d_in[10];
    const float* dec_b_ih = (const float*)d_in[11];
    const float* dec_b_hh = (const float*)d_in[12];
    const float* out_w   = (const float*)d_in[13];
    const float* out_b   = (const float*)d_in[14];
    float* out = (float*)d_out;

    const int B = in_sizes[0] / (OBS * 2);

    cudaFuncSetAttribute(k_layer0,  cudaFuncAttributeMaxDynamicSharedMemorySize, L0_SMEM);
    cudaFuncSetAttribute(k_layer1,  cudaFuncAttributeMaxDynamicSharedMemorySize, K2_SMEM);
    cudaFuncSetAttribute(k_decoder, cudaFuncAttributeMaxDynamicSharedMemorySize, D_SMEM);

    k_layer0<<<B / L0_EPB, TPB, L0_SMEM>>>(obs, w_ih_l0, w_hh_l0, b_ih_l0, b_hh_l0, B);
    k_layer1<<<B / K2_EPB, TPB, K2_SMEM>>>(w_ih_l1, w_hh_l1, b_ih_l1, b_hh_l1, B);
    k_decoder<<<B / D_EPB, TPB, D_SMEM>>>(obs, dec_w_ih, dec_w_hh, dec_b_ih, dec_b_hh,
                                          out_w, out_b, out, B);
}

// round 16
// speedup vs baseline: 2.6676x; 1.0202x over previous
#include <cuda_runtime.h>
#include <cstdint>

// Problem constants
static constexpr int HID  = 64;
static constexpr int OBS  = 20;
static constexpr int PRED = 12;
static constexpr int BMAX = 32768;

static constexpr int TPB = 512;   // 16 warps: 16 M-rows per warp

// Scratch (allocation-free rule: __device__ globals)
// layer0 hidden states stored PRE-CONVERTED as bf16 hi/lo pairs (u32 each)
__device__ uint32_t g_hs1h[(size_t)OBS * BMAX * 32];
__device__ uint32_t g_hs1l[(size_t)OBS * BMAX * 32];
__device__ float g_h1[(size_t)BMAX * HID];
__device__ float g_c1[(size_t)BMAX * HID];

__device__ __forceinline__ float sigf(float x) {
    return __fdividef(1.0f, 1.0f + __expf(-x));
}
__device__ __forceinline__ float tanhf_(float x) {
    return fmaf(2.0f, sigf(2.0f * x), -1.0f);
}

// bf16x2 pack: low 16 bits = lo value, high 16 bits = hi value
__device__ __forceinline__ uint32_t pk_bf2(float lo, float hi) {
    uint32_t r;
    asm("cvt.rn.bf16x2.f32 %0, %1, %2;" : "=r"(r) : "f"(hi), "f"(lo));
    return r;
}
__device__ __forceinline__ float bf_lo(uint32_t p) { return __uint_as_float(p << 16); }
__device__ __forceinline__ float bf_hi(uint32_t p) { return __uint_as_float(p & 0xffff0000u); }

#define MMA_B16(c, a, b0, b1) \
    asm volatile("mma.sync.aligned.m16n8k16.row.col.f32.bf16.bf16.f32 " \
        "{%0,%1,%2,%3}, {%4,%5,%6,%7}, {%8,%9}, {%0,%1,%2,%3};" \
        : "+f"((c)[0]), "+f"((c)[1]), "+f"((c)[2]), "+f"((c)[3]) \
        : "r"((a)[0]), "r"((a)[1]), "r"((a)[2]), "r"((a)[3]), "r"(b0), "r"(b1))

static constexpr int HS  = 68;    // fp32 h stride (decoder vsh)
static constexpr int BS0 = 36;    // bf16x2 stride, 32 k-pairs (≡4 mod 32; 16B-aligned rows)
static constexpr int BS1 = 68;    // bf16x2 stride, 64 k-pairs (layer1)
static constexpr int ZSA = 130;   // zbuf stride, EPB=128

// ===========================================================================
// Kernel 1: encoder layer 0. EPB=128, bf16 end-to-end; VECTORIZED bf16 stores.
// ===========================================================================
static constexpr int L0_EPB = 128;
static constexpr int L0_BH  = 0;
static constexpr int L0_BL  = L0_BH + L0_EPB * BS0;
static constexpr int L0_Z   = L0_BL + L0_EPB * BS0;
static constexpr int L0_OBS = L0_Z + 256 * ZSA;
static constexpr int L0_SMEM = (L0_OBS + L0_EPB * 40) * 4;

__global__ void __launch_bounds__(TPB, 1) k_layer0(
    const float* __restrict__ obs, const float* __restrict__ wih,
    const float* __restrict__ whh, const float* __restrict__ bih,
    const float* __restrict__ bhh, int B)
{
    extern __shared__ float sm[];
    uint32_t* vbh   = (uint32_t*)(sm + L0_BH);
    uint32_t* vbl   = (uint32_t*)(sm + L0_BL);
    float*    zbuf  = sm + L0_Z;
    float*    obs_s = sm + L0_OBS;

    const int tid = threadIdx.x;
    const size_t blockBase = (size_t)blockIdx.x * L0_EPB;
    const int warp = tid >> 5;
    const int gid  = (tid & 31) >> 2;
    const int tig  = tid & 3;
    const int rbase = warp * 16;

    uint32_t ahi[16], alo[16];
    #pragma unroll
    for (int kt = 0; kt < 4; ++kt)
    #pragma unroll
    for (int j = 0; j < 4; ++j) {
        int row = rbase + gid + (j & 1) * 8;
        int col = 16 * kt + 2 * tig + (j >> 1) * 8;
        float f0 = whh[row * 64 + col], f1 = whh[row * 64 + col + 1];
        uint32_t h = pk_bf2(f0, f1);
        uint32_t l = pk_bf2(f0 - bf_lo(h), f1 - bf_hi(h));
        ahi[kt * 4 + j] = h;
        alo[kt * 4 + j] = l;
    }

    const int u  = tid & 63;
    const int eg = tid >> 6;
    const float wxi0 = wih[2*u],           wxi1 = wih[2*u+1];
    const float wxf0 = wih[2*(64+u)],      wxf1 = wih[2*(64+u)+1];
    const float wxg0 = wih[2*(128+u)],     wxg1 = wih[2*(128+u)+1];
    const float wxo0 = wih[2*(192+u)],     wxo1 = wih[2*(192+u)+1];
    const float bi = bih[u]       + bhh[u];
    const float bf = bih[64+u]    + bhh[64+u];
    const float bg = bih[128+u]   + bhh[128+u];
    const float bo = bih[192+u]   + bhh[192+u];

    for (int i = tid; i < L0_EPB * 32; i += TPB) {
        int e = i >> 5, kp = i & 31;
        vbh[e * BS0 + kp] = 0u;
        vbl[e * BS0 + kp] = 0u;
    }
    for (int i = tid; i < L0_EPB * 40; i += TPB) {
        int ee = i / 40, j = i % 40;
        obs_s[i] = obs[(blockBase + ee) * 40 + j];
    }

    float c[16];
    #pragma unroll
    for (int j = 0; j < 16; ++j) c[j] = 0.f;

    #pragma unroll 1
    for (int t = 0; t < OBS; ++t) {
        __syncthreads();   // epilogue bf16 h(t-1) visible; zbuf free
        if (t > 0) {       // VECTORIZED store of pre-converted h(t-1)
            const size_t gb = ((size_t)(t - 1) * B + blockBase) * 32;
            for (int i = tid; i < L0_EPB * 8; i += TPB) {
                int e = i >> 3, q = (i & 7) * 4;
                *(uint4*)(g_hs1h + gb + (size_t)e * 32 + q) = *(const uint4*)(vbh + e * BS0 + q);
                *(uint4*)(g_hs1l + gb + (size_t)e * 32 + q) = *(const uint4*)(vbl + e * BS0 + q);
            }
        }

        #pragma unroll 1
        for (int nh = 0; nh < 4; ++nh) {
            float acc[16];
            #pragma unroll
            for (int i = 0; i < 16; ++i) acc[i] = 0.f;
            #pragma unroll
            for (int kt = 0; kt < 4; ++kt) {
                #pragma unroll
                for (int nt = 0; nt < 4; ++nt) {
                    const int e = (nh * 4 + nt) * 8 + gid;
                    const int base = e * BS0 + 8 * kt + tig;
                    uint32_t bh0 = vbh[base], bh1 = vbh[base + 4];
                    uint32_t bl0 = vbl[base], bl1 = vbl[base + 4];
                    float* a = acc + nt * 4;
                    const uint32_t* Ah = ahi + kt * 4;
                    const uint32_t* Al = alo + kt * 4;
                    MMA_B16(a, Ah, bh0, bh1);
                    MMA_B16(a, Ah, bl0, bl1);
                    MMA_B16(a, Al, bh0, bh1);
                }
            }
            #pragma unroll
            for (int nt = 0; nt < 4; ++nt) {
                const int e0 = (nh * 4 + nt) * 8 + 2 * tig;
                const int r0 = rbase + gid;
                const float* a = acc + nt * 4;
                *(float2*)(zbuf + r0 * ZSA + e0)       = make_float2(a[0], a[1]);
                *(float2*)(zbuf + (r0 + 8) * ZSA + e0) = make_float2(a[2], a[3]);
            }
        }
        __syncthreads();   // zbuf ready; vbf reads (GEMM + store) done

        #pragma unroll
        for (int j = 0; j < 16; ++j) {
            const int e = eg * 16 + j;
            const float x0 = obs_s[e * 40 + 2 * t], x1 = obs_s[e * 40 + 2 * t + 1];
            float zi = zbuf[u * ZSA + e]         + fmaf(wxi1, x1, fmaf(wxi0, x0, bi));
            float zf = zbuf[(64 + u) * ZSA + e]  + fmaf(wxf1, x1, fmaf(wxf0, x0, bf));
            float zg = zbuf[(128 + u) * ZSA + e] + fmaf(wxg1, x1, fmaf(wxg0, x0, bg));
            float zo = zbuf[(192 + u) * ZSA + e] + fmaf(wxo1, x1, fmaf(wxo0, x0, bo));
            float cn = sigf(zf) * c[j] + sigf(zi) * tanhf_(zg);
            c[j] = cn;
            float hn = sigf(zo) * tanhf_(cn);
            float hp = __shfl_xor_sync(0xffffffffu, hn, 1);   // partner = u^1
            if ((u & 1) == 0) {
                uint32_t hh = pk_bf2(hn, hp);
                vbh[e * BS0 + (u >> 1)] = hh;
                vbl[e * BS0 + (u >> 1)] = pk_bf2(hn - bf_lo(hh), hp - bf_hi(hh));
            }
        }
    }
    __syncthreads();
    {
        const size_t gb = ((size_t)(OBS - 1) * B + blockBase) * 32;
        for (int i = tid; i < L0_EPB * 8; i += TPB) {
            int e = i >> 3, q = (i & 7) * 4;
            *(uint4*)(g_hs1h + gb + (size_t)e * 32 + q) = *(const uint4*)(vbh + e * BS0 + q);
            *(uint4*)(g_hs1l + gb + (size_t)e * 32 + q) = *(const uint4*)(vbl + e * BS0 + q);
        }
    }
}

// ===========================================================================
// Kernel 2: layer 1. EPB=128; VECTORIZED x-copy of pre-converted bf16.
// ===========================================================================
static constexpr int K2_EPB = 128;
static constexpr int K2_BH  = 0;
static constexpr int K2_BL  = K2_BH + K2_EPB * BS1;
static constexpr int K2_Z   = K2_BL + K2_EPB * BS1;
static constexpr int K2_B   = K2_Z + 256 * ZSA;
static constexpr int K2_SMEM = (K2_B + 256) * 4;

__global__ void __launch_bounds__(TPB, 1) k_layer1(
    const float* __restrict__ wih, const float* __restrict__ whh,
    const float* __restrict__ bih, const float* __restrict__ bhh, int B)
{
    extern __shared__ float sm[];
    uint32_t* vbh  = (uint32_t*)(sm + K2_BH);
    uint32_t* vbl  = (uint32_t*)(sm + K2_BL);
    float*    zbuf = sm + K2_Z;
    float*    bs   = sm + K2_B;

    const int tid = threadIdx.x;
    const size_t blockBase = (size_t)blockIdx.x * K2_EPB;
    const int warp = tid >> 5;
    const int gid  = (tid & 31) >> 2;
    const int tig  = tid & 3;
    const int rbase = warp * 16;

    uint32_t ahi[32], alo[32];
    #pragma unroll
    for (int kt = 0; kt < 8; ++kt)
    #pragma unroll
    for (int j = 0; j < 4; ++j) {
        int row = rbase + gid + (j & 1) * 8;
        int col = 16 * kt + 2 * tig + (j >> 1) * 8;
        const float* src = (col < 64) ? (wih + row * 64 + col)
                                      : (whh + row * 64 + (col - 64));
        float f0 = src[0], f1 = src[1];
        uint32_t h = pk_bf2(f0, f1);
        uint32_t l = pk_bf2(f0 - bf_lo(h), f1 - bf_hi(h));
        ahi[kt * 4 + j] = h;
        alo[kt * 4 + j] = l;
    }

    for (int i = tid; i < 256; i += TPB) bs[i] = bih[i] + bhh[i];
    for (int i = tid; i < K2_EPB * 32; i += TPB) {   // h0 = 0 (k-pairs 32..63)
        int e = i >> 5, kp = i & 31;
        vbh[e * BS1 + 32 + kp] = 0u;
        vbl[e * BS1 + 32 + kp] = 0u;
    }

    const int u  = tid & 63;
    const int eg = tid >> 6;
    float c[16];
    #pragma unroll
    for (int j = 0; j < 16; ++j) c[j] = 0.f;

    #pragma unroll 1
    for (int t = 0; t < OBS; ++t) {
        __syncthreads();   // epilogue h-writes visible; x k-pairs free
        {   // x: VECTORIZED copy of pre-converted bf16 hi/lo (k-pairs 0..31)
            const size_t gb = ((size_t)t * B + blockBase) * 32;
            for (int i = tid; i < K2_EPB * 8; i += TPB) {
                int e = i >> 3, q = (i & 7) * 4;
                *(uint4*)(vbh + e * BS1 + q) = *(const uint4*)(g_hs1h + gb + (size_t)e * 32 + q);
                *(uint4*)(vbl + e * BS1 + q) = *(const uint4*)(g_hs1l + gb + (size_t)e * 32 + q);
            }
        }
        __syncthreads();   // full v ready

        #pragma unroll 1
        for (int nh = 0; nh < 4; ++nh) {
            float acc[16];
            #pragma unroll
            for (int i = 0; i < 16; ++i) acc[i] = 0.f;

            #pragma unroll
            for (int kt = 0; kt < 8; ++kt) {
                #pragma unroll
                for (int nt = 0; nt < 4; ++nt) {
                    const int e = (nh * 4 + nt) * 8 + gid;
                    const int base = e * BS1 + 8 * kt + tig;
                    uint32_t bh0 = vbh[base], bh1 = vbh[base + 4];
                    uint32_t bl0 = vbl[base], bl1 = vbl[base + 4];
                    float* a = acc + nt * 4;
                    const uint32_t* Ah = ahi + kt * 4;
                    const uint32_t* Al = alo + kt * 4;
                    MMA_B16(a, Ah, bh0, bh1);
                    MMA_B16(a, Ah, bl0, bl1);
                    MMA_B16(a, Al, bh0, bh1);
                }
            }
            #pragma unroll
            for (int nt = 0; nt < 4; ++nt) {
                const int e0 = (nh * 4 + nt) * 8 + 2 * tig;
                const int r0 = rbase + gid;
                const float* a = acc + nt * 4;
                *(float2*)(zbuf + r0 * ZSA + e0)       = make_float2(a[0], a[1]);
                *(float2*)(zbuf + (r0 + 8) * ZSA + e0) = make_float2(a[2], a[3]);
            }
        }
        __syncthreads();   // zbuf ready; all vbf reads done

        const bool last = (t == OBS - 1);
        #pragma unroll
        for (int j = 0; j < 16; ++j) {
            const int e = eg * 16 + j;
            float zi = zbuf[u * ZSA + e]          + bs[u];
            float zf = zbuf[(64 + u) * ZSA + e]   + bs[64 + u];
            float zg = zbuf[(128 + u) * ZSA + e]  + bs[128 + u];
            float zo = zbuf[(192 + u) * ZSA + e]  + bs[192 + u];
            float cn = sigf(zf) * c[j] + sigf(zi) * tanhf_(zg);
            c[j] = cn;
            float hn = sigf(zo) * tanhf_(cn);
            float hp = __shfl_xor_sync(0xffffffffu, hn, 1);
            if ((u & 1) == 0) {
                uint32_t hh = pk_bf2(hn, hp);
                vbh[e * BS1 + 32 + (u >> 1)] = hh;
                vbl[e * BS1 + 32 + (u >> 1)] = pk_bf2(hn - bf_lo(hh), hp - bf_hi(hh));
            }
            if (last) {
                g_h1[(blockBase + e) * HID + u] = hn;
                g_c1[(blockBase + e) * HID + u] = cn;
            }
        }
    }
}

// ===========================================================================
// Kernel 3: decoder — VERBATIM round 15 (EPB=128, bf16 B + fp32 vsh for proj).
// ===========================================================================
static constexpr int D_EPB = 128;
static constexpr int D_V  = 0;
static constexpr int D_BH = D_EPB * HS;
static constexpr int D_BL = D_BH + D_EPB * BS0;
static constexpr int D_Z  = D_BL + D_EPB * BS0;
static constexpr int D_OW = D_Z + 256 * ZSA;
static constexpr int D_OB = D_OW + 128;
static constexpr int D_X  = D_OB + 2;
static constexpr int D_SMEM = (D_X + 256) * 4;

__global__ void __launch_bounds__(TPB, 1) k_decoder(
    const float* __restrict__ obs, const float* __restrict__ wih,
    const float* __restrict__ whh, const float* __restrict__ bih,
    const float* __restrict__ bhh, const float* __restrict__ outw,
    const float* __restrict__ outb, float* __restrict__ out, int B)
{
    extern __shared__ float sm[];
    float*    vsh  = sm + D_V;
    uint32_t* vbh  = (uint32_t*)(sm + D_BH);
    uint32_t* vbl  = (uint32_t*)(sm + D_BL);
    float*    zbuf = sm + D_Z;
    float*    ow   = sm + D_OW;
    float*    ob   = sm + D_OB;
    float*    xbuf = sm + D_X;

    const int tid = threadIdx.x;
    const size_t blockBase = (size_t)blockIdx.x * D_EPB;
    const int warp = tid >> 5;
    const int gid  = (tid & 31) >> 2;
    const int tig  = tid & 3;
    const int rbase = warp * 16;

    uint32_t ahi[16], alo[16];
    #pragma unroll
    for (int kt = 0; kt < 4; ++kt)
    #pragma unroll
    for (int j = 0; j < 4; ++j) {
        int row = rbase + gid + (j & 1) * 8;
        int col = 16 * kt + 2 * tig + (j >> 1) * 8;
        float f0 = whh[row * 64 + col], f1 = whh[row * 64 + col + 1];
        uint32_t h = pk_bf2(f0, f1);
        uint32_t l = pk_bf2(f0 - bf_lo(h), f1 - bf_hi(h));
        ahi[kt * 4 + j] = h;
        alo[kt * 4 + j] = l;
    }

    const int u  = tid & 63;
    const int eg = tid >> 6;
    const float wxi0 = wih[2*u],           wxi1 = wih[2*u+1];
    const float wxf0 = wih[2*(64+u)],      wxf1 = wih[2*(64+u)+1];
    const float wxg0 = wih[2*(128+u)],     wxg1 = wih[2*(128+u)+1];
    const float wxo0 = wih[2*(192+u)],     wxo1 = wih[2*(192+u)+1];
    const float bi = bih[u]       + bhh[u];
    const float bf = bih[64+u]    + bhh[64+u];
    const float bg = bih[128+u]   + bhh[128+u];
    const float bo = bih[192+u]   + bhh[192+u];

    for (int i = tid; i < 128; i += TPB) ow[i] = outw[i];
    if (tid < 2) ob[tid] = outb[tid];
    {
        const float4* src = (const float4*)(g_h1 + blockBase * HID);
        for (int i = tid; i < D_EPB * 16; i += TPB) {
            int ee = i >> 4, k4 = i & 15;
            float4 v = src[i];
            *(float4*)(vsh + ee * HS + k4 * 4) = v;
            uint32_t h0 = pk_bf2(v.x, v.y), h1 = pk_bf2(v.z, v.w);
            vbh[ee * BS0 + 2 * k4]     = h0;
            vbh[ee * BS0 + 2 * k4 + 1] = h1;
            vbl[ee * BS0 + 2 * k4]     = pk_bf2(v.x - bf_lo(h0), v.y - bf_hi(h0));
            vbl[ee * BS0 + 2 * k4 + 1] = pk_bf2(v.z - bf_lo(h1), v.w - bf_hi(h1));
        }
        for (int i = tid; i < D_EPB * 2; i += TPB) {
            int ee = i >> 1, j = i & 1;
            xbuf[i] = obs[(blockBase + ee) * 40 + 38 + j];
        }
    }
    float c[16];
    #pragma unroll
    for (int j = 0; j < 16; ++j)
        c[j] = g_c1[(blockBase + eg * 16 + j) * HID + u];
    __syncthreads();

    #pragma unroll 1
    for (int t = 0; t < PRED; ++t) {
        #pragma unroll 1
        for (int nh = 0; nh < 4; ++nh) {
            float acc[16];
            #pragma unroll
            for (int i = 0; i < 16; ++i) acc[i] = 0.f;
            #pragma unroll
            for (int kt = 0; kt < 4; ++kt) {
                #pragma unroll
                for (int nt = 0; nt < 4; ++nt) {
                    const int e = (nh * 4 + nt) * 8 + gid;
                    const int base = e * BS0 + 8 * kt + tig;
                    uint32_t bh0 = vbh[base], bh1 = vbh[base + 4];
                    uint32_t bl0 = vbl[base], bl1 = vbl[base + 4];
                    float* a = acc + nt * 4;
                    const uint32_t* Ah = ahi + kt * 4;
                    const uint32_t* Al = alo + kt * 4;
                    MMA_B16(a, Ah, bh0, bh1);
                    MMA_B16(a, Ah, bl0, bl1);
                    MMA_B16(a, Al, bh0, bh1);
                }
            }
            #pragma unroll
            for (int nt = 0; nt < 4; ++nt) {
                const int e0 = (nh * 4 + nt) * 8 + 2 * tig;
                const int r0 = rbase + gid;
                const float* a = acc + nt * 4;
                *(float2*)(zbuf + r0 * ZSA + e0)       = make_float2(a[0], a[1]);
                *(float2*)(zbuf + (r0 + 8) * ZSA + e0) = make_float2(a[2], a[3]);
            }
        }
        __syncthreads();

        #pragma unroll
        for (int j = 0; j < 16; ++j) {
            const int e = eg * 16 + j;
            const float x0 = xbuf[e * 2], x1 = xbuf[e * 2 + 1];
            float zi = zbuf[u * ZSA + e]         + fmaf(wxi1, x1, fmaf(wxi0, x0, bi));
            float zf = zbuf[(64 + u) * ZSA + e]  + fmaf(wxf1, x1, fmaf(wxf0, x0, bf));
            float zg = zbuf[(128 + u) * ZSA + e] + fmaf(wxg1, x1, fmaf(wxg0, x0, bg));
            float zo = zbuf[(192 + u) * ZSA + e] + fmaf(wxo1, x1, fmaf(wxo0, x0, bo));
            float cn = sigf(zf) * c[j] + sigf(zi) * tanhf_(zg);
            c[j] = cn;
            float hn = sigf(zo) * tanhf_(cn);
            vsh[e * HS + u] = hn;
            float hp = __shfl_xor_sync(0xffffffffu, hn, 1);
            if ((u & 1) == 0) {
                uint32_t hh = pk_bf2(hn, hp);
                vbh[e * BS0 + (u >> 1)] = hh;
                vbl[e * BS0 + (u >> 1)] = pk_bf2(hn - bf_lo(hh), hp - bf_hi(hh));
            }
        }
        __syncthreads();

        if (tid < 2 * D_EPB) {
            const int e = tid >> 1, od = tid & 1;
            float o = ob[od];
            #pragma unroll
            for (int k4 = 0; k4 < 16; ++k4) {
                float4 hh = *(const float4*)(vsh + e * HS + k4 * 4);
                float4 w  = *(const float4*)(ow + od * 64 + k4 * 4);
                o += w.x * hh.x + w.y * hh.y + w.z * hh.z + w.w * hh.w;
            }
            out[(blockBase + e) * (PRED * 2) + t * 2 + od] = o;
            xbuf[e * 2 + od] = o;
        }
        __syncthreads();
    }
}

// ---------------------------------------------------------------------------
extern "C" void kernel_launch(void* const* d_in, const int* in_sizes, int n_in,
                              void* d_out, int out_size)
{
    const float* obs     = (const float*)d_in[0];
    const float* w_ih_l0 = (const float*)d_in[1];
    const float* w_hh_l0 = (const float*)d_in[2];
    const float* b_ih_l0 = (const float*)d_in[3];
    const float* b_hh_l0 = (const float*)d_in[4];
    const float* w_ih_l1 = (const float*)d_in[5];
    const float* w_hh_l1 = (const float*)d_in[6];
    const float* b_ih_l1 = (const float*)d_in[7];
    const float* b_hh_l1 = (const float*)d_in[8];
    const float* dec_w_ih = (const float*)d_in[9];
    const float* dec_w_hh = (const float*)d_in[10];
    const float* dec_b_ih = (const float*)d_in[11];
    const float* dec_b_hh = (const float*)d_in[12];
    const float* out_w   = (const float*)d_in[13];
    const float* out_b   = (const float*)d_in[14];
    float* out = (float*)d_out;

    const int B = in_sizes[0] / (OBS * 2);

    cudaFuncSetAttribute(k_layer0,  cudaFuncAttributeMaxDynamicSharedMemorySize, L0_SMEM);
    cudaFuncSetAttribute(k_layer1,  cudaFuncAttributeMaxDynamicSharedMemorySize, K2_SMEM);
    cudaFuncSetAttribute(k_decoder, cudaFuncAttributeMaxDynamicSharedMemorySize, D_SMEM);

    k_layer0<<<B / L0_EPB, TPB, L0_SMEM>>>(obs, w_ih_l0, w_hh_l0, b_ih_l0, b_hh_l0, B);
    k_layer1<<<B / K2_EPB, TPB, K2_SMEM>>>(w_ih_l1, w_hh_l1, b_ih_l1, b_hh_l1, B);
    k_decoder<<<B / D_EPB, TPB, D_SMEM>>>(obs, dec_w_ih, dec_w_hh, dec_b_ih, dec_b_hh,
                                          out_w, out_b, out, B);
}

// round 17
// speedup vs baseline: 2.6950x; 1.0103x over previous
#include <cuda_runtime.h>
#include <cstdint>

// Problem constants
static constexpr int HID  = 64;
static constexpr int OBS  = 20;
static constexpr int PRED = 12;
static constexpr int BMAX = 32768;

static constexpr int TPB = 512;   // 16 warps: 16 M-rows per warp

// Scratch (allocation-free rule: __device__ globals)
__device__ uint32_t g_hs1h[(size_t)OBS * BMAX * 32];
__device__ uint32_t g_hs1l[(size_t)OBS * BMAX * 32];
__device__ float g_h1[(size_t)BMAX * HID];
__device__ float g_c1[(size_t)BMAX * HID];

__device__ __forceinline__ float sigf(float x) {
    return __fdividef(1.0f, 1.0f + __expf(-x));
}
__device__ __forceinline__ float tanhf_(float x) {
    return fmaf(2.0f, sigf(2.0f * x), -1.0f);
}

__device__ __forceinline__ uint32_t pk_bf2(float lo, float hi) {
    uint32_t r;
    asm("cvt.rn.bf16x2.f32 %0, %1, %2;" : "=r"(r) : "f"(hi), "f"(lo));
    return r;
}
__device__ __forceinline__ float bf_lo(uint32_t p) { return __uint_as_float(p << 16); }
__device__ __forceinline__ float bf_hi(uint32_t p) { return __uint_as_float(p & 0xffff0000u); }

#define MMA_B16(c, a, b0, b1) \
    asm volatile("mma.sync.aligned.m16n8k16.row.col.f32.bf16.bf16.f32 " \
        "{%0,%1,%2,%3}, {%4,%5,%6,%7}, {%8,%9}, {%0,%1,%2,%3};" \
        : "+f"((c)[0]), "+f"((c)[1]), "+f"((c)[2]), "+f"((c)[3]) \
        : "r"((a)[0]), "r"((a)[1]), "r"((a)[2]), "r"((a)[3]), "r"(b0), "r"(b1))

static constexpr int HS  = 68;    // fp32 h stride
static constexpr int BS0 = 36;    // bf16x2 stride, 32 k-pairs
static constexpr int BS1 = 68;    // bf16x2 stride, 64 k-pairs (layer1)
static constexpr int ZSA = 130;   // zbuf stride, EPB=128

// ===========================================================================
// Kernel 1: encoder layer 0. EPB=128; r13-style phases (no epilogue shfl),
// bf16 global stores from the converted buffer.
// ===========================================================================
static constexpr int L0_EPB = 128;
static constexpr int L0_V   = 0;                          // 128*68 fp32
static constexpr int L0_BH  = L0_EPB * HS;                // 128*36 u32
static constexpr int L0_BL  = L0_BH + L0_EPB * BS0;       // 128*36 u32
static constexpr int L0_Z   = L0_BL + L0_EPB * BS0;       // 256*130 fp32
static constexpr int L0_OBS = L0_Z + 256 * ZSA;           // 128*40 fp32
static constexpr int L0_SMEM = (L0_OBS + L0_EPB * 40) * 4;  // 225,280 B

__global__ void __launch_bounds__(TPB, 1) k_layer0(
    const float* __restrict__ obs, const float* __restrict__ wih,
    const float* __restrict__ whh, const float* __restrict__ bih,
    const float* __restrict__ bhh, int B)
{
    extern __shared__ float sm[];
    float*    vsh   = sm + L0_V;
    uint32_t* vbh   = (uint32_t*)(sm + L0_BH);
    uint32_t* vbl   = (uint32_t*)(sm + L0_BL);
    float*    zbuf  = sm + L0_Z;
    float*    obs_s = sm + L0_OBS;

    const int tid = threadIdx.x;
    const size_t blockBase = (size_t)blockIdx.x * L0_EPB;
    const int warp = tid >> 5;
    const int gid  = (tid & 31) >> 2;
    const int tig  = tid & 3;
    const int rbase = warp * 16;

    uint32_t ahi[16], alo[16];
    #pragma unroll
    for (int kt = 0; kt < 4; ++kt)
    #pragma unroll
    for (int j = 0; j < 4; ++j) {
        int row = rbase + gid + (j & 1) * 8;
        int col = 16 * kt + 2 * tig + (j >> 1) * 8;
        float f0 = whh[row * 64 + col], f1 = whh[row * 64 + col + 1];
        uint32_t h = pk_bf2(f0, f1);
        uint32_t l = pk_bf2(f0 - bf_lo(h), f1 - bf_hi(h));
        ahi[kt * 4 + j] = h;
        alo[kt * 4 + j] = l;
    }

    const int u  = tid & 63;
    const int eg = tid >> 6;
    const float wxi0 = wih[2*u],           wxi1 = wih[2*u+1];
    const float wxf0 = wih[2*(64+u)],      wxf1 = wih[2*(64+u)+1];
    const float wxg0 = wih[2*(128+u)],     wxg1 = wih[2*(128+u)+1];
    const float wxo0 = wih[2*(192+u)],     wxo1 = wih[2*(192+u)+1];
    const float bi = bih[u]       + bhh[u];
    const float bf = bih[64+u]    + bhh[64+u];
    const float bg = bih[128+u]   + bhh[128+u];
    const float bo = bih[192+u]   + bhh[192+u];

    for (int i = tid; i < L0_EPB * HS; i += TPB) vsh[i] = 0.f;   // h0 = 0
    for (int i = tid; i < L0_EPB * 40; i += TPB) {
        int ee = i / 40, j = i % 40;
        obs_s[i] = obs[(blockBase + ee) * 40 + j];
    }

    float c[16];
    #pragma unroll
    for (int j = 0; j < 16; ++j) c[j] = 0.f;

    #pragma unroll 1
    for (int t = 0; t < OBS; ++t) {
        __syncthreads();   // epilogue fp32 h(t-1) visible; vbf free
        // Convert h(t-1) fp32 -> bf16 hi/lo (cooperative, off critical path)
        for (int i = tid; i < L0_EPB * 32; i += TPB) {
            int e = i >> 5, kp = i & 31;
            float2 p = *(const float2*)(vsh + e * HS + 2 * kp);
            uint32_t h = pk_bf2(p.x, p.y);
            vbh[e * BS0 + kp] = h;
            vbl[e * BS0 + kp] = pk_bf2(p.x - bf_lo(h), p.y - bf_hi(h));
        }
        __syncthreads();   // vbf ready
        if (t > 0) {       // vectorized bf16 store of h(t-1)
            const size_t gb = ((size_t)(t - 1) * B + blockBase) * 32;
            for (int i = tid; i < L0_EPB * 8; i += TPB) {
                int e = i >> 3, q = (i & 7) * 4;
                *(uint4*)(g_hs1h + gb + (size_t)e * 32 + q) = *(const uint4*)(vbh + e * BS0 + q);
                *(uint4*)(g_hs1l + gb + (size_t)e * 32 + q) = *(const uint4*)(vbl + e * BS0 + q);
            }
        }

        #pragma unroll 1
        for (int nh = 0; nh < 4; ++nh) {
            float acc[16];
            #pragma unroll
            for (int i = 0; i < 16; ++i) acc[i] = 0.f;
            #pragma unroll
            for (int kt = 0; kt < 4; ++kt) {
                #pragma unroll
                for (int nt = 0; nt < 4; ++nt) {
                    const int e = (nh * 4 + nt) * 8 + gid;
                    const int base = e * BS0 + 8 * kt + tig;
                    uint32_t bh0 = vbh[base], bh1 = vbh[base + 4];
                    uint32_t bl0 = vbl[base], bl1 = vbl[base + 4];
                    float* a = acc + nt * 4;
                    const uint32_t* Ah = ahi + kt * 4;
                    const uint32_t* Al = alo + kt * 4;
                    MMA_B16(a, Ah, bh0, bh1);
                    MMA_B16(a, Ah, bl0, bl1);
                    MMA_B16(a, Al, bh0, bh1);
                }
            }
            #pragma unroll
            for (int nt = 0; nt < 4; ++nt) {
                const int e0 = (nh * 4 + nt) * 8 + 2 * tig;
                const int r0 = rbase + gid;
                const float* a = acc + nt * 4;
                *(float2*)(zbuf + r0 * ZSA + e0)       = make_float2(a[0], a[1]);
                *(float2*)(zbuf + (r0 + 8) * ZSA + e0) = make_float2(a[2], a[3]);
            }
        }
        __syncthreads();   // zbuf ready; vsh/vbf reads done

        #pragma unroll
        for (int j = 0; j < 16; ++j) {
            const int e = eg * 16 + j;
            const float x0 = obs_s[e * 40 + 2 * t], x1 = obs_s[e * 40 + 2 * t + 1];
            float zi = zbuf[u * ZSA + e]         + fmaf(wxi1, x1, fmaf(wxi0, x0, bi));
            float zf = zbuf[(64 + u) * ZSA + e]  + fmaf(wxf1, x1, fmaf(wxf0, x0, bf));
            float zg = zbuf[(128 + u) * ZSA + e] + fmaf(wxg1, x1, fmaf(wxg0, x0, bg));
            float zo = zbuf[(192 + u) * ZSA + e] + fmaf(wxo1, x1, fmaf(wxo0, x0, bo));
            float cn = sigf(zf) * c[j] + sigf(zi) * tanhf_(zg);
            c[j] = cn;
            vsh[e * HS + u] = sigf(zo) * tanhf_(cn);
        }
    }
    __syncthreads();
    // final: convert + store h(OBS-1)
    for (int i = tid; i < L0_EPB * 32; i += TPB) {
        int e = i >> 5, kp = i & 31;
        float2 p = *(const float2*)(vsh + e * HS + 2 * kp);
        uint32_t h = pk_bf2(p.x, p.y);
        vbh[e * BS0 + kp] = h;
        vbl[e * BS0 + kp] = pk_bf2(p.x - bf_lo(h), p.y - bf_hi(h));
    }
    __syncthreads();
    {
        const size_t gb = ((size_t)(OBS - 1) * B + blockBase) * 32;
        for (int i = tid; i < L0_EPB * 8; i += TPB) {
            int e = i >> 3, q = (i & 7) * 4;
            *(uint4*)(g_hs1h + gb + (size_t)e * 32 + q) = *(const uint4*)(vbh + e * BS0 + q);
            *(uint4*)(g_hs1l + gb + (size_t)e * 32 + q) = *(const uint4*)(vbl + e * BS0 + q);
        }
    }
}

// ===========================================================================
// Kernel 2: layer 1 — VERBATIM round 16 (EPB=128, vectorized pure-copy x).
// ===========================================================================
static constexpr int K2_EPB = 128;
static constexpr int K2_BH  = 0;
static constexpr int K2_BL  = K2_BH + K2_EPB * BS1;
static constexpr int K2_Z   = K2_BL + K2_EPB * BS1;
static constexpr int K2_B   = K2_Z + 256 * ZSA;
static constexpr int K2_SMEM = (K2_B + 256) * 4;

__global__ void __launch_bounds__(TPB, 1) k_layer1(
    const float* __restrict__ wih, const float* __restrict__ whh,
    const float* __restrict__ bih, const float* __restrict__ bhh, int B)
{
    extern __shared__ float sm[];
    uint32_t* vbh  = (uint32_t*)(sm + K2_BH);
    uint32_t* vbl  = (uint32_t*)(sm + K2_BL);
    float*    zbuf = sm + K2_Z;
    float*    bs   = sm + K2_B;

    const int tid = threadIdx.x;
    const size_t blockBase = (size_t)blockIdx.x * K2_EPB;
    const int warp = tid >> 5;
    const int gid  = (tid & 31) >> 2;
    const int tig  = tid & 3;
    const int rbase = warp * 16;

    uint32_t ahi[32], alo[32];
    #pragma unroll
    for (int kt = 0; kt < 8; ++kt)
    #pragma unroll
    for (int j = 0; j < 4; ++j) {
        int row = rbase + gid + (j & 1) * 8;
        int col = 16 * kt + 2 * tig + (j >> 1) * 8;
        const float* src = (col < 64) ? (wih + row * 64 + col)
                                      : (whh + row * 64 + (col - 64));
        float f0 = src[0], f1 = src[1];
        uint32_t h = pk_bf2(f0, f1);
        uint32_t l = pk_bf2(f0 - bf_lo(h), f1 - bf_hi(h));
        ahi[kt * 4 + j] = h;
        alo[kt * 4 + j] = l;
    }

    for (int i = tid; i < 256; i += TPB) bs[i] = bih[i] + bhh[i];
    for (int i = tid; i < K2_EPB * 32; i += TPB) {
        int e = i >> 5, kp = i & 31;
        vbh[e * BS1 + 32 + kp] = 0u;
        vbl[e * BS1 + 32 + kp] = 0u;
    }

    const int u  = tid & 63;
    const int eg = tid >> 6;
    float c[16];
    #pragma unroll
    for (int j = 0; j < 16; ++j) c[j] = 0.f;

    #pragma unroll 1
    for (int t = 0; t < OBS; ++t) {
        __syncthreads();
        {
            const size_t gb = ((size_t)t * B + blockBase) * 32;
            for (int i = tid; i < K2_EPB * 8; i += TPB) {
                int e = i >> 3, q = (i & 7) * 4;
                *(uint4*)(vbh + e * BS1 + q) = *(const uint4*)(g_hs1h + gb + (size_t)e * 32 + q);
                *(uint4*)(vbl + e * BS1 + q) = *(const uint4*)(g_hs1l + gb + (size_t)e * 32 + q);
            }
        }
        __syncthreads();

        #pragma unroll 1
        for (int nh = 0; nh < 4; ++nh) {
            float acc[16];
            #pragma unroll
            for (int i = 0; i < 16; ++i) acc[i] = 0.f;

            #pragma unroll
            for (int kt = 0; kt < 8; ++kt) {
                #pragma unroll
                for (int nt = 0; nt < 4; ++nt) {
                    const int e = (nh * 4 + nt) * 8 + gid;
                    const int base = e * BS1 + 8 * kt + tig;
                    uint32_t bh0 = vbh[base], bh1 = vbh[base + 4];
                    uint32_t bl0 = vbl[base], bl1 = vbl[base + 4];
                    float* a = acc + nt * 4;
                    const uint32_t* Ah = ahi + kt * 4;
                    const uint32_t* Al = alo + kt * 4;
                    MMA_B16(a, Ah, bh0, bh1);
                    MMA_B16(a, Ah, bl0, bl1);
                    MMA_B16(a, Al, bh0, bh1);
                }
            }
            #pragma unroll
            for (int nt = 0; nt < 4; ++nt) {
                const int e0 = (nh * 4 + nt) * 8 + 2 * tig;
                const int r0 = rbase + gid;
                const float* a = acc + nt * 4;
                *(float2*)(zbuf + r0 * ZSA + e0)       = make_float2(a[0], a[1]);
                *(float2*)(zbuf + (r0 + 8) * ZSA + e0) = make_float2(a[2], a[3]);
            }
        }
        __syncthreads();

        const bool last = (t == OBS - 1);
        #pragma unroll
        for (int j = 0; j < 16; ++j) {
            const int e = eg * 16 + j;
            float zi = zbuf[u * ZSA + e]          + bs[u];
            float zf = zbuf[(64 + u) * ZSA + e]   + bs[64 + u];
            float zg = zbuf[(128 + u) * ZSA + e]  + bs[128 + u];
            float zo = zbuf[(192 + u) * ZSA + e]  + bs[192 + u];
            float cn = sigf(zf) * c[j] + sigf(zi) * tanhf_(zg);
            c[j] = cn;
            float hn = sigf(zo) * tanhf_(cn);
            float hp = __shfl_xor_sync(0xffffffffu, hn, 1);
            if ((u & 1) == 0) {
                uint32_t hh = pk_bf2(hn, hp);
                vbh[e * BS1 + 32 + (u >> 1)] = hh;
                vbl[e * BS1 + 32 + (u >> 1)] = pk_bf2(hn - bf_lo(hh), hp - bf_hi(hh));
            }
            if (last) {
                g_h1[(blockBase + e) * HID + u] = hn;
                g_c1[(blockBase + e) * HID + u] = cn;
            }
        }
    }
}

// ===========================================================================
// Kernel 3: decoder. EPB=128; epilogue writes fp32 vsh only; threads 256-511
// convert vsh->vbf during the out-projection phase (no epilogue shfl).
// ===========================================================================
static constexpr int D_EPB = 128;
static constexpr int D_V  = 0;
static constexpr int D_BH = D_EPB * HS;
static constexpr int D_BL = D_BH + D_EPB * BS0;
static constexpr int D_Z  = D_BL + D_EPB * BS0;
static constexpr int D_OW = D_Z + 256 * ZSA;
static constexpr int D_OB = D_OW + 128;
static constexpr int D_X  = D_OB + 2;
static constexpr int D_SMEM = (D_X + 256) * 4;

__global__ void __launch_bounds__(TPB, 1) k_decoder(
    const float* __restrict__ obs, const float* __restrict__ wih,
    const float* __restrict__ whh, const float* __restrict__ bih,
    const float* __restrict__ bhh, const float* __restrict__ outw,
    const float* __restrict__ outb, float* __restrict__ out, int B)
{
    extern __shared__ float sm[];
    float*    vsh  = sm + D_V;
    uint32_t* vbh  = (uint32_t*)(sm + D_BH);
    uint32_t* vbl  = (uint32_t*)(sm + D_BL);
    float*    zbuf = sm + D_Z;
    float*    ow   = sm + D_OW;
    float*    ob   = sm + D_OB;
    float*    xbuf = sm + D_X;

    const int tid = threadIdx.x;
    const size_t blockBase = (size_t)blockIdx.x * D_EPB;
    const int warp = tid >> 5;
    const int gid  = (tid & 31) >> 2;
    const int tig  = tid & 3;
    const int rbase = warp * 16;

    uint32_t ahi[16], alo[16];
    #pragma unroll
    for (int kt = 0; kt < 4; ++kt)
    #pragma unroll
    for (int j = 0; j < 4; ++j) {
        int row = rbase + gid + (j & 1) * 8;
        int col = 16 * kt + 2 * tig + (j >> 1) * 8;
        float f0 = whh[row * 64 + col], f1 = whh[row * 64 + col + 1];
        uint32_t h = pk_bf2(f0, f1);
        uint32_t l = pk_bf2(f0 - bf_lo(h), f1 - bf_hi(h));
        ahi[kt * 4 + j] = h;
        alo[kt * 4 + j] = l;
    }

    const int u  = tid & 63;
    const int eg = tid >> 6;
    const float wxi0 = wih[2*u],           wxi1 = wih[2*u+1];
    const float wxf0 = wih[2*(64+u)],      wxf1 = wih[2*(64+u)+1];
    const float wxg0 = wih[2*(128+u)],     wxg1 = wih[2*(128+u)+1];
    const float wxo0 = wih[2*(192+u)],     wxo1 = wih[2*(192+u)+1];
    const float bi = bih[u]       + bhh[u];
    const float bf = bih[64+u]    + bhh[64+u];
    const float bg = bih[128+u]   + bhh[128+u];
    const float bo = bih[192+u]   + bhh[192+u];

    for (int i = tid; i < 128; i += TPB) ow[i] = outw[i];
    if (tid < 2) ob[tid] = outb[tid];
    {
        const float4* src = (const float4*)(g_h1 + blockBase * HID);
        for (int i = tid; i < D_EPB * 16; i += TPB) {
            int ee = i >> 4, k4 = i & 15;
            float4 v = src[i];
            *(float4*)(vsh + ee * HS + k4 * 4) = v;
            uint32_t h0 = pk_bf2(v.x, v.y), h1 = pk_bf2(v.z, v.w);
            vbh[ee * BS0 + 2 * k4]     = h0;
            vbh[ee * BS0 + 2 * k4 + 1] = h1;
            vbl[ee * BS0 + 2 * k4]     = pk_bf2(v.x - bf_lo(h0), v.y - bf_hi(h0));
            vbl[ee * BS0 + 2 * k4 + 1] = pk_bf2(v.z - bf_lo(h1), v.w - bf_hi(h1));
        }
        for (int i = tid; i < D_EPB * 2; i += TPB) {
            int ee = i >> 1, j = i & 1;
            xbuf[i] = obs[(blockBase + ee) * 40 + 38 + j];
        }
    }
    float c[16];
    #pragma unroll
    for (int j = 0; j < 16; ++j)
        c[j] = g_c1[(blockBase + eg * 16 + j) * HID + u];
    __syncthreads();

    #pragma unroll 1
    for (int t = 0; t < PRED; ++t) {
        #pragma unroll 1
        for (int nh = 0; nh < 4; ++nh) {
            float acc[16];
            #pragma unroll
            for (int i = 0; i < 16; ++i) acc[i] = 0.f;
            #pragma unroll
            for (int kt = 0; kt < 4; ++kt) {
                #pragma unroll
                for (int nt = 0; nt < 4; ++nt) {
                    const int e = (nh * 4 + nt) * 8 + gid;
                    const int base = e * BS0 + 8 * kt + tig;
                    uint32_t bh0 = vbh[base], bh1 = vbh[base + 4];
                    uint32_t bl0 = vbl[base], bl1 = vbl[base + 4];
                    float* a = acc + nt * 4;
                    const uint32_t* Ah = ahi + kt * 4;
                    const uint32_t* Al = alo + kt * 4;
                    MMA_B16(a, Ah, bh0, bh1);
                    MMA_B16(a, Ah, bl0, bl1);
                    MMA_B16(a, Al, bh0, bh1);
                }
            }
            #pragma unroll
            for (int nt = 0; nt < 4; ++nt) {
                const int e0 = (nh * 4 + nt) * 8 + 2 * tig;
                const int r0 = rbase + gid;
                const float* a = acc + nt * 4;
                *(float2*)(zbuf + r0 * ZSA + e0)       = make_float2(a[0], a[1]);
                *(float2*)(zbuf + (r0 + 8) * ZSA + e0) = make_float2(a[2], a[3]);
            }
        }
        __syncthreads();   // zbuf ready; vbf reads done

        #pragma unroll
        for (int j = 0; j < 16; ++j) {
            const int e = eg * 16 + j;
            const float x0 = xbuf[e * 2], x1 = xbuf[e * 2 + 1];
            float zi = zbuf[u * ZSA + e]         + fmaf(wxi1, x1, fmaf(wxi0, x0, bi));
            float zf = zbuf[(64 + u) * ZSA + e]  + fmaf(wxf1, x1, fmaf(wxf0, x0, bf));
            float zg = zbuf[(128 + u) * ZSA + e] + fmaf(wxg1, x1, fmaf(wxg0, x0, bg));
            float zo = zbuf[(192 + u) * ZSA + e] + fmaf(wxo1, x1, fmaf(wxo0, x0, bo));
            float cn = sigf(zf) * c[j] + sigf(zi) * tanhf_(zg);
            c[j] = cn;
            vsh[e * HS + u] = sigf(zo) * tanhf_(cn);
        }
        __syncthreads();   // h(t) fp32 ready; xbuf/zbuf reads done

        // Out-projection (threads 0..255) || vsh->bf16 conversion (256..511)
        if (tid < 2 * D_EPB) {
            const int e = tid >> 1, od = tid & 1;
            float o = ob[od];
            #pragma unroll
            for (int k4 = 0; k4 < 16; ++k4) {
                float4 hh = *(const float4*)(vsh + e * HS + k4 * 4);
                float4 w  = *(const float4*)(ow + od * 64 + k4 * 4);
                o += w.x * hh.x + w.y * hh.y + w.z * hh.z + w.w * hh.w;
            }
            out[(blockBase + e) * (PRED * 2) + t * 2 + od] = o;
            xbuf[e * 2 + od] = o;
        } else {
            const int base = tid - 256;              // 0..255
            for (int i = base; i < D_EPB * 32; i += 256) {
                int e = i >> 5, kp = i & 31;
                float2 p = *(const float2*)(vsh + e * HS + 2 * kp);
                uint32_t h = pk_bf2(p.x, p.y);
                vbh[e * BS0 + kp] = h;
                vbl[e * BS0 + kp] = pk_bf2(p.x - bf_lo(h), p.y - bf_hi(h));
            }
        }
        __syncthreads();   // xbuf(t+1) + vbf(t) ready before next GEMM
    }
}

// ---------------------------------------------------------------------------
extern "C" void kernel_launch(void* const* d_in, const int* in_sizes, int n_in,
                              void* d_out, int out_size)
{
    const float* obs     = (const float*)d_in[0];
    const float* w_ih_l0 = (const float*)d_in[1];
    const float* w_hh_l0 = (const float*)d_in[2];
    const float* b_ih_l0 = (const float*)d_in[3];
    const float* b_hh_l0 = (const float*)d_in[4];
    const float* w_ih_l1 = (const float*)d_in[5];
    const float* w_hh_l1 = (const float*)d_in[6];
    const float* b_ih_l1 = (const float*)d_in[7];
    const float* b_hh_l1 = (const float*)d_in[8];
    const float* dec_w_ih = (const float*)d_in[9];
    const float* dec_w_hh = (const float*)d_in[10];
    const float* dec_b_ih = (const float*)d_in[11];
    const float* dec_b_hh = (const float*)d_in[12];
    const float* out_w   = (const float*)d_in[13];
    const float* out_b   = (const float*)d_in[14];
    float* out = (float*)d_out;

    const int B = in_sizes[0] / (OBS * 2);

    cudaFuncSetAttribute(k_layer0,  cudaFuncAttributeMaxDynamicSharedMemorySize, L0_SMEM);
    cudaFuncSetAttribute(k_layer1,  cudaFuncAttributeMaxDynamicSharedMemorySize, K2_SMEM);
    cudaFuncSetAttribute(k_decoder, cudaFuncAttributeMaxDynamicSharedMemorySize, D_SMEM);

    k_layer0<<<B / L0_EPB, TPB, L0_SMEM>>>(obs, w_ih_l0, w_hh_l0, b_ih_l0, b_hh_l0, B);
    k_layer1<<<B / K2_EPB, TPB, K2_SMEM>>>(w_ih_l1, w_hh_l1, b_ih_l1, b_hh_l1, B);
    k_decoder<<<B / D_EPB, TPB, D_SMEM>>>(obs, dec_w_ih, dec_w_hh, dec_b_ih, dec_b_hh,
                                          out_w, out_b, out, B);
}